// round 2
// baseline (speedup 1.0000x reference)
#include <cuda_runtime.h>
#include <math.h>

#define Bsz 8
#define HWsz 16384
#define Cch 128
#define Ntot (Bsz*HWsz)   // 131072 rows

// ---------------- scratch (device globals; no allocation) ----------------
__device__ float g_ln_pre[(size_t)Ntot*Cch];
__device__ float g_ln_cur[(size_t)Ntot*Cch];
__device__ float g_q1[(size_t)Ntot*Cch];
__device__ float g_kv1[(size_t)Ntot*2*Cch];
__device__ float g_q2[(size_t)Ntot*Cch];
__device__ float g_kv2[(size_t)Ntot*2*Cch];
__device__ float g_out1[(size_t)Ntot*Cch];
__device__ float g_att_part[(size_t)Bsz*16*Cch*Cch];  // split-K partials
__device__ float g_att[(size_t)Bsz*Cch*Cch];
__device__ float g_norm_part[2*Bsz*32*Cch];
__device__ float g_invnorm[2*Bsz*Cch];                // [which(q=0,k=1)][b][c]

// ---------------- LayerNorm over channel dim, one warp per row ----------------
__global__ __launch_bounds__(256)
void ln_kernel(const float* __restrict__ pre, const float* __restrict__ cur,
               const float* __restrict__ w1, const float* __restrict__ b1,
               const float* __restrict__ w2, const float* __restrict__ b2)
{
    int warp = (blockIdx.x * blockDim.x + threadIdx.x) >> 5;
    int lane = threadIdx.x & 31;
    if (warp >= 2 * Ntot) return;
    const float* src; float* dst; const float* w; const float* bb; int row;
    if (warp < Ntot) { src = pre; dst = g_ln_pre; w = w1; bb = b1; row = warp; }
    else            { src = cur; dst = g_ln_cur; w = w2; bb = b2; row = warp - Ntot; }

    const float4* p = (const float4*)(src + (size_t)row * Cch);
    float4 v = p[lane];
    float s  = v.x + v.y + v.z + v.w;
    float ss = v.x*v.x + v.y*v.y + v.z*v.z + v.w*v.w;
    #pragma unroll
    for (int o = 16; o; o >>= 1) {
        s  += __shfl_xor_sync(0xFFFFFFFFu, s,  o);
        ss += __shfl_xor_sync(0xFFFFFFFFu, ss, o);
    }
    float mu  = s * (1.0f / Cch);
    float var = ss * (1.0f / Cch) - mu * mu;
    float inv = rsqrtf(var + 1e-5f);
    int c = lane * 4;
    float4 ww = *(const float4*)(w + c);
    float4 wb = *(const float4*)(bb + c);
    float4 o4;
    o4.x = (v.x - mu) * inv * ww.x + wb.x;
    o4.y = (v.y - mu) * inv * ww.y + wb.y;
    o4.z = (v.z - mu) * inv * ww.z + wb.z;
    o4.w = (v.w - mu) * inv * ww.w + wb.w;
    ((float4*)(dst + (size_t)row * Cch))[lane] = o4;
}

// ---------------- generic NT GEMM:  C[m,o] = sum_k A[m,k] * W[o,k] (+bias)(+res) ----------------
// K = 128 fixed. 64x64 tile, 256 threads, 4x4 microtile.
__global__ __launch_bounds__(256)
void gemm_nt(const float* __restrict__ A, const float* __restrict__ W,
             const float* __restrict__ bias, const float* __restrict__ Res,
             float* __restrict__ C,
             int lda, int ldc,
             long long bsA, long long bsW, long long bsC, long long bsR)
{
    int b = blockIdx.z;
    A += (size_t)b * bsA;
    W += (size_t)b * bsW;
    C += (size_t)b * bsC;
    if (Res) Res += (size_t)b * bsR;

    int m0 = blockIdx.y * 64;
    int o0 = blockIdx.x * 64;

    __shared__ float As[16][65];
    __shared__ float Ws[16][65];

    int tid = threadIdx.x;
    int tx = tid & 15, ty = tid >> 4;
    int lk = tid & 15, lr = tid >> 4;

    float acc[4][4];
    #pragma unroll
    for (int i = 0; i < 4; i++)
        #pragma unroll
        for (int j = 0; j < 4; j++) acc[i][j] = 0.f;

    for (int kb = 0; kb < 128; kb += 16) {
        #pragma unroll
        for (int p = 0; p < 4; p++) {
            int r = lr + p * 16;
            As[lk][r] = A[(size_t)(m0 + r) * lda + kb + lk];
            Ws[lk][r] = W[(size_t)(o0 + r) * 128 + kb + lk];
        }
        __syncthreads();
        #pragma unroll
        for (int k = 0; k < 16; k++) {
            float a[4], w[4];
            #pragma unroll
            for (int i = 0; i < 4; i++) a[i] = As[k][ty + 16 * i];
            #pragma unroll
            for (int j = 0; j < 4; j++) w[j] = Ws[k][tx + 16 * j];
            #pragma unroll
            for (int i = 0; i < 4; i++)
                #pragma unroll
                for (int j = 0; j < 4; j++) acc[i][j] += a[i] * w[j];
        }
        __syncthreads();
    }

    #pragma unroll
    for (int i = 0; i < 4; i++) {
        int m = m0 + ty + 16 * i;
        #pragma unroll
        for (int j = 0; j < 4; j++) {
            int o = o0 + tx + 16 * j;
            float v = acc[i][j];
            if (bias) v += bias[o];
            if (Res)  v += Res[(size_t)m * ldc + o];
            C[(size_t)m * ldc + o] = v;
        }
    }
}

// ---------------- depthwise 3x3 conv, [b,hw,ch] layout, smem tiled ----------------
// grid: (64 spatial tiles of 16x16, ch/32 groups, B). block 256.
__global__ __launch_bounds__(256)
void dwconv_kernel(const float* __restrict__ in, float* __restrict__ out,
                   const float* __restrict__ wt, const float* __restrict__ bias, int ch)
{
    __shared__ float s[18 * 18 * 32];
    int tile = blockIdx.x;
    int g = blockIdx.y;
    int b = blockIdx.z;
    int ty0 = (tile >> 3) * 16, tx0 = (tile & 7) * 16;
    int tid = threadIdx.x;

    const size_t basein = (size_t)b * HWsz * ch + (size_t)g * 32;
    for (int idx = tid; idx < 18 * 18 * 32; idx += 256) {
        int cl = idx & 31;
        int rest = idx >> 5;
        int xx = rest % 18, yy = rest / 18;
        int y = ty0 + yy - 1, x = tx0 + xx - 1;
        float v = 0.f;
        if (y >= 0 && y < 128 && x >= 0 && x < 128)
            v = in[basein + (size_t)(y * 128 + x) * ch + cl];
        s[idx] = v;
    }
    __syncthreads();

    int cl = tid & 31, sp = tid >> 5;
    int cg = g * 32 + cl;
    float w9[9];
    #pragma unroll
    for (int t = 0; t < 9; t++) w9[t] = wt[cg * 9 + t];
    float bb = bias[cg];

    #pragma unroll 4
    for (int q = 0; q < 32; q++) {
        int p = sp * 32 + q;
        int py = p >> 4, px = p & 15;
        float acc = bb;
        #pragma unroll
        for (int dy = 0; dy < 3; dy++)
            #pragma unroll
            for (int dx = 0; dx < 3; dx++)
                acc += s[((py + dy) * 18 + px + dx) * 32 + cl] * w9[dy * 3 + dx];
        out[basein + (size_t)((ty0 + py) * 128 + tx0 + px) * ch + cl] = acc;
    }
}

// ---------------- per-(b,c) sum of squares over hw (partials) ----------------
// grid (32 chunks, 2 which, 8 b), block 128
__global__ __launch_bounds__(128)
void norm_part_kernel()
{
    int chunk = blockIdx.x, which = blockIdx.y, b = blockIdx.z;
    int c = threadIdx.x;
    const float* src; int lda;
    if (which == 0) { src = g_q2  + (size_t)b * HWsz * 128; lda = 128; }
    else            { src = g_kv2 + (size_t)b * HWsz * 256; lda = 256; }  // k = first 128 ch
    src += (size_t)chunk * 512 * lda + c;
    float s = 0.f;
    #pragma unroll 8
    for (int r = 0; r < 512; r++) {
        float v = src[(size_t)r * lda];
        s += v * v;
    }
    g_norm_part[((which * 8 + b) * 32 + chunk) * 128 + c] = s;
}

__global__ __launch_bounds__(128)
void norm_reduce_kernel()
{
    int idx = blockIdx.x;   // which*8 + b, 16 blocks
    int c = threadIdx.x;
    float s = 0.f;
    #pragma unroll
    for (int ch = 0; ch < 32; ch++)
        s += g_norm_part[(idx * 32 + ch) * 128 + c];
    g_invnorm[idx * 128 + c] = 1.0f / fmaxf(sqrtf(s), 1e-12f);
}

// ---------------- TN GEMM: att_raw partial[b,chunk,c,d] = sum_{n in chunk} q2[b,n,c]*k2[b,n,d] ----
// grid (2, 2, B*16), block 256. chunk = 1024 n rows.
__global__ __launch_bounds__(256)
void gemm_tn_part()
{
    int z = blockIdx.z;
    int b = z >> 4, chunk = z & 15;
    const float* Qb = g_q2  + (size_t)b * HWsz * 128;
    const float* Kb = g_kv2 + (size_t)b * HWsz * 256;
    int c0 = blockIdx.y * 64, d0 = blockIdx.x * 64;

    __shared__ float Qs[16][65];
    __shared__ float Ks[16][65];

    int tid = threadIdx.x;
    int tx = tid & 15, ty = tid >> 4;
    int lc = tid & 63, lr = tid >> 6;

    float acc[4][4];
    #pragma unroll
    for (int i = 0; i < 4; i++)
        #pragma unroll
        for (int j = 0; j < 4; j++) acc[i][j] = 0.f;

    int nbase = chunk * 1024;
    for (int nb = 0; nb < 1024; nb += 16) {
        #pragma unroll
        for (int p = 0; p < 4; p++) {
            int r = lr + p * 4;
            Qs[r][lc] = Qb[(size_t)(nbase + nb + r) * 128 + c0 + lc];
            Ks[r][lc] = Kb[(size_t)(nbase + nb + r) * 256 + d0 + lc];
        }
        __syncthreads();
        #pragma unroll
        for (int k = 0; k < 16; k++) {
            float a[4], w[4];
            #pragma unroll
            for (int i = 0; i < 4; i++) a[i] = Qs[k][ty + 16 * i];
            #pragma unroll
            for (int j = 0; j < 4; j++) w[j] = Ks[k][tx + 16 * j];
            #pragma unroll
            for (int i = 0; i < 4; i++)
                #pragma unroll
                for (int j = 0; j < 4; j++) acc[i][j] += a[i] * w[j];
        }
        __syncthreads();
    }

    float* P = g_att_part + (size_t)(b * 16 + chunk) * 128 * 128;
    #pragma unroll
    for (int i = 0; i < 4; i++)
        #pragma unroll
        for (int j = 0; j < 4; j++)
            P[(size_t)(c0 + ty + 16 * i) * 128 + d0 + tx + 16 * j] = acc[i][j];
}

// ---------------- reduce partials + scale by inv norms + softmax over d ----------------
// one warp per (b,c) row. grid 128 blocks x 256 threads (8 warps).
__global__ __launch_bounds__(256)
void softmax_kernel()
{
    int warp = blockIdx.x * 8 + (threadIdx.x >> 5);
    int lane = threadIdx.x & 31;
    int b = warp >> 7, c = warp & 127;

    float4 s = make_float4(0.f, 0.f, 0.f, 0.f);
    #pragma unroll
    for (int ch = 0; ch < 16; ch++) {
        const float4* p = (const float4*)(g_att_part + (size_t)((b * 16 + ch) * 128 + c) * 128);
        float4 v = p[lane];
        s.x += v.x; s.y += v.y; s.z += v.z; s.w += v.w;
    }
    float invq = g_invnorm[b * 128 + c];
    float4 ik = ((const float4*)(g_invnorm + 1024 + b * 128))[lane];

    float l[4];
    l[0] = s.x * invq * ik.x;
    l[1] = s.y * invq * ik.y;
    l[2] = s.z * invq * ik.z;
    l[3] = s.w * invq * ik.w;

    float mx = fmaxf(fmaxf(l[0], l[1]), fmaxf(l[2], l[3]));
    #pragma unroll
    for (int o = 16; o; o >>= 1) mx = fmaxf(mx, __shfl_xor_sync(0xFFFFFFFFu, mx, o));

    float e[4], sum = 0.f;
    #pragma unroll
    for (int t = 0; t < 4; t++) { e[t] = expf(l[t] - mx); sum += e[t]; }
    #pragma unroll
    for (int o = 16; o; o >>= 1) sum += __shfl_xor_sync(0xFFFFFFFFu, sum, o);
    float inv = 1.0f / sum;

    float4 r = make_float4(e[0] * inv, e[1] * inv, e[2] * inv, e[3] * inv);
    ((float4*)(g_att + (size_t)(b * 128 + c) * 128))[lane] = r;
}

// ---------------- host ----------------
extern "C" void kernel_launch(void* const* d_in, const int* in_sizes, int n_in,
                              void* d_out, int out_size)
{
    const float* pre   = (const float*)d_in[0];
    const float* cur   = (const float*)d_in[1];
    const float* ln1_w = (const float*)d_in[2];
    const float* ln1_b = (const float*)d_in[3];
    const float* ln2_w = (const float*)d_in[4];
    const float* ln2_b = (const float*)d_in[5];
    const float* q_w1  = (const float*)d_in[6];
    const float* q_b1  = (const float*)d_in[7];
    const float* q_w2  = (const float*)d_in[8];
    const float* q_b2  = (const float*)d_in[9];
    const float* kv_w1 = (const float*)d_in[10];
    const float* kv_b1 = (const float*)d_in[11];
    const float* kv_w2 = (const float*)d_in[12];
    const float* kv_b2 = (const float*)d_in[13];
    const float* out_w = (const float*)d_in[14];
    const float* out_b = (const float*)d_in[15];
    float* out = (float*)d_out;

    float *p_ln_pre, *p_ln_cur, *p_q1, *p_kv1, *p_q2, *p_kv2, *p_out1, *p_att;
    cudaGetSymbolAddress((void**)&p_ln_pre, g_ln_pre);
    cudaGetSymbolAddress((void**)&p_ln_cur, g_ln_cur);
    cudaGetSymbolAddress((void**)&p_q1,  g_q1);
    cudaGetSymbolAddress((void**)&p_kv1, g_kv1);
    cudaGetSymbolAddress((void**)&p_q2,  g_q2);
    cudaGetSymbolAddress((void**)&p_kv2, g_kv2);
    cudaGetSymbolAddress((void**)&p_out1, g_out1);
    cudaGetSymbolAddress((void**)&p_att, g_att);

    // 1. LayerNorm both tensors (one warp per row; 2*Ntot rows)
    {
        int warps = 2 * Ntot;
        int blocks = (warps * 32) / 256;
        ln_kernel<<<blocks, 256>>>(pre, cur, ln1_w, ln1_b, ln2_w, ln2_b);
    }

    // 2. q = cur_ln @ q_w1^T + q_b1   [N,128]
    gemm_nt<<<dim3(2, Ntot / 64, 1), 256>>>(p_ln_cur, q_w1, q_b1, nullptr, p_q1,
                                            128, 128, 0, 0, 0, 0);
    // 3. kv = pre_ln @ kv_w1^T + kv_b1   [N,256]
    gemm_nt<<<dim3(4, Ntot / 64, 1), 256>>>(p_ln_pre, kv_w1, kv_b1, nullptr, p_kv1,
                                            128, 256, 0, 0, 0, 0);
    // 4-5. depthwise 3x3
    dwconv_kernel<<<dim3(64, 4, Bsz), 256>>>(p_q1,  p_q2,  q_w2,  q_b2,  128);
    dwconv_kernel<<<dim3(64, 8, Bsz), 256>>>(p_kv1, p_kv2, kv_w2, kv_b2, 256);

    // 6-7. L2 norms of q and k over hw
    norm_part_kernel<<<dim3(32, 2, Bsz), 128>>>();
    norm_reduce_kernel<<<16, 128>>>();

    // 8. logits partials: q^T k split-K over n
    gemm_tn_part<<<dim3(2, 2, Bsz * 16), 256>>>();

    // 9. reduce + scale + softmax
    softmax_kernel<<<128, 256>>>();

    // 10. out1[b,n,c] = sum_d v[b,n,d] * att[b,c,d]
    gemm_nt<<<dim3(2, HWsz / 64, Bsz), 256>>>(p_kv2 + 128, p_att, nullptr, nullptr, p_out1,
                                              256, 128,
                                              (long long)HWsz * 256, (long long)128 * 128,
                                              (long long)HWsz * 128, 0);

    // 11. final: out = out1 @ out_w^T + out_b + cur   -> d_out [b,hw,c]
    gemm_nt<<<dim3(2, Ntot / 64, 1), 256>>>(p_out1, out_w, out_b, cur, out,
                                            128, 128, 0, 0, 0, 0);
    (void)in_sizes; (void)n_in; (void)out_size;
}

// round 4
// speedup vs baseline: 2.4836x; 2.4836x over previous
#include <cuda_runtime.h>
#include <cuda_bf16.h>
#include <cstdint>
#include <cstring>
#include <math.h>

#define Bsz 8
#define HWsz 16384
#define Cch 128
#define Ntot (Bsz*HWsz)   // 131072 rows
typedef __nv_bfloat16 bf16;

// ---------------- scratch (device globals; no allocation) ----------------
__device__ bf16  g_wq[Cch*Cch];
__device__ bf16  g_wkv[2*Cch*Cch];
__device__ bf16  g_q1[(size_t)Ntot*Cch];
__device__ bf16  g_kv1[(size_t)Ntot*2*Cch];
__device__ bf16  g_q2[(size_t)Ntot*Cch];
__device__ bf16  g_kv2[(size_t)Ntot*2*Cch];
__device__ float g_att_part[(size_t)Bsz*16*Cch*Cch];
__device__ float g_att[(size_t)Bsz*Cch*Cch];
__device__ float g_norm_part[2*Bsz*64*Cch];
__device__ float g_invnorm[2*Bsz*Cch];
__device__ bf16  g_W2h[Bsz*Cch*Cch];

// ---------------- mma / ldmatrix helpers ----------------
__device__ __forceinline__ unsigned sptr(const void* p) {
    return (unsigned)__cvta_generic_to_shared(p);
}
__device__ __forceinline__ void ldm_x4(unsigned* r, unsigned a) {
    asm volatile("ldmatrix.sync.aligned.m8n8.x4.shared.b16 {%0,%1,%2,%3}, [%4];"
        : "=r"(r[0]), "=r"(r[1]), "=r"(r[2]), "=r"(r[3]) : "r"(a));
}
__device__ __forceinline__ void ldm_x4_t(unsigned* r, unsigned a) {
    asm volatile("ldmatrix.sync.aligned.m8n8.x4.trans.shared.b16 {%0,%1,%2,%3}, [%4];"
        : "=r"(r[0]), "=r"(r[1]), "=r"(r[2]), "=r"(r[3]) : "r"(a));
}
__device__ __forceinline__ void ldm_x2(unsigned* r, unsigned a) {
    asm volatile("ldmatrix.sync.aligned.m8n8.x2.shared.b16 {%0,%1}, [%2];"
        : "=r"(r[0]), "=r"(r[1]) : "r"(a));
}
__device__ __forceinline__ void ldm_x2_t(unsigned* r, unsigned a) {
    asm volatile("ldmatrix.sync.aligned.m8n8.x2.trans.shared.b16 {%0,%1}, [%2];"
        : "=r"(r[0]), "=r"(r[1]) : "r"(a));
}
__device__ __forceinline__ void mma16816(float* c, const unsigned* a, const unsigned* b) {
    asm volatile("mma.sync.aligned.m16n8k16.row.col.f32.bf16.bf16.f32 "
        "{%0,%1,%2,%3},{%4,%5,%6,%7},{%8,%9},{%0,%1,%2,%3};"
        : "+f"(c[0]), "+f"(c[1]), "+f"(c[2]), "+f"(c[3])
        : "r"(a[0]), "r"(a[1]), "r"(a[2]), "r"(a[3]), "r"(b[0]), "r"(b[1]));
}

#define SROW 136   // smem row stride in halves (128 + 8 pad -> conflict-free ldmatrix)

// ---------------- weight prep: fp32 -> bf16 ----------------
__global__ void prep_weights(const float* __restrict__ qw, const float* __restrict__ kvw)
{
    int i = blockIdx.x * 256 + threadIdx.x;
    if (i < Cch * Cch)     g_wq[i]  = __float2bfloat16_rn(qw[i]);
    if (i < 2 * Cch * Cch) g_wkv[i] = __float2bfloat16_rn(kvw[i]);
}

// ---------------- fused LayerNorm + 1x1-conv GEMM (bf16 mma) ----------------
__global__ __launch_bounds__(256)
void lngemm(const float* __restrict__ A, const bf16* __restrict__ Wg,
            const float* __restrict__ lnw, const float* __restrict__ lnb,
            const float* __restrict__ bias, bf16* __restrict__ C,
            int ntiles, int ldc)
{
    extern __shared__ bf16 sm[];
    bf16* As = sm;               // [128][SROW]
    bf16* Ws = sm + 128 * SROW;  // [128][SROW]
    int tid = threadIdx.x, lane = tid & 31, w = tid >> 5;
    int m0 = blockIdx.y * 128;

    // LN stats + stage A (each warp: 16 rows)
    float4 wv = *(const float4*)(lnw + lane * 4);
    float4 bv = *(const float4*)(lnb + lane * 4);
    for (int i = 0; i < 16; i++) {
        int rl = w * 16 + i;
        float4 v = *(const float4*)(A + (size_t)(m0 + rl) * 128 + lane * 4);
        float s  = v.x + v.y + v.z + v.w;
        float ss = fmaf(v.x, v.x, fmaf(v.y, v.y, fmaf(v.z, v.z, v.w * v.w)));
        #pragma unroll
        for (int o = 16; o; o >>= 1) {
            s  += __shfl_xor_sync(0xFFFFFFFFu, s,  o);
            ss += __shfl_xor_sync(0xFFFFFFFFu, ss, o);
        }
        float mu  = s * (1.0f / 128.0f);
        float inv = rsqrtf(ss * (1.0f / 128.0f) - mu * mu + 1e-5f);
        float x0 = (v.x - mu) * inv * wv.x + bv.x;
        float x1 = (v.y - mu) * inv * wv.y + bv.y;
        float x2 = (v.z - mu) * inv * wv.z + bv.z;
        float x3 = (v.w - mu) * inv * wv.w + bv.w;
        __nv_bfloat162 p0 = __floats2bfloat162_rn(x0, x1);
        __nv_bfloat162 p1 = __floats2bfloat162_rn(x2, x3);
        *(__nv_bfloat162*)(As + rl * SROW + lane * 4)     = p0;
        *(__nv_bfloat162*)(As + rl * SROW + lane * 4 + 2) = p1;
    }

    int wm = (w & 1) * 64, wn = (w >> 1) * 32;
    int arow  = (lane & 7) + ((lane >> 3) & 1) * 8;
    int akoff = (lane >> 4) * 8;
    int brow  = (lane & 7);
    int bkoff = ((lane >> 3) & 1) * 8;
    int g = lane >> 2, t2 = (lane & 3) * 2;

    for (int nt = 0; nt < ntiles; nt++) {
        if (nt) __syncthreads();
        for (int it = tid; it < 128 * 16; it += 256) {
            int o = it >> 4, c8 = (it & 15) * 8;
            *(uint4*)(Ws + o * SROW + c8) =
                *(const uint4*)(Wg + (size_t)(nt * 128 + o) * 128 + c8);
        }
        __syncthreads();

        float acc[4][4][4];
        #pragma unroll
        for (int mi = 0; mi < 4; mi++)
            #pragma unroll
            for (int ni = 0; ni < 4; ni++)
                #pragma unroll
                for (int t = 0; t < 4; t++) acc[mi][ni][t] = 0.f;

        for (int k0 = 0; k0 < 128; k0 += 16) {
            unsigned af[4][4];
            unsigned bfr[4][2];
            #pragma unroll
            for (int mi = 0; mi < 4; mi++)
                ldm_x4(af[mi], sptr(As + (wm + 16 * mi + arow) * SROW + k0 + akoff));
            #pragma unroll
            for (int ni = 0; ni < 4; ni++)
                ldm_x2(bfr[ni], sptr(Ws + (wn + 8 * ni + brow) * SROW + k0 + bkoff));
            #pragma unroll
            for (int mi = 0; mi < 4; mi++)
                #pragma unroll
                for (int ni = 0; ni < 4; ni++)
                    mma16816(acc[mi][ni], af[mi], bfr[ni]);
        }

        #pragma unroll
        for (int mi = 0; mi < 4; mi++) {
            int r0 = m0 + wm + 16 * mi + g;
            #pragma unroll
            for (int ni = 0; ni < 4; ni++) {
                int col = nt * 128 + wn + 8 * ni + t2;
                float2 bb = *(const float2*)(bias + col);
                __nv_bfloat162 o0 = __floats2bfloat162_rn(acc[mi][ni][0] + bb.x, acc[mi][ni][1] + bb.y);
                __nv_bfloat162 o1 = __floats2bfloat162_rn(acc[mi][ni][2] + bb.x, acc[mi][ni][3] + bb.y);
                *(__nv_bfloat162*)(C + (size_t)r0 * ldc + col)       = o0;
                *(__nv_bfloat162*)(C + (size_t)(r0 + 8) * ldc + col) = o1;
            }
        }
    }
}

// ---------------- depthwise 3x3 conv (bf16 io) + sum-of-squares partials ----------------
__global__ __launch_bounds__(256)
void dwconv_kernel(const bf16* __restrict__ in, bf16* __restrict__ out,
                   const float* __restrict__ wt, const float* __restrict__ bias,
                   int ch, int which, int sq_groups)
{
    __shared__ float s[18 * 18 * 32];
    __shared__ float red[256];
    int tile = blockIdx.x, gg = blockIdx.y, b = blockIdx.z;
    int ty0 = (tile >> 3) * 16, tx0 = (tile & 7) * 16;
    int tid = threadIdx.x;

    const size_t basein = (size_t)b * HWsz * ch + (size_t)gg * 32;
    for (int idx = tid; idx < 18 * 18 * 32; idx += 256) {
        int cl = idx & 31;
        int rest = idx >> 5;
        int xx = rest % 18, yy = rest / 18;
        int y = ty0 + yy - 1, x = tx0 + xx - 1;
        float v = 0.f;
        if (y >= 0 && y < 128 && x >= 0 && x < 128)
            v = __bfloat162float(in[basein + (size_t)(y * 128 + x) * ch + cl]);
        s[idx] = v;
    }
    __syncthreads();

    int cl = tid & 31, sp = tid >> 5;
    int cg = gg * 32 + cl;
    float w9[9];
    #pragma unroll
    for (int t = 0; t < 9; t++) w9[t] = wt[cg * 9 + t];
    float bb = bias[cg];

    float sq = 0.f;
    #pragma unroll 4
    for (int q = 0; q < 32; q++) {
        int p = sp * 32 + q;
        int py = p >> 4, px = p & 15;
        float acc = bb;
        #pragma unroll
        for (int dy = 0; dy < 3; dy++)
            #pragma unroll
            for (int dx = 0; dx < 3; dx++)
                acc += s[((py + dy) * 18 + px + dx) * 32 + cl] * w9[dy * 3 + dx];
        out[basein + (size_t)((ty0 + py) * 128 + tx0 + px) * ch + cl] = __float2bfloat16_rn(acc);
        sq = fmaf(acc, acc, sq);
    }

    if (gg < sq_groups) {
        __syncthreads();
        red[tid] = sq;
        __syncthreads();
        if (tid < 32) {
            float t = 0.f;
            #pragma unroll
            for (int j = 0; j < 8; j++) t += red[j * 32 + tid];
            g_norm_part[((size_t)(which * 8 + b) * 64 + tile) * 128 + gg * 32 + tid] = t;
        }
    }
}

__global__ __launch_bounds__(128)
void norm_reduce_kernel()
{
    int idx = blockIdx.x;   // which*8 + b
    int c = threadIdx.x;
    float s = 0.f;
    #pragma unroll 8
    for (int t = 0; t < 64; t++)
        s += g_norm_part[((size_t)idx * 64 + t) * 128 + c];
    g_invnorm[idx * 128 + c] = 1.0f / fmaxf(sqrtf(s), 1e-12f);
}

// ---------------- QK^T (bf16 mma, split-K over n), partials fp32 ----------------
__global__ __launch_bounds__(256)
void qk_kernel()
{
    __shared__ bf16 Qs[32 * SROW];
    __shared__ bf16 Ks[32 * SROW];
    int bx = blockIdx.x;
    int b = bx >> 4, chunk = bx & 15;
    const bf16* Qb = g_q2  + (size_t)b * HWsz * 128;
    const bf16* Kb = g_kv2 + (size_t)b * HWsz * 256;
    int tid = threadIdx.x, lane = tid & 31, w = tid >> 5;
    int wm = (w & 1) * 64, wn = (w >> 1) * 32;

    int at_row  = (lane & 7) + ((lane >> 4) & 1) * 8;   // k-row
    int at_coff = ((lane >> 3) & 1) * 8;                // m-col
    int bt_row  = (lane & 7) + ((lane >> 3) & 1) * 8;   // k-row
    int g = lane >> 2, t2 = (lane & 3) * 2;

    float acc[4][4][4];
    #pragma unroll
    for (int mi = 0; mi < 4; mi++)
        #pragma unroll
        for (int ni = 0; ni < 4; ni++)
            #pragma unroll
            for (int t = 0; t < 4; t++) acc[mi][ni][t] = 0.f;

    for (int st = 0; st < 32; st++) {
        int n0 = chunk * 1024 + st * 32;
        if (st) __syncthreads();
        for (int it = tid; it < 32 * 16; it += 256) {
            int r = it >> 4, c8 = (it & 15) * 8;
            *(uint4*)(Qs + r * SROW + c8) = *(const uint4*)(Qb + (size_t)(n0 + r) * 128 + c8);
            *(uint4*)(Ks + r * SROW + c8) = *(const uint4*)(Kb + (size_t)(n0 + r) * 256 + c8);
        }
        __syncthreads();
        #pragma unroll
        for (int k0 = 0; k0 < 32; k0 += 16) {
            unsigned af[4][4];
            unsigned bfr[4][2];
            #pragma unroll
            for (int mi = 0; mi < 4; mi++)
                ldm_x4_t(af[mi], sptr(Qs + (k0 + at_row) * SROW + wm + 16 * mi + at_coff));
            #pragma unroll
            for (int ni = 0; ni < 4; ni++)
                ldm_x2_t(bfr[ni], sptr(Ks + (k0 + bt_row) * SROW + wn + 8 * ni));
            #pragma unroll
            for (int mi = 0; mi < 4; mi++)
                #pragma unroll
                for (int ni = 0; ni < 4; ni++)
                    mma16816(acc[mi][ni], af[mi], bfr[ni]);
        }
    }

    float* P = g_att_part + (size_t)bx * 16384;
    #pragma unroll
    for (int mi = 0; mi < 4; mi++) {
        int row = wm + 16 * mi + g;
        #pragma unroll
        for (int ni = 0; ni < 4; ni++) {
            int col = wn + 8 * ni + t2;
            *(float2*)(P + row * 128 + col)       = make_float2(acc[mi][ni][0], acc[mi][ni][1]);
            *(float2*)(P + (row + 8) * 128 + col) = make_float2(acc[mi][ni][2], acc[mi][ni][3]);
        }
    }
}

// ---------------- reduce partials + scale + softmax ----------------
__global__ __launch_bounds__(256)
void softmax_kernel()
{
    int warp = blockIdx.x * 8 + (threadIdx.x >> 5);
    int lane = threadIdx.x & 31;
    int b = warp >> 7, c = warp & 127;

    float4 s = make_float4(0.f, 0.f, 0.f, 0.f);
    #pragma unroll
    for (int ch = 0; ch < 16; ch++) {
        float4 v = ((const float4*)(g_att_part + (size_t)((b * 16 + ch) * 128 + c) * 128))[lane];
        s.x += v.x; s.y += v.y; s.z += v.z; s.w += v.w;
    }
    float invq = g_invnorm[b * 128 + c];
    float4 ik = ((const float4*)(g_invnorm + 1024 + b * 128))[lane];

    float l0 = s.x * invq * ik.x;
    float l1 = s.y * invq * ik.y;
    float l2 = s.z * invq * ik.z;
    float l3 = s.w * invq * ik.w;

    float mx = fmaxf(fmaxf(l0, l1), fmaxf(l2, l3));
    #pragma unroll
    for (int o = 16; o; o >>= 1) mx = fmaxf(mx, __shfl_xor_sync(0xFFFFFFFFu, mx, o));
    float e0 = expf(l0 - mx), e1 = expf(l1 - mx), e2 = expf(l2 - mx), e3 = expf(l3 - mx);
    float sum = e0 + e1 + e2 + e3;
    #pragma unroll
    for (int o = 16; o; o >>= 1) sum += __shfl_xor_sync(0xFFFFFFFFu, sum, o);
    float inv = 1.0f / sum;

    ((float4*)(g_att + (size_t)(b * 128 + c) * 128))[lane] =
        make_float4(e0 * inv, e1 * inv, e2 * inv, e3 * inv);
}

// ---------------- W2[b] = out_w @ att[b]  (fp32 compute, bf16 out) ----------------
__global__ __launch_bounds__(256)
void w2_kernel(const float* __restrict__ out_w)
{
    __shared__ float sa[16 * 128];
    int b = blockIdx.x, tid = threadIdx.x;
    int c = tid >> 1, dh = (tid & 1) * 64;
    float acc[64];
    #pragma unroll
    for (int j = 0; j < 64; j++) acc[j] = 0.f;

    for (int e0 = 0; e0 < 128; e0 += 16) {
        if (e0) __syncthreads();
        for (int it = tid; it < 2048; it += 256)
            sa[it] = g_att[(size_t)b * 16384 + (size_t)(e0 + (it >> 7)) * 128 + (it & 127)];
        __syncthreads();
        for (int e = 0; e < 16; e++) {
            float wvv = out_w[c * 128 + e0 + e];
            #pragma unroll
            for (int j = 0; j < 64; j++)
                acc[j] = fmaf(wvv, sa[e * 128 + dh + j], acc[j]);
        }
    }
    for (int j = 0; j < 64; j++)
        g_W2h[(size_t)b * 16384 + c * 128 + dh + j] = __float2bfloat16_rn(acc[j]);
}

// ---------------- final: out[b,n,c] = sum_d W2[c,d] v[b,n,d] + out_b[c] + cur ----------------
__global__ __launch_bounds__(256)
void vgemm(const float* __restrict__ cur, const float* __restrict__ out_b,
           float* __restrict__ out)
{
    extern __shared__ bf16 sm[];
    bf16* As = sm;               // v tile [128][SROW]
    bf16* Bs = sm + 128 * SROW;  // W2 [128][SROW]
    int b = blockIdx.z;
    int m0 = blockIdx.y * 128;
    const bf16* V  = g_kv2 + (size_t)b * HWsz * 256 + 128;
    const bf16* W2 = g_W2h + (size_t)b * 16384;
    int tid = threadIdx.x, lane = tid & 31, w = tid >> 5;

    for (int it = tid; it < 128 * 16; it += 256) {
        int r = it >> 4, c8 = (it & 15) * 8;
        *(uint4*)(As + r * SROW + c8) = *(const uint4*)(V + (size_t)(m0 + r) * 256 + c8);
        *(uint4*)(Bs + r * SROW + c8) = *(const uint4*)(W2 + (size_t)r * 128 + c8);
    }
    __syncthreads();

    int wm = (w & 1) * 64, wn = (w >> 1) * 32;
    int arow  = (lane & 7) + ((lane >> 3) & 1) * 8;
    int akoff = (lane >> 4) * 8;
    int brow  = (lane & 7);
    int bkoff = ((lane >> 3) & 1) * 8;
    int g = lane >> 2, t2 = (lane & 3) * 2;

    float acc[4][4][4];
    #pragma unroll
    for (int mi = 0; mi < 4; mi++)
        #pragma unroll
        for (int ni = 0; ni < 4; ni++)
            #pragma unroll
            for (int t = 0; t < 4; t++) acc[mi][ni][t] = 0.f;

    for (int k0 = 0; k0 < 128; k0 += 16) {
        unsigned af[4][4];
        unsigned bfr[4][2];
        #pragma unroll
        for (int mi = 0; mi < 4; mi++)
            ldm_x4(af[mi], sptr(As + (wm + 16 * mi + arow) * SROW + k0 + akoff));
        #pragma unroll
        for (int ni = 0; ni < 4; ni++)
            ldm_x2(bfr[ni], sptr(Bs + (wn + 8 * ni + brow) * SROW + k0 + bkoff));
        #pragma unroll
        for (int mi = 0; mi < 4; mi++)
            #pragma unroll
            for (int ni = 0; ni < 4; ni++)
                mma16816(acc[mi][ni], af[mi], bfr[ni]);
    }

    const float* curb = cur + (size_t)b * HWsz * 128;
    float* outb = out + (size_t)b * HWsz * 128;
    #pragma unroll
    for (int mi = 0; mi < 4; mi++) {
        int r0 = m0 + wm + 16 * mi + g;
        #pragma unroll
        for (int ni = 0; ni < 4; ni++) {
            int col = wn + 8 * ni + t2;
            float2 bb = *(const float2*)(out_b + col);
            float2 c0 = *(const float2*)(curb + (size_t)r0 * 128 + col);
            float2 c1 = *(const float2*)(curb + (size_t)(r0 + 8) * 128 + col);
            *(float2*)(outb + (size_t)r0 * 128 + col) =
                make_float2(acc[mi][ni][0] + bb.x + c0.x, acc[mi][ni][1] + bb.y + c0.y);
            *(float2*)(outb + (size_t)(r0 + 8) * 128 + col) =
                make_float2(acc[mi][ni][2] + bb.x + c1.x, acc[mi][ni][3] + bb.y + c1.y);
        }
    }
}

// ---------------- host ----------------
extern "C" void kernel_launch(void* const* d_in, const int* in_sizes, int n_in,
                              void* d_out, int out_size)
{
    const float* pre   = (const float*)d_in[0];
    const float* cur   = (const float*)d_in[1];
    const float* ln1_w = (const float*)d_in[2];
    const float* ln1_b = (const float*)d_in[3];
    const float* ln2_w = (const float*)d_in[4];
    const float* ln2_b = (const float*)d_in[5];
    const float* q_w1  = (const float*)d_in[6];
    const float* q_b1  = (const float*)d_in[7];
    const float* q_w2  = (const float*)d_in[8];
    const float* q_b2  = (const float*)d_in[9];
    const float* kv_w1 = (const float*)d_in[10];
    const float* kv_b1 = (const float*)d_in[11];
    const float* kv_w2 = (const float*)d_in[12];
    const float* kv_b2 = (const float*)d_in[13];
    const float* out_w = (const float*)d_in[14];
    const float* out_b = (const float*)d_in[15];
    float* out = (float*)d_out;

    bf16 *p_wq, *p_wkv, *p_q1, *p_kv1, *p_q2, *p_kv2;
    cudaGetSymbolAddress((void**)&p_wq,  g_wq);
    cudaGetSymbolAddress((void**)&p_wkv, g_wkv);
    cudaGetSymbolAddress((void**)&p_q1,  g_q1);
    cudaGetSymbolAddress((void**)&p_kv1, g_kv1);
    cudaGetSymbolAddress((void**)&p_q2,  g_q2);
    cudaGetSymbolAddress((void**)&p_kv2, g_kv2);

    const int SMEM_GEMM = 2 * 128 * SROW * (int)sizeof(bf16);  // 69632
    cudaFuncSetAttribute(lngemm, cudaFuncAttributeMaxDynamicSharedMemorySize, SMEM_GEMM);
    cudaFuncSetAttribute(vgemm,  cudaFuncAttributeMaxDynamicSharedMemorySize, SMEM_GEMM);

    // 0. weights to bf16
    prep_weights<<<128, 256>>>(q_w1, kv_w1);

    // 1. fused LN + 1x1 conv GEMMs
    lngemm<<<dim3(1, Ntot / 128), 256, SMEM_GEMM>>>(cur, p_wq,  ln2_w, ln2_b, q_b1,  p_q1,  1, 128);
    lngemm<<<dim3(1, Ntot / 128), 256, SMEM_GEMM>>>(pre, p_wkv, ln1_w, ln1_b, kv_b1, p_kv1, 2, 256);

    // 2. depthwise 3x3 (+sumsq partials for q and k)
    dwconv_kernel<<<dim3(64, 4, Bsz), 256>>>(p_q1,  p_q2,  q_w2,  q_b2,  128, 0, 4);
    dwconv_kernel<<<dim3(64, 8, Bsz), 256>>>(p_kv1, p_kv2, kv_w2, kv_b2, 256, 1, 4);

    // 3. l2 norms
    norm_reduce_kernel<<<16, 128>>>();

    // 4. QK^T partials (bf16 mma)
    qk_kernel<<<128, 256>>>();

    // 5. reduce + scale + softmax
    softmax_kernel<<<128, 256>>>();

    // 6. W2 = out_w @ att
    w2_kernel<<<Bsz, 256>>>(out_w);

    // 7. final fused GEMM + bias + residual
    vgemm<<<dim3(1, HWsz / 128, Bsz), 256, SMEM_GEMM>>>(cur, out_b, out);

    (void)in_sizes; (void)n_in; (void)out_size;
}

// round 5
// speedup vs baseline: 3.6394x; 1.4654x over previous
#include <cuda_runtime.h>
#include <cuda_bf16.h>
#include <cstdint>
#include <cstring>
#include <math.h>

#define Bsz 8
#define HWsz 16384
#define Cch 128
#define Ntot (Bsz*HWsz)   // 131072 rows
#define NCHUNK 32         // qk split-K chunks per batch
typedef __nv_bfloat16 bf16;

// ---------------- scratch (device globals; no allocation) ----------------
__device__ bf16  g_wq[Cch*Cch];
__device__ bf16  g_wkv[2*Cch*Cch];
__device__ bf16  g_q1[(size_t)Ntot*Cch];
__device__ bf16  g_kv1[(size_t)Ntot*2*Cch];
__device__ bf16  g_q2[(size_t)Ntot*Cch];
__device__ bf16  g_kv2[(size_t)Ntot*2*Cch];
__device__ float g_att_part[(size_t)Bsz*NCHUNK*Cch*Cch];
__device__ float g_att[(size_t)Bsz*Cch*Cch];
__device__ float g_norm_part[2*Bsz*16*Cch];
__device__ float g_invnorm[2*Bsz*Cch];
__device__ bf16  g_W2h[Bsz*Cch*Cch];

// ---------------- mma / ldmatrix helpers ----------------
__device__ __forceinline__ unsigned sptr(const void* p) {
    return (unsigned)__cvta_generic_to_shared(p);
}
__device__ __forceinline__ void ldm_x4(unsigned* r, unsigned a) {
    asm volatile("ldmatrix.sync.aligned.m8n8.x4.shared.b16 {%0,%1,%2,%3}, [%4];"
        : "=r"(r[0]), "=r"(r[1]), "=r"(r[2]), "=r"(r[3]) : "r"(a));
}
__device__ __forceinline__ void ldm_x4_t(unsigned* r, unsigned a) {
    asm volatile("ldmatrix.sync.aligned.m8n8.x4.trans.shared.b16 {%0,%1,%2,%3}, [%4];"
        : "=r"(r[0]), "=r"(r[1]), "=r"(r[2]), "=r"(r[3]) : "r"(a));
}
__device__ __forceinline__ void ldm_x2(unsigned* r, unsigned a) {
    asm volatile("ldmatrix.sync.aligned.m8n8.x2.shared.b16 {%0,%1}, [%2];"
        : "=r"(r[0]), "=r"(r[1]) : "r"(a));
}
__device__ __forceinline__ void ldm_x2_t(unsigned* r, unsigned a) {
    asm volatile("ldmatrix.sync.aligned.m8n8.x2.trans.shared.b16 {%0,%1}, [%2];"
        : "=r"(r[0]), "=r"(r[1]) : "r"(a));
}
__device__ __forceinline__ void mma16816(float* c, const unsigned* a, const unsigned* b) {
    asm volatile("mma.sync.aligned.m16n8k16.row.col.f32.bf16.bf16.f32 "
        "{%0,%1,%2,%3},{%4,%5,%6,%7},{%8,%9},{%0,%1,%2,%3};"
        : "+f"(c[0]), "+f"(c[1]), "+f"(c[2]), "+f"(c[3])
        : "r"(a[0]), "r"(a[1]), "r"(a[2]), "r"(a[3]), "r"(b[0]), "r"(b[1]));
}

#define SROW 136   // smem row stride in halves (128 + 8 pad -> conflict-free ldmatrix)

// ---------------- weight prep: fp32 -> bf16 ----------------
__global__ void prep_weights(const float* __restrict__ qw, const float* __restrict__ kvw)
{
    int i = blockIdx.x * 256 + threadIdx.x;
    if (i < Cch * Cch)     g_wq[i]  = __float2bfloat16_rn(qw[i]);
    if (i < 2 * Cch * Cch) g_wkv[i] = __float2bfloat16_rn(kvw[i]);
}

// ---------------- fused LayerNorm + 1x1-conv GEMM (bf16 mma), q & kv merged ----------------
__global__ __launch_bounds__(256)
void lngemm(const float* __restrict__ cur, const float* __restrict__ pre,
            const float* __restrict__ ln2w, const float* __restrict__ ln2b,
            const float* __restrict__ ln1w, const float* __restrict__ ln1b,
            const float* __restrict__ qb, const float* __restrict__ kvb)
{
    extern __shared__ bf16 sm[];
    bf16* As = sm;               // [128][SROW]
    bf16* Ws = sm + 128 * SROW;  // [128][SROW]
    int tid = threadIdx.x, lane = tid & 31, w = tid >> 5;
    int m0 = blockIdx.y * 128;

    const float* A;  const bf16* Wg;  const float* lnw;  const float* lnb;
    const float* bias;  bf16* C;  int ntiles, ldc;
    if (blockIdx.z == 0) {
        A = cur; Wg = g_wq;  lnw = ln2w; lnb = ln2b; bias = qb;  C = g_q1;  ntiles = 1; ldc = 128;
    } else {
        A = pre; Wg = g_wkv; lnw = ln1w; lnb = ln1b; bias = kvb; C = g_kv1; ntiles = 2; ldc = 256;
    }

    // LN stats + stage A (each warp: 16 rows)
    float4 wv = *(const float4*)(lnw + lane * 4);
    float4 bv = *(const float4*)(lnb + lane * 4);
    for (int i = 0; i < 16; i++) {
        int rl = w * 16 + i;
        float4 v = *(const float4*)(A + (size_t)(m0 + rl) * 128 + lane * 4);
        float s  = v.x + v.y + v.z + v.w;
        float ss = fmaf(v.x, v.x, fmaf(v.y, v.y, fmaf(v.z, v.z, v.w * v.w)));
        #pragma unroll
        for (int o = 16; o; o >>= 1) {
            s  += __shfl_xor_sync(0xFFFFFFFFu, s,  o);
            ss += __shfl_xor_sync(0xFFFFFFFFu, ss, o);
        }
        float mu  = s * (1.0f / 128.0f);
        float inv = rsqrtf(ss * (1.0f / 128.0f) - mu * mu + 1e-5f);
        float x0 = (v.x - mu) * inv * wv.x + bv.x;
        float x1 = (v.y - mu) * inv * wv.y + bv.y;
        float x2 = (v.z - mu) * inv * wv.z + bv.z;
        float x3 = (v.w - mu) * inv * wv.w + bv.w;
        __nv_bfloat162 p0 = __floats2bfloat162_rn(x0, x1);
        __nv_bfloat162 p1 = __floats2bfloat162_rn(x2, x3);
        *(__nv_bfloat162*)(As + rl * SROW + lane * 4)     = p0;
        *(__nv_bfloat162*)(As + rl * SROW + lane * 4 + 2) = p1;
    }

    int wm = (w & 1) * 64, wn = (w >> 1) * 32;
    int arow  = (lane & 7) + ((lane >> 3) & 1) * 8;
    int akoff = (lane >> 4) * 8;
    int brow  = (lane & 7);
    int bkoff = ((lane >> 3) & 1) * 8;
    int g = lane >> 2, t2 = (lane & 3) * 2;

    for (int nt = 0; nt < ntiles; nt++) {
        if (nt) __syncthreads();
        for (int it = tid; it < 128 * 16; it += 256) {
            int o = it >> 4, c8 = (it & 15) * 8;
            *(uint4*)(Ws + o * SROW + c8) =
                *(const uint4*)(Wg + (size_t)(nt * 128 + o) * 128 + c8);
        }
        __syncthreads();

        float acc[4][4][4];
        #pragma unroll
        for (int mi = 0; mi < 4; mi++)
            #pragma unroll
            for (int ni = 0; ni < 4; ni++)
                #pragma unroll
                for (int t = 0; t < 4; t++) acc[mi][ni][t] = 0.f;

        for (int k0 = 0; k0 < 128; k0 += 16) {
            unsigned af[4][4];
            unsigned bfr[4][2];
            #pragma unroll
            for (int mi = 0; mi < 4; mi++)
                ldm_x4(af[mi], sptr(As + (wm + 16 * mi + arow) * SROW + k0 + akoff));
            #pragma unroll
            for (int ni = 0; ni < 4; ni++)
                ldm_x2(bfr[ni], sptr(Ws + (wn + 8 * ni + brow) * SROW + k0 + bkoff));
            #pragma unroll
            for (int mi = 0; mi < 4; mi++)
                #pragma unroll
                for (int ni = 0; ni < 4; ni++)
                    mma16816(acc[mi][ni], af[mi], bfr[ni]);
        }

        #pragma unroll
        for (int mi = 0; mi < 4; mi++) {
            int r0 = m0 + wm + 16 * mi + g;
            #pragma unroll
            for (int ni = 0; ni < 4; ni++) {
                int col = nt * 128 + wn + 8 * ni + t2;
                float2 bb = *(const float2*)(bias + col);
                __nv_bfloat162 o0 = __floats2bfloat162_rn(acc[mi][ni][0] + bb.x, acc[mi][ni][1] + bb.y);
                __nv_bfloat162 o1 = __floats2bfloat162_rn(acc[mi][ni][2] + bb.x, acc[mi][ni][3] + bb.y);
                *(__nv_bfloat162*)(C + (size_t)r0 * ldc + col)       = o0;
                *(__nv_bfloat162*)(C + (size_t)(r0 + 8) * ldc + col) = o1;
            }
        }
    }
}

// ---------------- depthwise 3x3 conv: bf16 smem, hfma2, 32x32 tiles, q+kv merged ----------------
// grid: (16 tiles, 12 groups, B). block 256. groups 0-3: q (ch=128); 4-11: kv (ch=256).
// smem tile: 34x34 positions x 32 ch bf16 = 73984 B (dynamic).
__global__ __launch_bounds__(256)
void dwconv_kernel(const float* __restrict__ q_wt, const float* __restrict__ q_bias,
                   const float* __restrict__ kv_wt, const float* __restrict__ kv_bias)
{
    extern __shared__ bf16 s[];            // [34*34][32]
    __shared__ float2 red2[256];
    int tile = blockIdx.x, gg = blockIdx.y, b = blockIdx.z;
    int ty0 = (tile >> 2) * 32, tx0 = (tile & 3) * 32;
    int tid = threadIdx.x;

    const bf16* in; bf16* out; const float* wt; const float* bias;
    int ch, grp, which, do_sq;
    if (gg < 4) { in = g_q1;  out = g_q2;  wt = q_wt;  bias = q_bias;  ch = 128; grp = gg;     which = 0; do_sq = 1; }
    else        { in = g_kv1; out = g_kv2; wt = kv_wt; bias = kv_bias; ch = 256; grp = gg - 4; which = 1; do_sq = (gg - 4) < 4; }

    const size_t base = (size_t)b * HWsz * ch + (size_t)grp * 32;

    // load 34x34x32 halo tile (uint4 = 8 bf16)
    for (int idx = tid; idx < 34 * 34 * 4; idx += 256) {
        int pos = idx >> 2, c8 = (idx & 3) * 8;
        int y = pos / 34, x = pos - y * 34;
        int gy = ty0 + y - 1, gx = tx0 + x - 1;
        uint4 v = make_uint4(0u, 0u, 0u, 0u);
        if (gy >= 0 && gy < 128 && gx >= 0 && gx < 128)
            v = *(const uint4*)(in + base + (size_t)(gy * 128 + gx) * ch + c8);
        *(uint4*)(s + pos * 32 + c8) = v;
    }
    __syncthreads();

    // compute: thread = (warp w: 4 rows) x (xl: x parity) x (cp: channel pair)
    int cp = tid & 15, xl = (tid >> 4) & 1, wrp = tid >> 5;
    int cg = grp * 32 + cp * 2;
    __nv_bfloat162 w2[9];
    #pragma unroll
    for (int t = 0; t < 9; t++)
        w2[t] = __floats2bfloat162_rn(wt[cg * 9 + t], wt[(cg + 1) * 9 + t]);
    __nv_bfloat162 bb2 = __floats2bfloat162_rn(bias[cg], bias[cg + 1]);

    const __nv_bfloat162* s2 = (const __nv_bfloat162*)s;   // word idx = pos*16 + cp
    float sq0 = 0.f, sq1 = 0.f;

    #pragma unroll 1
    for (int r = 0; r < 4; r++) {
        int yr = wrp * 4 + r;            // output row within tile
        #pragma unroll 4
        for (int xi = 0; xi < 16; xi++) {
            int x = xl + 2 * xi;         // output col within tile
            __nv_bfloat162 acc = bb2;
            int p00 = (yr * 34 + x) * 16 + cp;   // tap (dy=0,dx=0); output center is (yr+1,x+1)
            #pragma unroll
            for (int dy = 0; dy < 3; dy++) {
                int pb = p00 + dy * (34 * 16);
                acc = __hfma2(s2[pb],      w2[dy * 3],     acc);
                acc = __hfma2(s2[pb + 16], w2[dy * 3 + 1], acc);
                acc = __hfma2(s2[pb + 32], w2[dy * 3 + 2], acc);
            }
            *(__nv_bfloat162*)(out + base + (size_t)((ty0 + yr) * 128 + tx0 + x) * ch + cp * 2) = acc;
            if (do_sq) {
                float a0 = __bfloat162float(__low2bfloat16(acc));
                float a1 = __bfloat162float(__high2bfloat16(acc));
                sq0 = fmaf(a0, a0, sq0);
                sq1 = fmaf(a1, a1, sq1);
            }
        }
    }

    if (do_sq) {
        red2[tid] = make_float2(sq0, sq1);
        __syncthreads();
        if (tid < 16) {
            float t0 = 0.f, t1 = 0.f;
            #pragma unroll
            for (int ww = 0; ww < 8; ww++)
                #pragma unroll
                for (int xx = 0; xx < 2; xx++) {
                    float2 v = red2[ww * 32 + xx * 16 + tid];
                    t0 += v.x; t1 += v.y;
                }
            float* dst = g_norm_part + ((size_t)(which * 8 + b) * 16 + tile) * 128 + grp * 32 + tid * 2;
            dst[0] = t0; dst[1] = t1;
        }
    }
}

__global__ __launch_bounds__(128)
void norm_reduce_kernel()
{
    int idx = blockIdx.x;   // which*8 + b
    int c = threadIdx.x;
    float s = 0.f;
    #pragma unroll
    for (int t = 0; t < 16; t++)
        s += g_norm_part[((size_t)idx * 16 + t) * 128 + c];
    g_invnorm[idx * 128 + c] = 1.0f / fmaxf(sqrtf(s), 1e-12f);
}

// ---------------- QK^T (bf16 mma, split-K over n), partials fp32, reg double-buffer ----------------
__global__ __launch_bounds__(256)
void qk_kernel()
{
    __shared__ bf16 Qs[32 * SROW];
    __shared__ bf16 Ks[32 * SROW];
    int bx = blockIdx.x;
    int b = bx >> 5, chunk = bx & 31;
    const bf16* Qb = g_q2  + (size_t)b * HWsz * 128;
    const bf16* Kb = g_kv2 + (size_t)b * HWsz * 256;
    int tid = threadIdx.x, lane = tid & 31, w = tid >> 5;
    int wm = (w & 1) * 64, wn = (w >> 1) * 32;

    int at_row  = (lane & 7) + ((lane >> 4) & 1) * 8;
    int at_coff = ((lane >> 3) & 1) * 8;
    int bt_row  = (lane & 7) + ((lane >> 3) & 1) * 8;
    int g = lane >> 2, t2 = (lane & 3) * 2;

    // staging slots for this thread: it = tid + 256*j
    int r0s = tid >> 4,        c0s = (tid & 15) * 8;        // j=0
    int r1s = (tid + 256) >> 4, c1s = ((tid + 256) & 15) * 8; // j=1

    float acc[4][4][4];
    #pragma unroll
    for (int mi = 0; mi < 4; mi++)
        #pragma unroll
        for (int ni = 0; ni < 4; ni++)
            #pragma unroll
            for (int t = 0; t < 4; t++) acc[mi][ni][t] = 0.f;

    const int NS = 16;          // 16 stages x 32 rows = 512 rows per chunk
    int nbase = chunk * 512;

    uint4 pq0, pq1, pk0, pk1;
    {
        int n0 = nbase;
        pq0 = *(const uint4*)(Qb + (size_t)(n0 + r0s) * 128 + c0s);
        pq1 = *(const uint4*)(Qb + (size_t)(n0 + r1s) * 128 + c1s);
        pk0 = *(const uint4*)(Kb + (size_t)(n0 + r0s) * 256 + c0s);
        pk1 = *(const uint4*)(Kb + (size_t)(n0 + r1s) * 256 + c1s);
    }

    for (int st = 0; st < NS; st++) {
        *(uint4*)(Qs + r0s * SROW + c0s) = pq0;
        *(uint4*)(Qs + r1s * SROW + c1s) = pq1;
        *(uint4*)(Ks + r0s * SROW + c0s) = pk0;
        *(uint4*)(Ks + r1s * SROW + c1s) = pk1;
        __syncthreads();

        if (st + 1 < NS) {
            int n0 = nbase + (st + 1) * 32;
            pq0 = *(const uint4*)(Qb + (size_t)(n0 + r0s) * 128 + c0s);
            pq1 = *(const uint4*)(Qb + (size_t)(n0 + r1s) * 128 + c1s);
            pk0 = *(const uint4*)(Kb + (size_t)(n0 + r0s) * 256 + c0s);
            pk1 = *(const uint4*)(Kb + (size_t)(n0 + r1s) * 256 + c1s);
        }

        #pragma unroll
        for (int k0 = 0; k0 < 32; k0 += 16) {
            unsigned af[4][4];
            unsigned bfr[4][2];
            #pragma unroll
            for (int mi = 0; mi < 4; mi++)
                ldm_x4_t(af[mi], sptr(Qs + (k0 + at_row) * SROW + wm + 16 * mi + at_coff));
            #pragma unroll
            for (int ni = 0; ni < 4; ni++)
                ldm_x2_t(bfr[ni], sptr(Ks + (k0 + bt_row) * SROW + wn + 8 * ni));
            #pragma unroll
            for (int mi = 0; mi < 4; mi++)
                #pragma unroll
                for (int ni = 0; ni < 4; ni++)
                    mma16816(acc[mi][ni], af[mi], bfr[ni]);
        }
        __syncthreads();
    }

    float* P = g_att_part + (size_t)bx * 16384;
    #pragma unroll
    for (int mi = 0; mi < 4; mi++) {
        int row = wm + 16 * mi + g;
        #pragma unroll
        for (int ni = 0; ni < 4; ni++) {
            int col = wn + 8 * ni + t2;
            *(float2*)(P + row * 128 + col)       = make_float2(acc[mi][ni][0], acc[mi][ni][1]);
            *(float2*)(P + (row + 8) * 128 + col) = make_float2(acc[mi][ni][2], acc[mi][ni][3]);
        }
    }
}

// ---------------- reduce partials + scale + softmax ----------------
__global__ __launch_bounds__(256)
void softmax_kernel()
{
    int warp = blockIdx.x * 8 + (threadIdx.x >> 5);
    int lane = threadIdx.x & 31;
    int b = warp >> 7, c = warp & 127;

    float4 s = make_float4(0.f, 0.f, 0.f, 0.f);
    #pragma unroll
    for (int ch = 0; ch < NCHUNK; ch++) {
        float4 v = ((const float4*)(g_att_part + (size_t)((b * NCHUNK + ch) * 128 + c) * 128))[lane];
        s.x += v.x; s.y += v.y; s.z += v.z; s.w += v.w;
    }
    float invq = g_invnorm[b * 128 + c];
    float4 ik = ((const float4*)(g_invnorm + 1024 + b * 128))[lane];

    float l0 = s.x * invq * ik.x;
    float l1 = s.y * invq * ik.y;
    float l2 = s.z * invq * ik.z;
    float l3 = s.w * invq * ik.w;

    float mx = fmaxf(fmaxf(l0, l1), fmaxf(l2, l3));
    #pragma unroll
    for (int o = 16; o; o >>= 1) mx = fmaxf(mx, __shfl_xor_sync(0xFFFFFFFFu, mx, o));
    float e0 = expf(l0 - mx), e1 = expf(l1 - mx), e2 = expf(l2 - mx), e3 = expf(l3 - mx);
    float sum = e0 + e1 + e2 + e3;
    #pragma unroll
    for (int o = 16; o; o >>= 1) sum += __shfl_xor_sync(0xFFFFFFFFu, sum, o);
    float inv = 1.0f / sum;

    ((float4*)(g_att + (size_t)(b * 128 + c) * 128))[lane] =
        make_float4(e0 * inv, e1 * inv, e2 * inv, e3 * inv);
}

// ---------------- W2[b] = out_w @ att[b]  (fp32 compute, bf16 out) ----------------
__global__ __launch_bounds__(256)
void w2_kernel(const float* __restrict__ out_w)
{
    __shared__ float sa[16 * 128];
    int b = blockIdx.x, tid = threadIdx.x;
    int c = tid >> 1, dh = (tid & 1) * 64;
    float acc[64];
    #pragma unroll
    for (int j = 0; j < 64; j++) acc[j] = 0.f;

    for (int e0 = 0; e0 < 128; e0 += 16) {
        if (e0) __syncthreads();
        for (int it = tid; it < 2048; it += 256)
            sa[it] = g_att[(size_t)b * 16384 + (size_t)(e0 + (it >> 7)) * 128 + (it & 127)];
        __syncthreads();
        for (int e = 0; e < 16; e++) {
            float wvv = out_w[c * 128 + e0 + e];
            #pragma unroll
            for (int j = 0; j < 64; j++)
                acc[j] = fmaf(wvv, sa[e * 128 + dh + j], acc[j]);
        }
    }
    for (int j = 0; j < 64; j++)
        g_W2h[(size_t)b * 16384 + c * 128 + dh + j] = __float2bfloat16_rn(acc[j]);
}

// ---------------- final: out[b,n,c] = sum_d W2[c,d] v[b,n,d] + out_b[c] + cur ----------------
__global__ __launch_bounds__(256)
void vgemm(const float* __restrict__ cur, const float* __restrict__ out_b,
           float* __restrict__ out)
{
    extern __shared__ bf16 sm[];
    bf16* As = sm;               // v tile [128][SROW]
    bf16* Bs = sm + 128 * SROW;  // W2 [128][SROW]
    int b = blockIdx.z;
    int m0 = blockIdx.y * 128;
    const bf16* V  = g_kv2 + (size_t)b * HWsz * 256 + 128;
    const bf16* W2 = g_W2h + (size_t)b * 16384;
    int tid = threadIdx.x, lane = tid & 31, w = tid >> 5;

    for (int it = tid; it < 128 * 16; it += 256) {
        int r = it >> 4, c8 = (it & 15) * 8;
        *(uint4*)(As + r * SROW + c8) = *(const uint4*)(V + (size_t)(m0 + r) * 256 + c8);
        *(uint4*)(Bs + r * SROW + c8) = *(const uint4*)(W2 + (size_t)r * 128 + c8);
    }
    __syncthreads();

    int wm = (w & 1) * 64, wn = (w >> 1) * 32;
    int arow  = (lane & 7) + ((lane >> 3) & 1) * 8;
    int akoff = (lane >> 4) * 8;
    int brow  = (lane & 7);
    int bkoff = ((lane >> 3) & 1) * 8;
    int g = lane >> 2, t2 = (lane & 3) * 2;

    float acc[4][4][4];
    #pragma unroll
    for (int mi = 0; mi < 4; mi++)
        #pragma unroll
        for (int ni = 0; ni < 4; ni++)
            #pragma unroll
            for (int t = 0; t < 4; t++) acc[mi][ni][t] = 0.f;

    for (int k0 = 0; k0 < 128; k0 += 16) {
        unsigned af[4][4];
        unsigned bfr[4][2];
        #pragma unroll
        for (int mi = 0; mi < 4; mi++)
            ldm_x4(af[mi], sptr(As + (wm + 16 * mi + arow) * SROW + k0 + akoff));
        #pragma unroll
        for (int ni = 0; ni < 4; ni++)
            ldm_x2(bfr[ni], sptr(Bs + (wn + 8 * ni + brow) * SROW + k0 + bkoff));
        #pragma unroll
        for (int mi = 0; mi < 4; mi++)
            #pragma unroll
            for (int ni = 0; ni < 4; ni++)
                mma16816(acc[mi][ni], af[mi], bfr[ni]);
    }

    const float* curb = cur + (size_t)b * HWsz * 128;
    float* outb = out + (size_t)b * HWsz * 128;
    #pragma unroll
    for (int mi = 0; mi < 4; mi++) {
        int r0 = m0 + wm + 16 * mi + g;
        #pragma unroll
        for (int ni = 0; ni < 4; ni++) {
            int col = wn + 8 * ni + t2;
            float2 bb = *(const float2*)(out_b + col);
            float2 c0 = *(const float2*)(curb + (size_t)r0 * 128 + col);
            float2 c1 = *(const float2*)(curb + (size_t)(r0 + 8) * 128 + col);
            *(float2*)(outb + (size_t)r0 * 128 + col) =
                make_float2(acc[mi][ni][0] + bb.x + c0.x, acc[mi][ni][1] + bb.y + c0.y);
            *(float2*)(outb + (size_t)(r0 + 8) * 128 + col) =
                make_float2(acc[mi][ni][2] + bb.x + c1.x, acc[mi][ni][3] + bb.y + c1.y);
        }
    }
}

// ---------------- host ----------------
extern "C" void kernel_launch(void* const* d_in, const int* in_sizes, int n_in,
                              void* d_out, int out_size)
{
    const float* pre   = (const float*)d_in[0];
    const float* cur   = (const float*)d_in[1];
    const float* ln1_w = (const float*)d_in[2];
    const float* ln1_b = (const float*)d_in[3];
    const float* ln2_w = (const float*)d_in[4];
    const float* ln2_b = (const float*)d_in[5];
    const float* q_w1  = (const float*)d_in[6];
    const float* q_b1  = (const float*)d_in[7];
    const float* q_w2  = (const float*)d_in[8];
    const float* q_b2  = (const float*)d_in[9];
    const float* kv_w1 = (const float*)d_in[10];
    const float* kv_b1 = (const float*)d_in[11];
    const float* kv_w2 = (const float*)d_in[12];
    const float* kv_b2 = (const float*)d_in[13];
    const float* out_w = (const float*)d_in[14];
    const float* out_b = (const float*)d_in[15];
    float* out = (float*)d_out;

    const int SMEM_GEMM = 2 * 128 * SROW * (int)sizeof(bf16);  // 69632
    const int SMEM_DW   = 34 * 34 * 32 * (int)sizeof(bf16);    // 73984
    cudaFuncSetAttribute(lngemm, cudaFuncAttributeMaxDynamicSharedMemorySize, SMEM_GEMM);
    cudaFuncSetAttribute(vgemm,  cudaFuncAttributeMaxDynamicSharedMemorySize, SMEM_GEMM);
    cudaFuncSetAttribute(dwconv_kernel, cudaFuncAttributeMaxDynamicSharedMemorySize, SMEM_DW);

    // 0. weights to bf16
    prep_weights<<<128, 256>>>(q_w1, kv_w1);

    // 1. fused LN + 1x1 conv GEMMs (q and kv merged via z)
    lngemm<<<dim3(1, Ntot / 128, 2), 256, SMEM_GEMM>>>(cur, pre, ln2_w, ln2_b, ln1_w, ln1_b,
                                                       q_b1, kv_b1);

    // 2. depthwise 3x3 (+sumsq partials), q+kv merged
    dwconv_kernel<<<dim3(16, 12, Bsz), 256, SMEM_DW>>>(q_w2, q_b2, kv_w2, kv_b2);

    // 3. l2 norms
    norm_reduce_kernel<<<16, 128>>>();

    // 4. QK^T partials (bf16 mma, 32 chunks)
    qk_kernel<<<Bsz * NCHUNK, 256>>>();

    // 5. reduce + scale + softmax
    softmax_kernel<<<128, 256>>>();

    // 6. W2 = out_w @ att
    w2_kernel<<<Bsz, 256>>>(out_w);

    // 7. final fused GEMM + bias + residual
    vgemm<<<dim3(1, HWsz / 128, Bsz), 256, SMEM_GEMM>>>(cur, out_b, out);

    (void)in_sizes; (void)n_in; (void)out_size;
}

// round 6
// speedup vs baseline: 3.7344x; 1.0261x over previous
#include <cuda_runtime.h>
#include <cuda_bf16.h>
#include <cstdint>
#include <cstring>
#include <math.h>

#define Bsz 8
#define HWsz 16384
#define Cch 128
#define Ntot (Bsz*HWsz)   // 131072 rows
#define NCHUNK 32         // qk split-K chunks per batch
typedef __nv_bfloat16 bf16;

// ---------------- scratch (device globals; no allocation) ----------------
__device__ bf16  g_wq[Cch*Cch];
__device__ bf16  g_wkv[2*Cch*Cch];
__device__ bf16  g_q1[(size_t)Ntot*Cch];
__device__ bf16  g_kv1[(size_t)Ntot*2*Cch];
__device__ bf16  g_q2[(size_t)Ntot*Cch];
__device__ bf16  g_kv2[(size_t)Ntot*2*Cch];
__device__ float g_att_part[(size_t)Bsz*NCHUNK*Cch*Cch];
__device__ float g_att[(size_t)Bsz*Cch*Cch];
__device__ float g_norm_part[2*Bsz*16*Cch];
__device__ bf16  g_W2h[Bsz*Cch*Cch];

// ---------------- mma / ldmatrix helpers ----------------
__device__ __forceinline__ unsigned sptr(const void* p) {
    return (unsigned)__cvta_generic_to_shared(p);
}
__device__ __forceinline__ void ldm_x4(unsigned* r, unsigned a) {
    asm volatile("ldmatrix.sync.aligned.m8n8.x4.shared.b16 {%0,%1,%2,%3}, [%4];"
        : "=r"(r[0]), "=r"(r[1]), "=r"(r[2]), "=r"(r[3]) : "r"(a));
}
__device__ __forceinline__ void ldm_x4_t(unsigned* r, unsigned a) {
    asm volatile("ldmatrix.sync.aligned.m8n8.x4.trans.shared.b16 {%0,%1,%2,%3}, [%4];"
        : "=r"(r[0]), "=r"(r[1]), "=r"(r[2]), "=r"(r[3]) : "r"(a));
}
__device__ __forceinline__ void ldm_x2(unsigned* r, unsigned a) {
    asm volatile("ldmatrix.sync.aligned.m8n8.x2.shared.b16 {%0,%1}, [%2];"
        : "=r"(r[0]), "=r"(r[1]) : "r"(a));
}
__device__ __forceinline__ void ldm_x2_t(unsigned* r, unsigned a) {
    asm volatile("ldmatrix.sync.aligned.m8n8.x2.trans.shared.b16 {%0,%1}, [%2];"
        : "=r"(r[0]), "=r"(r[1]) : "r"(a));
}
__device__ __forceinline__ void mma16816(float* c, const unsigned* a, const unsigned* b) {
    asm volatile("mma.sync.aligned.m16n8k16.row.col.f32.bf16.bf16.f32 "
        "{%0,%1,%2,%3},{%4,%5,%6,%7},{%8,%9},{%0,%1,%2,%3};"
        : "+f"(c[0]), "+f"(c[1]), "+f"(c[2]), "+f"(c[3])
        : "r"(a[0]), "r"(a[1]), "r"(a[2]), "r"(a[3]), "r"(b[0]), "r"(b[1]));
}

#define SROW 136   // smem row stride in halves (128 + 8 pad -> conflict-free ldmatrix)

// ---------------- weight prep: fp32 -> bf16 ----------------
__global__ void prep_weights(const float* __restrict__ qw, const float* __restrict__ kvw)
{
    int i = blockIdx.x * 256 + threadIdx.x;
    if (i < Cch * Cch)     g_wq[i]  = __float2bfloat16_rn(qw[i]);
    if (i < 2 * Cch * Cch) g_wkv[i] = __float2bfloat16_rn(kvw[i]);
}

// ---------------- fused LayerNorm + 1x1-conv GEMM (bf16 mma), q & kv merged ----------------
__global__ __launch_bounds__(256)
void lngemm(const float* __restrict__ cur, const float* __restrict__ pre,
            const float* __restrict__ ln2w, const float* __restrict__ ln2b,
            const float* __restrict__ ln1w, const float* __restrict__ ln1b,
            const float* __restrict__ qb, const float* __restrict__ kvb)
{
    extern __shared__ bf16 sm[];
    bf16* As = sm;               // [128][SROW]
    bf16* Ws = sm + 128 * SROW;  // [128][SROW]  (weights, then reused for output staging)
    int tid = threadIdx.x, lane = tid & 31, w = tid >> 5;
    int m0 = blockIdx.y * 128;

    const float* A;  const bf16* Wg;  const float* lnw;  const float* lnb;
    const float* bias;  bf16* C;  int ntiles, ldc;
    if (blockIdx.z == 0) {
        A = cur; Wg = g_wq;  lnw = ln2w; lnb = ln2b; bias = qb;  C = g_q1;  ntiles = 1; ldc = 128;
    } else {
        A = pre; Wg = g_wkv; lnw = ln1w; lnb = ln1b; bias = kvb; C = g_kv1; ntiles = 2; ldc = 256;
    }

    // LN stats + stage A (each warp: 16 rows)
    float4 wv = *(const float4*)(lnw + lane * 4);
    float4 bv = *(const float4*)(lnb + lane * 4);
    for (int i = 0; i < 16; i++) {
        int rl = w * 16 + i;
        float4 v = *(const float4*)(A + (size_t)(m0 + rl) * 128 + lane * 4);
        float s  = v.x + v.y + v.z + v.w;
        float ss = fmaf(v.x, v.x, fmaf(v.y, v.y, fmaf(v.z, v.z, v.w * v.w)));
        #pragma unroll
        for (int o = 16; o; o >>= 1) {
            s  += __shfl_xor_sync(0xFFFFFFFFu, s,  o);
            ss += __shfl_xor_sync(0xFFFFFFFFu, ss, o);
        }
        float mu  = s * (1.0f / 128.0f);
        float inv = rsqrtf(ss * (1.0f / 128.0f) - mu * mu + 1e-5f);
        float x0 = (v.x - mu) * inv * wv.x + bv.x;
        float x1 = (v.y - mu) * inv * wv.y + bv.y;
        float x2 = (v.z - mu) * inv * wv.z + bv.z;
        float x3 = (v.w - mu) * inv * wv.w + bv.w;
        __nv_bfloat162 p0 = __floats2bfloat162_rn(x0, x1);
        __nv_bfloat162 p1 = __floats2bfloat162_rn(x2, x3);
        *(__nv_bfloat162*)(As + rl * SROW + lane * 4)     = p0;
        *(__nv_bfloat162*)(As + rl * SROW + lane * 4 + 2) = p1;
    }

    int wm = (w & 1) * 64, wn = (w >> 1) * 32;
    int arow  = (lane & 7) + ((lane >> 3) & 1) * 8;
    int akoff = (lane >> 4) * 8;
    int brow  = (lane & 7);
    int bkoff = ((lane >> 3) & 1) * 8;
    int g = lane >> 2, t2 = (lane & 3) * 2;

    for (int nt = 0; nt < ntiles; nt++) {
        if (nt) __syncthreads();        // previous copy-out done before restaging Ws
        for (int it = tid; it < 128 * 16; it += 256) {
            int o = it >> 4, c8 = (it & 15) * 8;
            *(uint4*)(Ws + o * SROW + c8) =
                *(const uint4*)(Wg + (size_t)(nt * 128 + o) * 128 + c8);
        }
        __syncthreads();

        float acc[4][4][4];
        #pragma unroll
        for (int mi = 0; mi < 4; mi++)
            #pragma unroll
            for (int ni = 0; ni < 4; ni++)
                #pragma unroll
                for (int t = 0; t < 4; t++) acc[mi][ni][t] = 0.f;

        for (int k0 = 0; k0 < 128; k0 += 16) {
            unsigned af[4][4];
            unsigned bfr[4][2];
            #pragma unroll
            for (int mi = 0; mi < 4; mi++)
                ldm_x4(af[mi], sptr(As + (wm + 16 * mi + arow) * SROW + k0 + akoff));
            #pragma unroll
            for (int ni = 0; ni < 4; ni++)
                ldm_x2(bfr[ni], sptr(Ws + (wn + 8 * ni + brow) * SROW + k0 + bkoff));
            #pragma unroll
            for (int mi = 0; mi < 4; mi++)
                #pragma unroll
                for (int ni = 0; ni < 4; ni++)
                    mma16816(acc[mi][ni], af[mi], bfr[ni]);
        }

        // epilogue: +bias, stage into Ws (conflict-free), then coalesced uint4 copy-out
        __syncthreads();   // all warps done reading Ws as weights
        #pragma unroll
        for (int mi = 0; mi < 4; mi++) {
            int r0 = wm + 16 * mi + g;
            #pragma unroll
            for (int ni = 0; ni < 4; ni++) {
                int col = wn + 8 * ni + t2;
                float2 bb = *(const float2*)(bias + nt * 128 + col);
                __nv_bfloat162 o0 = __floats2bfloat162_rn(acc[mi][ni][0] + bb.x, acc[mi][ni][1] + bb.y);
                __nv_bfloat162 o1 = __floats2bfloat162_rn(acc[mi][ni][2] + bb.x, acc[mi][ni][3] + bb.y);
                *(__nv_bfloat162*)(Ws + r0 * SROW + col)       = o0;
                *(__nv_bfloat162*)(Ws + (r0 + 8) * SROW + col) = o1;
            }
        }
        __syncthreads();
        for (int it = tid; it < 128 * 16; it += 256) {
            int r = it >> 4, c8 = (it & 15) * 8;
            *(uint4*)(C + (size_t)(m0 + r) * ldc + nt * 128 + c8) =
                *(const uint4*)(Ws + r * SROW + c8);
        }
    }
}

// ---------------- depthwise 3x3 conv: bf16 smem, hfma2, 32x32 tiles, q+kv merged ----------------
__global__ __launch_bounds__(256)
void dwconv_kernel(const float* __restrict__ q_wt, const float* __restrict__ q_bias,
                   const float* __restrict__ kv_wt, const float* __restrict__ kv_bias)
{
    extern __shared__ bf16 s[];            // [34*34][32]
    __shared__ float2 red2[256];
    int tile = blockIdx.x, gg = blockIdx.y, b = blockIdx.z;
    int ty0 = (tile >> 2) * 32, tx0 = (tile & 3) * 32;
    int tid = threadIdx.x;

    const bf16* in; bf16* out; const float* wt; const float* bias;
    int ch, grp, which, do_sq;
    if (gg < 4) { in = g_q1;  out = g_q2;  wt = q_wt;  bias = q_bias;  ch = 128; grp = gg;     which = 0; do_sq = 1; }
    else        { in = g_kv1; out = g_kv2; wt = kv_wt; bias = kv_bias; ch = 256; grp = gg - 4; which = 1; do_sq = (gg - 4) < 4; }

    const size_t base = (size_t)b * HWsz * ch + (size_t)grp * 32;

    for (int idx = tid; idx < 34 * 34 * 4; idx += 256) {
        int pos = idx >> 2, c8 = (idx & 3) * 8;
        int y = pos / 34, x = pos - y * 34;
        int gy = ty0 + y - 1, gx = tx0 + x - 1;
        uint4 v = make_uint4(0u, 0u, 0u, 0u);
        if (gy >= 0 && gy < 128 && gx >= 0 && gx < 128)
            v = *(const uint4*)(in + base + (size_t)(gy * 128 + gx) * ch + c8);
        *(uint4*)(s + pos * 32 + c8) = v;
    }
    __syncthreads();

    int cp = tid & 15, xl = (tid >> 4) & 1, wrp = tid >> 5;
    int cg = grp * 32 + cp * 2;
    __nv_bfloat162 w2[9];
    #pragma unroll
    for (int t = 0; t < 9; t++)
        w2[t] = __floats2bfloat162_rn(wt[cg * 9 + t], wt[(cg + 1) * 9 + t]);
    __nv_bfloat162 bb2 = __floats2bfloat162_rn(bias[cg], bias[cg + 1]);

    const __nv_bfloat162* s2 = (const __nv_bfloat162*)s;
    float sq0 = 0.f, sq1 = 0.f;

    #pragma unroll 1
    for (int r = 0; r < 4; r++) {
        int yr = wrp * 4 + r;
        #pragma unroll 4
        for (int xi = 0; xi < 16; xi++) {
            int x = xl + 2 * xi;
            __nv_bfloat162 acc = bb2;
            int p00 = (yr * 34 + x) * 16 + cp;
            #pragma unroll
            for (int dy = 0; dy < 3; dy++) {
                int pb = p00 + dy * (34 * 16);
                acc = __hfma2(s2[pb],      w2[dy * 3],     acc);
                acc = __hfma2(s2[pb + 16], w2[dy * 3 + 1], acc);
                acc = __hfma2(s2[pb + 32], w2[dy * 3 + 2], acc);
            }
            *(__nv_bfloat162*)(out + base + (size_t)((ty0 + yr) * 128 + tx0 + x) * ch + cp * 2) = acc;
            if (do_sq) {
                float a0 = __bfloat162float(__low2bfloat16(acc));
                float a1 = __bfloat162float(__high2bfloat16(acc));
                sq0 = fmaf(a0, a0, sq0);
                sq1 = fmaf(a1, a1, sq1);
            }
        }
    }

    if (do_sq) {
        red2[tid] = make_float2(sq0, sq1);
        __syncthreads();
        if (tid < 16) {
            float t0 = 0.f, t1 = 0.f;
            #pragma unroll
            for (int ww = 0; ww < 8; ww++)
                #pragma unroll
                for (int xx = 0; xx < 2; xx++) {
                    float2 v = red2[ww * 32 + xx * 16 + tid];
                    t0 += v.x; t1 += v.y;
                }
            float* dst = g_norm_part + ((size_t)(which * 8 + b) * 16 + tile) * 128 + grp * 32 + tid * 2;
            dst[0] = t0; dst[1] = t1;
        }
    }
}

// ---------------- QK^T (bf16 mma, split-K over n), partials fp32, reg double-buffer ----------------
__global__ __launch_bounds__(256)
void qk_kernel()
{
    __shared__ bf16 Qs[32 * SROW];
    __shared__ bf16 Ks[32 * SROW];
    int bx = blockIdx.x;
    int b = bx >> 5, chunk = bx & 31;
    const bf16* Qb = g_q2  + (size_t)b * HWsz * 128;
    const bf16* Kb = g_kv2 + (size_t)b * HWsz * 256;
    int tid = threadIdx.x, lane = tid & 31, w = tid >> 5;
    int wm = (w & 1) * 64, wn = (w >> 1) * 32;

    int at_row  = (lane & 7) + ((lane >> 4) & 1) * 8;
    int at_coff = ((lane >> 3) & 1) * 8;
    int bt_row  = (lane & 7) + ((lane >> 3) & 1) * 8;
    int g = lane >> 2, t2 = (lane & 3) * 2;

    int r0s = tid >> 4,         c0s = (tid & 15) * 8;
    int r1s = (tid + 256) >> 4, c1s = ((tid + 256) & 15) * 8;

    float acc[4][4][4];
    #pragma unroll
    for (int mi = 0; mi < 4; mi++)
        #pragma unroll
        for (int ni = 0; ni < 4; ni++)
            #pragma unroll
            for (int t = 0; t < 4; t++) acc[mi][ni][t] = 0.f;

    const int NS = 16;
    int nbase = chunk * 512;

    uint4 pq0, pq1, pk0, pk1;
    {
        int n0 = nbase;
        pq0 = *(const uint4*)(Qb + (size_t)(n0 + r0s) * 128 + c0s);
        pq1 = *(const uint4*)(Qb + (size_t)(n0 + r1s) * 128 + c1s);
        pk0 = *(const uint4*)(Kb + (size_t)(n0 + r0s) * 256 + c0s);
        pk1 = *(const uint4*)(Kb + (size_t)(n0 + r1s) * 256 + c1s);
    }

    for (int st = 0; st < NS; st++) {
        *(uint4*)(Qs + r0s * SROW + c0s) = pq0;
        *(uint4*)(Qs + r1s * SROW + c1s) = pq1;
        *(uint4*)(Ks + r0s * SROW + c0s) = pk0;
        *(uint4*)(Ks + r1s * SROW + c1s) = pk1;
        __syncthreads();

        if (st + 1 < NS) {
            int n0 = nbase + (st + 1) * 32;
            pq0 = *(const uint4*)(Qb + (size_t)(n0 + r0s) * 128 + c0s);
            pq1 = *(const uint4*)(Qb + (size_t)(n0 + r1s) * 128 + c1s);
            pk0 = *(const uint4*)(Kb + (size_t)(n0 + r0s) * 256 + c0s);
            pk1 = *(const uint4*)(Kb + (size_t)(n0 + r1s) * 256 + c1s);
        }

        #pragma unroll
        for (int k0 = 0; k0 < 32; k0 += 16) {
            unsigned af[4][4];
            unsigned bfr[4][2];
            #pragma unroll
            for (int mi = 0; mi < 4; mi++)
                ldm_x4_t(af[mi], sptr(Qs + (k0 + at_row) * SROW + wm + 16 * mi + at_coff));
            #pragma unroll
            for (int ni = 0; ni < 4; ni++)
                ldm_x2_t(bfr[ni], sptr(Ks + (k0 + bt_row) * SROW + wn + 8 * ni));
            #pragma unroll
            for (int mi = 0; mi < 4; mi++)
                #pragma unroll
                for (int ni = 0; ni < 4; ni++)
                    mma16816(acc[mi][ni], af[mi], bfr[ni]);
        }
        __syncthreads();
    }

    float* P = g_att_part + (size_t)bx * 16384;
    #pragma unroll
    for (int mi = 0; mi < 4; mi++) {
        int row = wm + 16 * mi + g;
        #pragma unroll
        for (int ni = 0; ni < 4; ni++) {
            int col = wn + 8 * ni + t2;
            *(float2*)(P + row * 128 + col)       = make_float2(acc[mi][ni][0], acc[mi][ni][1]);
            *(float2*)(P + (row + 8) * 128 + col) = make_float2(acc[mi][ni][2], acc[mi][ni][3]);
        }
    }
}

// ---------------- reduce partials + norms + softmax (norm_reduce folded in) ----------------
__global__ __launch_bounds__(256)
void softmax_kernel()
{
    __shared__ float iq_s[128];
    __shared__ float ik_s[128];
    int tid = threadIdx.x;
    int b = blockIdx.x >> 4;

    if (tid < 128) {
        float sq = 0.f, sk = 0.f;
        #pragma unroll
        for (int t = 0; t < 16; t++) {
            sq += g_norm_part[((size_t)b * 16 + t) * 128 + tid];
            sk += g_norm_part[((size_t)(8 + b) * 16 + t) * 128 + tid];
        }
        iq_s[tid] = 1.0f / fmaxf(sqrtf(sq), 1e-12f);
        ik_s[tid] = 1.0f / fmaxf(sqrtf(sk), 1e-12f);
    }
    __syncthreads();

    int warp = blockIdx.x * 8 + (tid >> 5);
    int lane = tid & 31;
    int c = warp & 127;

    float4 s = make_float4(0.f, 0.f, 0.f, 0.f);
    #pragma unroll 8
    for (int ch = 0; ch < NCHUNK; ch++) {
        float4 v = ((const float4*)(g_att_part + (size_t)((b * NCHUNK + ch) * 128 + c) * 128))[lane];
        s.x += v.x; s.y += v.y; s.z += v.z; s.w += v.w;
    }
    float invq = iq_s[c];
    float4 ik = ((const float4*)ik_s)[lane];

    float l0 = s.x * invq * ik.x;
    float l1 = s.y * invq * ik.y;
    float l2 = s.z * invq * ik.z;
    float l3 = s.w * invq * ik.w;

    float mx = fmaxf(fmaxf(l0, l1), fmaxf(l2, l3));
    #pragma unroll
    for (int o = 16; o; o >>= 1) mx = fmaxf(mx, __shfl_xor_sync(0xFFFFFFFFu, mx, o));
    float e0 = expf(l0 - mx), e1 = expf(l1 - mx), e2 = expf(l2 - mx), e3 = expf(l3 - mx);
    float sum = e0 + e1 + e2 + e3;
    #pragma unroll
    for (int o = 16; o; o >>= 1) sum += __shfl_xor_sync(0xFFFFFFFFu, sum, o);
    float inv = 1.0f / sum;

    ((float4*)(g_att + (size_t)(b * 128 + c) * 128))[lane] =
        make_float4(e0 * inv, e1 * inv, e2 * inv, e3 * inv);
}

// ---------------- W2[b] = out_w @ att[b]  (fp32 compute, bf16 out) ----------------
__global__ __launch_bounds__(256)
void w2_kernel(const float* __restrict__ out_w)
{
    __shared__ float sa[16 * 128];
    int b = blockIdx.x, tid = threadIdx.x;
    int c = tid >> 1, dh = (tid & 1) * 64;
    float acc[64];
    #pragma unroll
    for (int j = 0; j < 64; j++) acc[j] = 0.f;

    for (int e0 = 0; e0 < 128; e0 += 16) {
        if (e0) __syncthreads();
        for (int it = tid; it < 2048; it += 256)
            sa[it] = g_att[(size_t)b * 16384 + (size_t)(e0 + (it >> 7)) * 128 + (it & 127)];
        __syncthreads();
        for (int e = 0; e < 16; e++) {
            float wvv = out_w[c * 128 + e0 + e];
            #pragma unroll
            for (int j = 0; j < 64; j++)
                acc[j] = fmaf(wvv, sa[e * 128 + dh + j], acc[j]);
        }
    }
    for (int j = 0; j < 64; j++)
        g_W2h[(size_t)b * 16384 + c * 128 + dh + j] = __float2bfloat16_rn(acc[j]);
}

// ---------------- final: out[b,n,c] = sum_d W2[c,d] v[b,n,d] + out_b[c] + cur ----------------
__global__ __launch_bounds__(256)
void vgemm(const float* __restrict__ cur, const float* __restrict__ out_b,
           float* __restrict__ out)
{
    extern __shared__ bf16 sm[];
    bf16* As = sm;
    bf16* Bs = sm + 128 * SROW;
    int b = blockIdx.z;
    int m0 = blockIdx.y * 128;
    const bf16* V  = g_kv2 + (size_t)b * HWsz * 256 + 128;
    const bf16* W2 = g_W2h + (size_t)b * 16384;
    int tid = threadIdx.x, lane = tid & 31, w = tid >> 5;

    for (int it = tid; it < 128 * 16; it += 256) {
        int r = it >> 4, c8 = (it & 15) * 8;
        *(uint4*)(As + r * SROW + c8) = *(const uint4*)(V + (size_t)(m0 + r) * 256 + c8);
        *(uint4*)(Bs + r * SROW + c8) = *(const uint4*)(W2 + (size_t)r * 128 + c8);
    }
    __syncthreads();

    int wm = (w & 1) * 64, wn = (w >> 1) * 32;
    int arow  = (lane & 7) + ((lane >> 3) & 1) * 8;
    int akoff = (lane >> 4) * 8;
    int brow  = (lane & 7);
    int bkoff = ((lane >> 3) & 1) * 8;
    int g = lane >> 2, t2 = (lane & 3) * 2;

    float acc[4][4][4];
    #pragma unroll
    for (int mi = 0; mi < 4; mi++)
        #pragma unroll
        for (int ni = 0; ni < 4; ni++)
            #pragma unroll
            for (int t = 0; t < 4; t++) acc[mi][ni][t] = 0.f;

    for (int k0 = 0; k0 < 128; k0 += 16) {
        unsigned af[4][4];
        unsigned bfr[4][2];
        #pragma unroll
        for (int mi = 0; mi < 4; mi++)
            ldm_x4(af[mi], sptr(As + (wm + 16 * mi + arow) * SROW + k0 + akoff));
        #pragma unroll
        for (int ni = 0; ni < 4; ni++)
            ldm_x2(bfr[ni], sptr(Bs + (wn + 8 * ni + brow) * SROW + k0 + bkoff));
        #pragma unroll
        for (int mi = 0; mi < 4; mi++)
            #pragma unroll
            for (int ni = 0; ni < 4; ni++)
                mma16816(acc[mi][ni], af[mi], bfr[ni]);
    }

    const float* curb = cur + (size_t)b * HWsz * 128;
    float* outb = out + (size_t)b * HWsz * 128;
    #pragma unroll
    for (int mi = 0; mi < 4; mi++) {
        int r0 = m0 + wm + 16 * mi + g;
        #pragma unroll
        for (int ni = 0; ni < 4; ni++) {
            int col = wn + 8 * ni + t2;
            float2 bb = *(const float2*)(out_b + col);
            float2 c0 = *(const float2*)(curb + (size_t)r0 * 128 + col);
            float2 c1 = *(const float2*)(curb + (size_t)(r0 + 8) * 128 + col);
            *(float2*)(outb + (size_t)r0 * 128 + col) =
                make_float2(acc[mi][ni][0] + bb.x + c0.x, acc[mi][ni][1] + bb.y + c0.y);
            *(float2*)(outb + (size_t)(r0 + 8) * 128 + col) =
                make_float2(acc[mi][ni][2] + bb.x + c1.x, acc[mi][ni][3] + bb.y + c1.y);
        }
    }
}

// ---------------- host ----------------
extern "C" void kernel_launch(void* const* d_in, const int* in_sizes, int n_in,
                              void* d_out, int out_size)
{
    const float* pre   = (const float*)d_in[0];
    const float* cur   = (const float*)d_in[1];
    const float* ln1_w = (const float*)d_in[2];
    const float* ln1_b = (const float*)d_in[3];
    const float* ln2_w = (const float*)d_in[4];
    const float* ln2_b = (const float*)d_in[5];
    const float* q_w1  = (const float*)d_in[6];
    const float* q_b1  = (const float*)d_in[7];
    const float* q_w2  = (const float*)d_in[8];
    const float* q_b2  = (const float*)d_in[9];
    const float* kv_w1 = (const float*)d_in[10];
    const float* kv_b1 = (const float*)d_in[11];
    const float* kv_w2 = (const float*)d_in[12];
    const float* kv_b2 = (const float*)d_in[13];
    const float* out_w = (const float*)d_in[14];
    const float* out_b = (const float*)d_in[15];
    float* out = (float*)d_out;

    const int SMEM_GEMM = 2 * 128 * SROW * (int)sizeof(bf16);  // 69632
    const int SMEM_DW   = 34 * 34 * 32 * (int)sizeof(bf16);    // 73984
    cudaFuncSetAttribute(lngemm, cudaFuncAttributeMaxDynamicSharedMemorySize, SMEM_GEMM);
    cudaFuncSetAttribute(vgemm,  cudaFuncAttributeMaxDynamicSharedMemorySize, SMEM_GEMM);
    cudaFuncSetAttribute(dwconv_kernel, cudaFuncAttributeMaxDynamicSharedMemorySize, SMEM_DW);

    prep_weights<<<128, 256>>>(q_w1, kv_w1);

    lngemm<<<dim3(1, Ntot / 128, 2), 256, SMEM_GEMM>>>(cur, pre, ln2_w, ln2_b, ln1_w, ln1_b,
                                                       q_b1, kv_b1);

    dwconv_kernel<<<dim3(16, 12, Bsz), 256, SMEM_DW>>>(q_w2, q_b2, kv_w2, kv_b2);

    qk_kernel<<<Bsz * NCHUNK, 256>>>();

    softmax_kernel<<<128, 256>>>();

    w2_kernel<<<Bsz, 256>>>(out_w);

    vgemm<<<dim3(1, HWsz / 128, Bsz), 256, SMEM_GEMM>>>(cur, out_b, out);

    (void)in_sizes; (void)n_in; (void)out_size;
}

// round 7
// speedup vs baseline: 3.9334x; 1.0533x over previous
#include <cuda_runtime.h>
#include <cuda_bf16.h>
#include <cstdint>
#include <cstring>
#include <math.h>

#define Bsz 8
#define HWsz 16384
#define Cch 128
#define Ntot (Bsz*HWsz)
#define NCHUNK 64         // qk split-K chunks per batch
typedef __nv_bfloat16 bf16;

// ---------------- scratch (device globals; no allocation) ----------------
__device__ bf16  g_wq[Cch*Cch];
__device__ bf16  g_wkv[2*Cch*Cch];
__device__ bf16  g_q2[(size_t)Ntot*Cch];
__device__ bf16  g_kv2[(size_t)Ntot*2*Cch];
__device__ float g_att_part[(size_t)Bsz*NCHUNK*Cch*Cch];
__device__ float g_att[(size_t)Bsz*Cch*Cch];
__device__ float g_norm_part[2*Bsz*16*Cch];
__device__ bf16  g_W2h[Bsz*Cch*Cch];

// ---------------- mma / ldmatrix helpers ----------------
__device__ __forceinline__ unsigned sptr(const void* p) {
    return (unsigned)__cvta_generic_to_shared(p);
}
__device__ __forceinline__ void ldm_x4(unsigned* r, unsigned a) {
    asm volatile("ldmatrix.sync.aligned.m8n8.x4.shared.b16 {%0,%1,%2,%3}, [%4];"
        : "=r"(r[0]), "=r"(r[1]), "=r"(r[2]), "=r"(r[3]) : "r"(a));
}
__device__ __forceinline__ void ldm_x4_t(unsigned* r, unsigned a) {
    asm volatile("ldmatrix.sync.aligned.m8n8.x4.trans.shared.b16 {%0,%1,%2,%3}, [%4];"
        : "=r"(r[0]), "=r"(r[1]), "=r"(r[2]), "=r"(r[3]) : "r"(a));
}
__device__ __forceinline__ void ldm_x2(unsigned* r, unsigned a) {
    asm volatile("ldmatrix.sync.aligned.m8n8.x2.shared.b16 {%0,%1}, [%2];"
        : "=r"(r[0]), "=r"(r[1]) : "r"(a));
}
__device__ __forceinline__ void ldm_x2_t(unsigned* r, unsigned a) {
    asm volatile("ldmatrix.sync.aligned.m8n8.x2.trans.shared.b16 {%0,%1}, [%2];"
        : "=r"(r[0]), "=r"(r[1]) : "r"(a));
}
__device__ __forceinline__ void mma16816(float* c, const unsigned* a, const unsigned* b) {
    asm volatile("mma.sync.aligned.m16n8k16.row.col.f32.bf16.bf16.f32 "
        "{%0,%1,%2,%3},{%4,%5,%6,%7},{%8,%9},{%0,%1,%2,%3};"
        : "+f"(c[0]), "+f"(c[1]), "+f"(c[2]), "+f"(c[3])
        : "r"(a[0]), "r"(a[1]), "r"(a[2]), "r"(a[3]), "r"(b[0]), "r"(b[1]));
}

#define SROW 136          // ldmatrix-padded stride (halves)
#define RROW 132          // ring row stride (halves): 66 words -> 2-way worst epilogue, cf conv
#define SLOTH (128*RROW)  // ring slot size in halves

// ---------------- weight prep: fp32 -> bf16 ----------------
__global__ void prep_weights(const float* __restrict__ qw, const float* __restrict__ kvw)
{
    int i = blockIdx.x * 256 + threadIdx.x;
    if (i < Cch * Cch)     g_wq[i]  = __float2bfloat16_rn(qw[i]);
    if (i < 2 * Cch * Cch) g_wkv[i] = __float2bfloat16_rn(kvw[i]);
}

// ================= MEGAFUSE: LN + 1x1 GEMM + dwconv3x3 + sumsq =================
// grid (16 strips, 3 paths, Bsz), 512 threads.
// path 0: q (cur,ln2) -> g_q2;  path 1: k (pre,ln1, kv rows 0-127) -> g_kv2[:,0:128];
// path 2: v (pre,ln1, kv rows 128-255) -> g_kv2[:,128:256].
__global__ __launch_bounds__(512)
void megafuse(const float* __restrict__ cur, const float* __restrict__ pre,
              const float* __restrict__ ln1w, const float* __restrict__ ln1b,
              const float* __restrict__ ln2w, const float* __restrict__ ln2b,
              const float* __restrict__ qb1, const float* __restrict__ kvb1,
              const float* __restrict__ qw2, const float* __restrict__ qb2,
              const float* __restrict__ kvw2, const float* __restrict__ kvb2)
{
    extern __shared__ bf16 sm[];
    bf16* As   = sm;                    // [128][SROW]
    bf16* Ws   = sm + 128 * SROW;       // [128][SROW]
    bf16* ring = sm + 2 * 128 * SROW;   // 3 x [128][RROW]
    __shared__ float2 red2[512];

    int tid = threadIdx.x, lane = tid & 31, w = tid >> 5;
    int strip = blockIdx.x, path = blockIdx.y, b = blockIdx.z;
    int y0 = strip * 8;

    const float* Ain; const float* lnw; const float* lnb; const bf16* Wg;
    const float* gb; const float* cwt; const float* cb;
    bf16* outp; int ldout, coloff, which, dosq;
    if (path == 0) {
        Ain = cur; lnw = ln2w; lnb = ln2b; Wg = g_wq;
        gb = qb1; cwt = qw2; cb = qb2;
        outp = g_q2; ldout = 128; coloff = 0; which = 0; dosq = 1;
    } else if (path == 1) {
        Ain = pre; lnw = ln1w; lnb = ln1b; Wg = g_wkv;
        gb = kvb1; cwt = kvw2; cb = kvb2;
        outp = g_kv2; ldout = 256; coloff = 0; which = 1; dosq = 1;
    } else {
        Ain = pre; lnw = ln1w; lnb = ln1b; Wg = g_wkv + 128 * 128;
        gb = kvb1 + 128; cwt = kvw2 + 128 * 9; cb = kvb2 + 128;
        outp = g_kv2; ldout = 256; coloff = 128; which = 0; dosq = 0;
    }

    // stage weights (synced by first pre-GEMM barrier)
    for (int it = tid; it < 128 * 16; it += 512) {
        int o = it >> 4, c8 = (it & 15) * 8;
        *(uint4*)(Ws + o * SROW + c8) = *(const uint4*)(Wg + (size_t)o * 128 + c8);
    }

    // conv weights/bias per thread (channel pair)
    int cp = tid & 63, xg = tid >> 6;
    int cg = cp * 2;
    __nv_bfloat162 cw[9];
    #pragma unroll
    for (int t = 0; t < 9; t++)
        cw[t] = __floats2bfloat162_rn(cwt[cg * 9 + t], cwt[cg * 9 + 9 + t]);
    __nv_bfloat162 cb2 = __floats2bfloat162_rn(cb[cg], cb[cg + 1]);
    const __nv_bfloat162 zz = __floats2bfloat162_rn(0.f, 0.f);

    // LN params per lane
    float4 wv = *(const float4*)(lnw + lane * 4);
    float4 bv = *(const float4*)(lnb + lane * 4);

    // GEMM warp tiling: 16 warps, warp tile 32x32
    int wm = (w & 3) * 32, wn = (w >> 2) * 32;
    int arow  = (lane & 7) + ((lane >> 3) & 1) * 8;
    int akoff = (lane >> 4) * 8;
    int brow  = (lane & 7);
    int bkoff = ((lane >> 3) & 1) * 8;
    int g = lane >> 2, t2 = (lane & 3) * 2;

    float sq0 = 0.f, sq1 = 0.f;

    for (int ri = 0; ri < 10; ri++) {
        int r = y0 - 1 + ri;
        bf16* rs = ring + (ri % 3) * SLOTH;

        if ((unsigned)r < 128u) {
            // --- LN + stage row r (each warp: 8 positions) ---
            #pragma unroll
            for (int i = 0; i < 8; i++) {
                int p = w * 8 + i;
                const float* ap = Ain + ((size_t)b * HWsz + (size_t)r * 128 + p) * 128 + lane * 4;
                float4 v = *(const float4*)ap;
                float s  = v.x + v.y + v.z + v.w;
                float ss = fmaf(v.x, v.x, fmaf(v.y, v.y, fmaf(v.z, v.z, v.w * v.w)));
                #pragma unroll
                for (int o = 16; o; o >>= 1) {
                    s  += __shfl_xor_sync(0xFFFFFFFFu, s,  o);
                    ss += __shfl_xor_sync(0xFFFFFFFFu, ss, o);
                }
                float mu  = s * (1.0f / 128.0f);
                float inv = rsqrtf(ss * (1.0f / 128.0f) - mu * mu + 1e-5f);
                float x0 = (v.x - mu) * inv * wv.x + bv.x;
                float x1 = (v.y - mu) * inv * wv.y + bv.y;
                float x2 = (v.z - mu) * inv * wv.z + bv.z;
                float x3 = (v.w - mu) * inv * wv.w + bv.w;
                *(__nv_bfloat162*)(As + p * SROW + lane * 4)     = __floats2bfloat162_rn(x0, x1);
                *(__nv_bfloat162*)(As + p * SROW + lane * 4 + 2) = __floats2bfloat162_rn(x2, x3);
            }
            __syncthreads();   // As ready; also orders prior conv reads before ring overwrite

            // --- GEMM 128x128x128 ---
            float acc[2][4][4];
            #pragma unroll
            for (int mi = 0; mi < 2; mi++)
                #pragma unroll
                for (int ni = 0; ni < 4; ni++)
                    #pragma unroll
                    for (int t = 0; t < 4; t++) acc[mi][ni][t] = 0.f;

            #pragma unroll
            for (int k0 = 0; k0 < 128; k0 += 16) {
                unsigned af[2][4];
                unsigned bfr[4][2];
                #pragma unroll
                for (int mi = 0; mi < 2; mi++)
                    ldm_x4(af[mi], sptr(As + (wm + 16 * mi + arow) * SROW + k0 + akoff));
                #pragma unroll
                for (int ni = 0; ni < 4; ni++)
                    ldm_x2(bfr[ni], sptr(Ws + (wn + 8 * ni + brow) * SROW + k0 + bkoff));
                #pragma unroll
                for (int mi = 0; mi < 2; mi++)
                    #pragma unroll
                    for (int ni = 0; ni < 4; ni++)
                        mma16816(acc[mi][ni], af[mi], bfr[ni]);
            }

            // --- epilogue: +bias, bf16 -> ring slot [pos][ch] ---
            #pragma unroll
            for (int mi = 0; mi < 2; mi++) {
                int p0 = wm + 16 * mi + g;
                #pragma unroll
                for (int ni = 0; ni < 4; ni++) {
                    int col = wn + 8 * ni + t2;
                    float2 bb = *(const float2*)(gb + col);
                    *(__nv_bfloat162*)(rs + p0 * RROW + col) =
                        __floats2bfloat162_rn(acc[mi][ni][0] + bb.x, acc[mi][ni][1] + bb.y);
                    *(__nv_bfloat162*)(rs + (p0 + 8) * RROW + col) =
                        __floats2bfloat162_rn(acc[mi][ni][2] + bb.x, acc[mi][ni][3] + bb.y);
                }
            }
            __syncthreads();   // ring slot visible; As free for next LN
        } else {
            __syncthreads();   // prior conv readers done before zeroing
            for (int it = tid; it < 128 * (RROW / 2); it += 512)
                ((unsigned*)rs)[it] = 0u;
            __syncthreads();
        }

        // --- dwconv output row yo = y0 + ri - 2 ---
        if (ri >= 2) {
            const __nv_bfloat162* r0 = (const __nv_bfloat162*)(ring + ((ri - 2) % 3) * SLOTH);
            const __nv_bfloat162* r1 = (const __nv_bfloat162*)(ring + ((ri - 1) % 3) * SLOTH);
            const __nv_bfloat162* r2 = (const __nv_bfloat162*)(ring + (ri % 3) * SLOTH);
            int yo = y0 + ri - 2;
            int x0 = xg * 16;
            const int RW = RROW / 2;

            __nv_bfloat162 m0, m1, m2, c0, c1, c2;
            if (x0 > 0) {
                m0 = r0[(x0 - 1) * RW + cp]; m1 = r1[(x0 - 1) * RW + cp]; m2 = r2[(x0 - 1) * RW + cp];
            } else { m0 = zz; m1 = zz; m2 = zz; }
            c0 = r0[x0 * RW + cp]; c1 = r1[x0 * RW + cp]; c2 = r2[x0 * RW + cp];

            bf16* ob = outp + ((size_t)b * HWsz + (size_t)yo * 128) * ldout + coloff + cg;
            #pragma unroll 4
            for (int xi = 0; xi < 16; xi++) {
                int x = x0 + xi;
                __nv_bfloat162 p0, p1, p2;
                if (x < 127) {
                    p0 = r0[(x + 1) * RW + cp]; p1 = r1[(x + 1) * RW + cp]; p2 = r2[(x + 1) * RW + cp];
                } else { p0 = zz; p1 = zz; p2 = zz; }
                __nv_bfloat162 a = cb2;
                a = __hfma2(m0, cw[0], a); a = __hfma2(c0, cw[1], a); a = __hfma2(p0, cw[2], a);
                a = __hfma2(m1, cw[3], a); a = __hfma2(c1, cw[4], a); a = __hfma2(p1, cw[5], a);
                a = __hfma2(m2, cw[6], a); a = __hfma2(c2, cw[7], a); a = __hfma2(p2, cw[8], a);
                *(__nv_bfloat162*)(ob + (size_t)x * ldout) = a;
                if (dosq) {
                    float f0 = __bfloat162float(__low2bfloat16(a));
                    float f1 = __bfloat162float(__high2bfloat16(a));
                    sq0 = fmaf(f0, f0, sq0);
                    sq1 = fmaf(f1, f1, sq1);
                }
                m0 = c0; c0 = p0; m1 = c1; c1 = p1; m2 = c2; c2 = p2;
            }
        }
    }

    // --- sumsq reduce over xg groups -> g_norm_part[(which*8+b)*16 + strip] ---
    red2[tid] = make_float2(sq0, sq1);
    __syncthreads();
    if (dosq && tid < 64) {
        float t0 = 0.f, t1 = 0.f;
        #pragma unroll
        for (int xx = 0; xx < 8; xx++) {
            float2 v = red2[xx * 64 + tid];
            t0 += v.x; t1 += v.y;
        }
        float* dst = g_norm_part + ((size_t)(which * 8 + b) * 16 + strip) * 128 + tid * 2;
        dst[0] = t0; dst[1] = t1;
    }
}

// ---------------- QK^T (bf16 mma, split-K over n), partials fp32, reg double-buffer ----------------
__global__ __launch_bounds__(256)
void qk_kernel()
{
    __shared__ bf16 Qs[32 * SROW];
    __shared__ bf16 Ks[32 * SROW];
    int bx = blockIdx.x;
    int b = bx >> 6, chunk = bx & 63;
    const bf16* Qb = g_q2  + (size_t)b * HWsz * 128;
    const bf16* Kb = g_kv2 + (size_t)b * HWsz * 256;
    int tid = threadIdx.x, lane = tid & 31, w = tid >> 5;
    int wm = (w & 1) * 64, wn = (w >> 1) * 32;

    int at_row  = (lane & 7) + ((lane >> 4) & 1) * 8;
    int at_coff = ((lane >> 3) & 1) * 8;
    int bt_row  = (lane & 7) + ((lane >> 3) & 1) * 8;
    int g = lane >> 2, t2 = (lane & 3) * 2;

    int r0s = tid >> 4,         c0s = (tid & 15) * 8;
    int r1s = (tid + 256) >> 4, c1s = ((tid + 256) & 15) * 8;

    float acc[4][4][4];
    #pragma unroll
    for (int mi = 0; mi < 4; mi++)
        #pragma unroll
        for (int ni = 0; ni < 4; ni++)
            #pragma unroll
            for (int t = 0; t < 4; t++) acc[mi][ni][t] = 0.f;

    const int NS = 8;            // 8 stages x 32 rows = 256 rows per chunk
    int nbase = chunk * 256;

    uint4 pq0, pq1, pk0, pk1;
    {
        int n0 = nbase;
        pq0 = *(const uint4*)(Qb + (size_t)(n0 + r0s) * 128 + c0s);
        pq1 = *(const uint4*)(Qb + (size_t)(n0 + r1s) * 128 + c1s);
        pk0 = *(const uint4*)(Kb + (size_t)(n0 + r0s) * 256 + c0s);
        pk1 = *(const uint4*)(Kb + (size_t)(n0 + r1s) * 256 + c1s);
    }

    for (int st = 0; st < NS; st++) {
        *(uint4*)(Qs + r0s * SROW + c0s) = pq0;
        *(uint4*)(Qs + r1s * SROW + c1s) = pq1;
        *(uint4*)(Ks + r0s * SROW + c0s) = pk0;
        *(uint4*)(Ks + r1s * SROW + c1s) = pk1;
        __syncthreads();

        if (st + 1 < NS) {
            int n0 = nbase + (st + 1) * 32;
            pq0 = *(const uint4*)(Qb + (size_t)(n0 + r0s) * 128 + c0s);
            pq1 = *(const uint4*)(Qb + (size_t)(n0 + r1s) * 128 + c1s);
            pk0 = *(const uint4*)(Kb + (size_t)(n0 + r0s) * 256 + c0s);
            pk1 = *(const uint4*)(Kb + (size_t)(n0 + r1s) * 256 + c1s);
        }

        #pragma unroll
        for (int k0 = 0; k0 < 32; k0 += 16) {
            unsigned af[4][4];
            unsigned bfr[4][2];
            #pragma unroll
            for (int mi = 0; mi < 4; mi++)
                ldm_x4_t(af[mi], sptr(Qs + (k0 + at_row) * SROW + wm + 16 * mi + at_coff));
            #pragma unroll
            for (int ni = 0; ni < 4; ni++)
                ldm_x2_t(bfr[ni], sptr(Ks + (k0 + bt_row) * SROW + wn + 8 * ni));
            #pragma unroll
            for (int mi = 0; mi < 4; mi++)
                #pragma unroll
                for (int ni = 0; ni < 4; ni++)
                    mma16816(acc[mi][ni], af[mi], bfr[ni]);
        }
        __syncthreads();
    }

    float* P = g_att_part + (size_t)bx * 16384;
    #pragma unroll
    for (int mi = 0; mi < 4; mi++) {
        int row = wm + 16 * mi + g;
        #pragma unroll
        for (int ni = 0; ni < 4; ni++) {
            int col = wn + 8 * ni + t2;
            *(float2*)(P + row * 128 + col)       = make_float2(acc[mi][ni][0], acc[mi][ni][1]);
            *(float2*)(P + (row + 8) * 128 + col) = make_float2(acc[mi][ni][2], acc[mi][ni][3]);
        }
    }
}

// ---------------- reduce partials + norms + softmax ----------------
__global__ __launch_bounds__(256)
void softmax_kernel()
{
    __shared__ float iq_s[128];
    __shared__ float ik_s[128];
    int tid = threadIdx.x;
    int b = blockIdx.x >> 4;

    if (tid < 128) {
        float sq = 0.f, sk = 0.f;
        #pragma unroll
        for (int t = 0; t < 16; t++) {
            sq += g_norm_part[((size_t)b * 16 + t) * 128 + tid];
            sk += g_norm_part[((size_t)(8 + b) * 16 + t) * 128 + tid];
        }
        iq_s[tid] = 1.0f / fmaxf(sqrtf(sq), 1e-12f);
        ik_s[tid] = 1.0f / fmaxf(sqrtf(sk), 1e-12f);
    }
    __syncthreads();

    int warp = blockIdx.x * 8 + (tid >> 5);
    int lane = tid & 31;
    int c = warp & 127;

    float4 s = make_float4(0.f, 0.f, 0.f, 0.f);
    #pragma unroll 8
    for (int ch = 0; ch < NCHUNK; ch++) {
        float4 v = ((const float4*)(g_att_part + (size_t)((b * NCHUNK + ch) * 128 + c) * 128))[lane];
        s.x += v.x; s.y += v.y; s.z += v.z; s.w += v.w;
    }
    float invq = iq_s[c];
    float4 ik = ((const float4*)ik_s)[lane];

    float l0 = s.x * invq * ik.x;
    float l1 = s.y * invq * ik.y;
    float l2 = s.z * invq * ik.z;
    float l3 = s.w * invq * ik.w;

    float mx = fmaxf(fmaxf(l0, l1), fmaxf(l2, l3));
    #pragma unroll
    for (int o = 16; o; o >>= 1) mx = fmaxf(mx, __shfl_xor_sync(0xFFFFFFFFu, mx, o));
    float e0 = expf(l0 - mx), e1 = expf(l1 - mx), e2 = expf(l2 - mx), e3 = expf(l3 - mx);
    float sum = e0 + e1 + e2 + e3;
    #pragma unroll
    for (int o = 16; o; o >>= 1) sum += __shfl_xor_sync(0xFFFFFFFFu, sum, o);
    float inv = 1.0f / sum;

    ((float4*)(g_att + (size_t)(b * 128 + c) * 128))[lane] =
        make_float4(e0 * inv, e1 * inv, e2 * inv, e3 * inv);
}

// ---------------- W2[b] = out_w @ att[b]  (fp32 compute, bf16 out) ----------------
__global__ __launch_bounds__(256)
void w2_kernel(const float* __restrict__ out_w)
{
    __shared__ float sa[16 * 128];
    int b = blockIdx.x, tid = threadIdx.x;
    int c = tid >> 1, dh = (tid & 1) * 64;
    float acc[64];
    #pragma unroll
    for (int j = 0; j < 64; j++) acc[j] = 0.f;

    for (int e0 = 0; e0 < 128; e0 += 16) {
        if (e0) __syncthreads();
        for (int it = tid; it < 2048; it += 256)
            sa[it] = g_att[(size_t)b * 16384 + (size_t)(e0 + (it >> 7)) * 128 + (it & 127)];
        __syncthreads();
        for (int e = 0; e < 16; e++) {
            float wvv = out_w[c * 128 + e0 + e];
            #pragma unroll
            for (int j = 0; j < 64; j++)
                acc[j] = fmaf(wvv, sa[e * 128 + dh + j], acc[j]);
        }
    }
    for (int j = 0; j < 64; j++)
        g_W2h[(size_t)b * 16384 + c * 128 + dh + j] = __float2bfloat16_rn(acc[j]);
}

// ---------------- final: out[b,n,c] = sum_d W2[c,d] v[b,n,d] + out_b[c] + cur ----------------
__global__ __launch_bounds__(256)
void vgemm(const float* __restrict__ cur, const float* __restrict__ out_b,
           float* __restrict__ out)
{
    extern __shared__ bf16 sm[];
    bf16* As = sm;
    bf16* Bs = sm + 128 * SROW;
    int b = blockIdx.z;
    int m0 = blockIdx.y * 128;
    const bf16* V  = g_kv2 + (size_t)b * HWsz * 256 + 128;
    const bf16* W2 = g_W2h + (size_t)b * 16384;
    int tid = threadIdx.x, lane = tid & 31, w = tid >> 5;

    for (int it = tid; it < 128 * 16; it += 256) {
        int r = it >> 4, c8 = (it & 15) * 8;
        *(uint4*)(As + r * SROW + c8) = *(const uint4*)(V + (size_t)(m0 + r) * 256 + c8);
        *(uint4*)(Bs + r * SROW + c8) = *(const uint4*)(W2 + (size_t)r * 128 + c8);
    }
    __syncthreads();

    int wm = (w & 1) * 64, wn = (w >> 1) * 32;
    int arow  = (lane & 7) + ((lane >> 3) & 1) * 8;
    int akoff = (lane >> 4) * 8;
    int brow  = (lane & 7);
    int bkoff = ((lane >> 3) & 1) * 8;
    int g = lane >> 2, t2 = (lane & 3) * 2;

    float acc[4][4][4];
    #pragma unroll
    for (int mi = 0; mi < 4; mi++)
        #pragma unroll
        for (int ni = 0; ni < 4; ni++)
            #pragma unroll
            for (int t = 0; t < 4; t++) acc[mi][ni][t] = 0.f;

    for (int k0 = 0; k0 < 128; k0 += 16) {
        unsigned af[4][4];
        unsigned bfr[4][2];
        #pragma unroll
        for (int mi = 0; mi < 4; mi++)
            ldm_x4(af[mi], sptr(As + (wm + 16 * mi + arow) * SROW + k0 + akoff));
        #pragma unroll
        for (int ni = 0; ni < 4; ni++)
            ldm_x2(bfr[ni], sptr(Bs + (wn + 8 * ni + brow) * SROW + k0 + bkoff));
        #pragma unroll
        for (int mi = 0; mi < 4; mi++)
            #pragma unroll
            for (int ni = 0; ni < 4; ni++)
                mma16816(acc[mi][ni], af[mi], bfr[ni]);
    }

    const float* curb = cur + (size_t)b * HWsz * 128;
    float* outb = out + (size_t)b * HWsz * 128;
    #pragma unroll
    for (int mi = 0; mi < 4; mi++) {
        int r0 = m0 + wm + 16 * mi + g;
        #pragma unroll
        for (int ni = 0; ni < 4; ni++) {
            int col = wn + 8 * ni + t2;
            float2 bb = *(const float2*)(out_b + col);
            float2 c0 = *(const float2*)(curb + (size_t)r0 * 128 + col);
            float2 c1 = *(const float2*)(curb + (size_t)(r0 + 8) * 128 + col);
            *(float2*)(outb + (size_t)r0 * 128 + col) =
                make_float2(acc[mi][ni][0] + bb.x + c0.x, acc[mi][ni][1] + bb.y + c0.y);
            *(float2*)(outb + (size_t)(r0 + 8) * 128 + col) =
                make_float2(acc[mi][ni][2] + bb.x + c1.x, acc[mi][ni][3] + bb.y + c1.y);
        }
    }
}

// ---------------- host ----------------
extern "C" void kernel_launch(void* const* d_in, const int* in_sizes, int n_in,
                              void* d_out, int out_size)
{
    const float* pre   = (const float*)d_in[0];
    const float* cur   = (const float*)d_in[1];
    const float* ln1_w = (const float*)d_in[2];
    const float* ln1_b = (const float*)d_in[3];
    const float* ln2_w = (const float*)d_in[4];
    const float* ln2_b = (const float*)d_in[5];
    const float* q_w1  = (const float*)d_in[6];
    const float* q_b1  = (const float*)d_in[7];
    const float* q_w2  = (const float*)d_in[8];
    const float* q_b2  = (const float*)d_in[9];
    const float* kv_w1 = (const float*)d_in[10];
    const float* kv_b1 = (const float*)d_in[11];
    const float* kv_w2 = (const float*)d_in[12];
    const float* kv_b2 = (const float*)d_in[13];
    const float* out_w = (const float*)d_in[14];
    const float* out_b = (const float*)d_in[15];
    float* out = (float*)d_out;

    const int SMEM_GEMM = 2 * 128 * SROW * (int)sizeof(bf16);               // 69632
    const int SMEM_MF   = (2 * 128 * SROW + 3 * SLOTH) * (int)sizeof(bf16); // 171008
    cudaFuncSetAttribute(megafuse, cudaFuncAttributeMaxDynamicSharedMemorySize, SMEM_MF);
    cudaFuncSetAttribute(vgemm,    cudaFuncAttributeMaxDynamicSharedMemorySize, SMEM_GEMM);

    prep_weights<<<128, 256>>>(q_w1, kv_w1);

    // fused LN + 1x1 conv + dwconv3x3 + sumsq
    megafuse<<<dim3(16, 3, Bsz), 512, SMEM_MF>>>(cur, pre, ln1_w, ln1_b, ln2_w, ln2_b,
                                                 q_b1, kv_b1, q_w2, q_b2, kv_w2, kv_b2);

    qk_kernel<<<Bsz * NCHUNK, 256>>>();

    softmax_kernel<<<128, 256>>>();

    w2_kernel<<<Bsz, 256>>>(out_w);

    vgemm<<<dim3(1, HWsz / 128, Bsz), 256, SMEM_GEMM>>>(cur, out_b, out);

    (void)in_sizes; (void)n_in; (void)out_size;
}

// round 8
// speedup vs baseline: 4.0628x; 1.0329x over previous
#include <cuda_runtime.h>
#include <cuda_bf16.h>
#include <cstdint>
#include <cstring>
#include <math.h>

#define Bsz 8
#define HWsz 16384
#define Cch 128
#define Ntot (Bsz*HWsz)
#define NCHUNK 64         // qk split-K chunks per batch
typedef __nv_bfloat16 bf16;

// ---------------- scratch (device globals; no allocation) ----------------
__device__ bf16  g_q2[(size_t)Ntot*Cch];
__device__ bf16  g_kv2[(size_t)Ntot*2*Cch];
__device__ float g_att_part[(size_t)Bsz*NCHUNK*Cch*Cch];
__device__ float g_att[(size_t)Bsz*Cch*Cch];
__device__ float g_norm_part[2*Bsz*16*Cch];
__device__ bf16  g_W2h[Bsz*Cch*Cch];

// ---------------- mma / ldmatrix helpers ----------------
__device__ __forceinline__ unsigned sptr(const void* p) {
    return (unsigned)__cvta_generic_to_shared(p);
}
__device__ __forceinline__ void ldm_x4(unsigned* r, unsigned a) {
    asm volatile("ldmatrix.sync.aligned.m8n8.x4.shared.b16 {%0,%1,%2,%3}, [%4];"
        : "=r"(r[0]), "=r"(r[1]), "=r"(r[2]), "=r"(r[3]) : "r"(a));
}
__device__ __forceinline__ void ldm_x4_t(unsigned* r, unsigned a) {
    asm volatile("ldmatrix.sync.aligned.m8n8.x4.trans.shared.b16 {%0,%1,%2,%3}, [%4];"
        : "=r"(r[0]), "=r"(r[1]), "=r"(r[2]), "=r"(r[3]) : "r"(a));
}
__device__ __forceinline__ void ldm_x2(unsigned* r, unsigned a) {
    asm volatile("ldmatrix.sync.aligned.m8n8.x2.shared.b16 {%0,%1}, [%2];"
        : "=r"(r[0]), "=r"(r[1]) : "r"(a));
}
__device__ __forceinline__ void ldm_x2_t(unsigned* r, unsigned a) {
    asm volatile("ldmatrix.sync.aligned.m8n8.x2.trans.shared.b16 {%0,%1}, [%2];"
        : "=r"(r[0]), "=r"(r[1]) : "r"(a));
}
__device__ __forceinline__ void mma16816(float* c, const unsigned* a, const unsigned* b) {
    asm volatile("mma.sync.aligned.m16n8k16.row.col.f32.bf16.bf16.f32 "
        "{%0,%1,%2,%3},{%4,%5,%6,%7},{%8,%9},{%0,%1,%2,%3};"
        : "+f"(c[0]), "+f"(c[1]), "+f"(c[2]), "+f"(c[3])
        : "r"(a[0]), "r"(a[1]), "r"(a[2]), "r"(a[3]), "r"(b[0]), "r"(b[1]));
}
__device__ __forceinline__ void pf_l2(const void* p) {
    asm volatile("prefetch.global.L2 [%0];" :: "l"(p));
}

#define SROW 136          // ldmatrix-padded stride (halves)
#define RROW 132          // ring row stride (halves)
#define SLOTH (128*RROW)  // ring slot size in halves

// ================= MEGAFUSE: LN + 1x1 GEMM + dwconv3x3 + sumsq =================
// grid (16 strips, 3 paths, Bsz), 512 threads.
__global__ __launch_bounds__(512)
void megafuse(const float* __restrict__ cur, const float* __restrict__ pre,
              const float* __restrict__ ln1w, const float* __restrict__ ln1b,
              const float* __restrict__ ln2w, const float* __restrict__ ln2b,
              const float* __restrict__ qw1, const float* __restrict__ kvw1,
              const float* __restrict__ qb1, const float* __restrict__ kvb1,
              const float* __restrict__ qw2, const float* __restrict__ qb2,
              const float* __restrict__ kvw2, const float* __restrict__ kvb2)
{
    extern __shared__ bf16 sm[];
    bf16* As   = sm;                    // [128][SROW]
    bf16* Ws   = sm + 128 * SROW;       // [128][SROW]
    bf16* ring = sm + 2 * 128 * SROW;   // 3 x [128][RROW]
    __shared__ float2 red2[512];

    int tid = threadIdx.x, lane = tid & 31, w = tid >> 5;
    int strip = blockIdx.x, path = blockIdx.y, b = blockIdx.z;
    int y0 = strip * 8;

    const float* Ain; const float* lnw; const float* lnb; const float* Wf;
    const float* gb; const float* cwt; const float* cb;
    bf16* outp; int ldout, coloff, which, dosq;
    if (path == 0) {
        Ain = cur; lnw = ln2w; lnb = ln2b; Wf = qw1;
        gb = qb1; cwt = qw2; cb = qb2;
        outp = g_q2; ldout = 128; coloff = 0; which = 0; dosq = 1;
    } else if (path == 1) {
        Ain = pre; lnw = ln1w; lnb = ln1b; Wf = kvw1;
        gb = kvb1; cwt = kvw2; cb = kvb2;
        outp = g_kv2; ldout = 256; coloff = 0; which = 1; dosq = 1;
    } else {
        Ain = pre; lnw = ln1w; lnb = ln1b; Wf = kvw1 + 128 * 128;
        gb = kvb1 + 128; cwt = kvw2 + 128 * 9; cb = kvb2 + 128;
        outp = g_kv2; ldout = 256; coloff = 128; which = 0; dosq = 0;
    }

    // stage weights from fp32, converting to bf16 (synced by first pre-GEMM barrier)
    for (int it = tid; it < 128 * 16; it += 512) {
        int o = it >> 4, c8 = (it & 15) * 8;
        const float* wp = Wf + (size_t)o * 128 + c8;
        float4 f0 = *(const float4*)wp;
        float4 f1 = *(const float4*)(wp + 4);
        __nv_bfloat162 h0 = __floats2bfloat162_rn(f0.x, f0.y);
        __nv_bfloat162 h1 = __floats2bfloat162_rn(f0.z, f0.w);
        __nv_bfloat162 h2 = __floats2bfloat162_rn(f1.x, f1.y);
        __nv_bfloat162 h3 = __floats2bfloat162_rn(f1.z, f1.w);
        bf16* dp = Ws + o * SROW + c8;
        *(__nv_bfloat162*)(dp)     = h0;
        *(__nv_bfloat162*)(dp + 2) = h1;
        *(__nv_bfloat162*)(dp + 4) = h2;
        *(__nv_bfloat162*)(dp + 6) = h3;
    }

    // conv weights/bias per thread (channel pair)
    int cp = tid & 63, xg = tid >> 6;
    int cg = cp * 2;
    __nv_bfloat162 cw[9];
    #pragma unroll
    for (int t = 0; t < 9; t++)
        cw[t] = __floats2bfloat162_rn(cwt[cg * 9 + t], cwt[cg * 9 + 9 + t]);
    __nv_bfloat162 cb2 = __floats2bfloat162_rn(cb[cg], cb[cg + 1]);
    const __nv_bfloat162 zz = __floats2bfloat162_rn(0.f, 0.f);

    // LN params per lane
    float4 wv = *(const float4*)(lnw + lane * 4);
    float4 bv = *(const float4*)(lnb + lane * 4);

    // GEMM warp tiling: 16 warps, warp tile 32x32
    int wm = (w & 3) * 32, wn = (w >> 2) * 32;
    int arow  = (lane & 7) + ((lane >> 3) & 1) * 8;
    int akoff = (lane >> 4) * 8;
    int brow  = (lane & 7);
    int bkoff = ((lane >> 3) & 1) * 8;
    int g = lane >> 2, t2 = (lane & 3) * 2;

    float sq0 = 0.f, sq1 = 0.f;

    // prefetch first row into L2
    {
        int r = y0 - 1;
        if ((unsigned)r < 128u) {
            #pragma unroll
            for (int i = 0; i < 8; i++) {
                int p = w * 8 + i;
                pf_l2(Ain + ((size_t)b * HWsz + (size_t)r * 128 + p) * 128 + lane * 4);
            }
        }
    }

    for (int ri = 0; ri < 10; ri++) {
        int r = y0 - 1 + ri;
        bf16* rs = ring + (ri % 3) * SLOTH;

        if ((unsigned)r < 128u) {
            // --- LN + stage row r (each warp: 8 positions) ---
            #pragma unroll
            for (int i = 0; i < 8; i++) {
                int p = w * 8 + i;
                const float* ap = Ain + ((size_t)b * HWsz + (size_t)r * 128 + p) * 128 + lane * 4;
                float4 v = *(const float4*)ap;
                float s  = v.x + v.y + v.z + v.w;
                float ss = fmaf(v.x, v.x, fmaf(v.y, v.y, fmaf(v.z, v.z, v.w * v.w)));
                #pragma unroll
                for (int o = 16; o; o >>= 1) {
                    s  += __shfl_xor_sync(0xFFFFFFFFu, s,  o);
                    ss += __shfl_xor_sync(0xFFFFFFFFu, ss, o);
                }
                float mu  = s * (1.0f / 128.0f);
                float inv = rsqrtf(ss * (1.0f / 128.0f) - mu * mu + 1e-5f);
                float x0 = (v.x - mu) * inv * wv.x + bv.x;
                float x1 = (v.y - mu) * inv * wv.y + bv.y;
                float x2 = (v.z - mu) * inv * wv.z + bv.z;
                float x3 = (v.w - mu) * inv * wv.w + bv.w;
                *(__nv_bfloat162*)(As + p * SROW + lane * 4)     = __floats2bfloat162_rn(x0, x1);
                *(__nv_bfloat162*)(As + p * SROW + lane * 4 + 2) = __floats2bfloat162_rn(x2, x3);
            }
            __syncthreads();   // As ready; also orders prior conv reads before ring overwrite

            // prefetch next row into L2 (hidden behind GEMM)
            {
                int rn = r + 1;
                if (ri + 1 < 10 && (unsigned)rn < 128u) {
                    #pragma unroll
                    for (int i = 0; i < 8; i++) {
                        int p = w * 8 + i;
                        pf_l2(Ain + ((size_t)b * HWsz + (size_t)rn * 128 + p) * 128 + lane * 4);
                    }
                }
            }

            // --- GEMM 128x128x128 ---
            float acc[2][4][4];
            #pragma unroll
            for (int mi = 0; mi < 2; mi++)
                #pragma unroll
                for (int ni = 0; ni < 4; ni++)
                    #pragma unroll
                    for (int t = 0; t < 4; t++) acc[mi][ni][t] = 0.f;

            #pragma unroll
            for (int k0 = 0; k0 < 128; k0 += 16) {
                unsigned af[2][4];
                unsigned bfr[4][2];
                #pragma unroll
                for (int mi = 0; mi < 2; mi++)
                    ldm_x4(af[mi], sptr(As + (wm + 16 * mi + arow) * SROW + k0 + akoff));
                #pragma unroll
                for (int ni = 0; ni < 4; ni++)
                    ldm_x2(bfr[ni], sptr(Ws + (wn + 8 * ni + brow) * SROW + k0 + bkoff));
                #pragma unroll
                for (int mi = 0; mi < 2; mi++)
                    #pragma unroll
                    for (int ni = 0; ni < 4; ni++)
                        mma16816(acc[mi][ni], af[mi], bfr[ni]);
            }

            // --- epilogue: +bias, bf16 -> ring slot [pos][ch] ---
            #pragma unroll
            for (int mi = 0; mi < 2; mi++) {
                int p0 = wm + 16 * mi + g;
                #pragma unroll
                for (int ni = 0; ni < 4; ni++) {
                    int col = wn + 8 * ni + t2;
                    float2 bb = *(const float2*)(gb + col);
                    *(__nv_bfloat162*)(rs + p0 * RROW + col) =
                        __floats2bfloat162_rn(acc[mi][ni][0] + bb.x, acc[mi][ni][1] + bb.y);
                    *(__nv_bfloat162*)(rs + (p0 + 8) * RROW + col) =
                        __floats2bfloat162_rn(acc[mi][ni][2] + bb.x, acc[mi][ni][3] + bb.y);
                }
            }
            __syncthreads();   // ring slot visible; As free for next LN
        } else {
            __syncthreads();   // prior conv readers done before zeroing
            for (int it = tid; it < 128 * (RROW / 2); it += 512)
                ((unsigned*)rs)[it] = 0u;
            __syncthreads();
        }

        // --- dwconv output row yo = y0 + ri - 2 ---
        if (ri >= 2) {
            const __nv_bfloat162* r0 = (const __nv_bfloat162*)(ring + ((ri - 2) % 3) * SLOTH);
            const __nv_bfloat162* r1 = (const __nv_bfloat162*)(ring + ((ri - 1) % 3) * SLOTH);
            const __nv_bfloat162* r2 = (const __nv_bfloat162*)(ring + (ri % 3) * SLOTH);
            int yo = y0 + ri - 2;
            int x0 = xg * 16;
            const int RW = RROW / 2;

            __nv_bfloat162 m0, m1, m2, c0, c1, c2;
            if (x0 > 0) {
                m0 = r0[(x0 - 1) * RW + cp]; m1 = r1[(x0 - 1) * RW + cp]; m2 = r2[(x0 - 1) * RW + cp];
            } else { m0 = zz; m1 = zz; m2 = zz; }
            c0 = r0[x0 * RW + cp]; c1 = r1[x0 * RW + cp]; c2 = r2[x0 * RW + cp];

            bf16* ob = outp + ((size_t)b * HWsz + (size_t)yo * 128) * ldout + coloff + cg;
            #pragma unroll 4
            for (int xi = 0; xi < 16; xi++) {
                int x = x0 + xi;
                __nv_bfloat162 p0, p1, p2;
                if (x < 127) {
                    p0 = r0[(x + 1) * RW + cp]; p1 = r1[(x + 1) * RW + cp]; p2 = r2[(x + 1) * RW + cp];
                } else { p0 = zz; p1 = zz; p2 = zz; }
                __nv_bfloat162 a = cb2;
                a = __hfma2(m0, cw[0], a); a = __hfma2(c0, cw[1], a); a = __hfma2(p0, cw[2], a);
                a = __hfma2(m1, cw[3], a); a = __hfma2(c1, cw[4], a); a = __hfma2(p1, cw[5], a);
                a = __hfma2(m2, cw[6], a); a = __hfma2(c2, cw[7], a); a = __hfma2(p2, cw[8], a);
                *(__nv_bfloat162*)(ob + (size_t)x * ldout) = a;
                if (dosq) {
                    float f0 = __bfloat162float(__low2bfloat16(a));
                    float f1 = __bfloat162float(__high2bfloat16(a));
                    sq0 = fmaf(f0, f0, sq0);
                    sq1 = fmaf(f1, f1, sq1);
                }
                m0 = c0; c0 = p0; m1 = c1; c1 = p1; m2 = c2; c2 = p2;
            }
        }
    }

    // --- sumsq reduce -> g_norm_part ---
    red2[tid] = make_float2(sq0, sq1);
    __syncthreads();
    if (dosq && tid < 64) {
        float t0 = 0.f, t1 = 0.f;
        #pragma unroll
        for (int xx = 0; xx < 8; xx++) {
            float2 v = red2[xx * 64 + tid];
            t0 += v.x; t1 += v.y;
        }
        float* dst = g_norm_part + ((size_t)(which * 8 + b) * 16 + strip) * 128 + tid * 2;
        dst[0] = t0; dst[1] = t1;
    }
}

// ---------------- QK^T (bf16 mma, split-K over n), partials fp32, reg double-buffer ----------------
__global__ __launch_bounds__(256)
void qk_kernel()
{
    __shared__ bf16 Qs[32 * SROW];
    __shared__ bf16 Ks[32 * SROW];
    int bx = blockIdx.x;
    int b = bx >> 6, chunk = bx & 63;
    const bf16* Qb = g_q2  + (size_t)b * HWsz * 128;
    const bf16* Kb = g_kv2 + (size_t)b * HWsz * 256;
    int tid = threadIdx.x, lane = tid & 31, w = tid >> 5;
    int wm = (w & 1) * 64, wn = (w >> 1) * 32;

    int at_row  = (lane & 7) + ((lane >> 4) & 1) * 8;
    int at_coff = ((lane >> 3) & 1) * 8;
    int bt_row  = (lane & 7) + ((lane >> 3) & 1) * 8;
    int g = lane >> 2, t2 = (lane & 3) * 2;

    int r0s = tid >> 4,         c0s = (tid & 15) * 8;
    int r1s = (tid + 256) >> 4, c1s = ((tid + 256) & 15) * 8;

    float acc[4][4][4];
    #pragma unroll
    for (int mi = 0; mi < 4; mi++)
        #pragma unroll
        for (int ni = 0; ni < 4; ni++)
            #pragma unroll
            for (int t = 0; t < 4; t++) acc[mi][ni][t] = 0.f;

    const int NS = 8;
    int nbase = chunk * 256;

    uint4 pq0, pq1, pk0, pk1;
    {
        int n0 = nbase;
        pq0 = *(const uint4*)(Qb + (size_t)(n0 + r0s) * 128 + c0s);
        pq1 = *(const uint4*)(Qb + (size_t)(n0 + r1s) * 128 + c1s);
        pk0 = *(const uint4*)(Kb + (size_t)(n0 + r0s) * 256 + c0s);
        pk1 = *(const uint4*)(Kb + (size_t)(n0 + r1s) * 256 + c1s);
    }

    for (int st = 0; st < NS; st++) {
        *(uint4*)(Qs + r0s * SROW + c0s) = pq0;
        *(uint4*)(Qs + r1s * SROW + c1s) = pq1;
        *(uint4*)(Ks + r0s * SROW + c0s) = pk0;
        *(uint4*)(Ks + r1s * SROW + c1s) = pk1;
        __syncthreads();

        if (st + 1 < NS) {
            int n0 = nbase + (st + 1) * 32;
            pq0 = *(const uint4*)(Qb + (size_t)(n0 + r0s) * 128 + c0s);
            pq1 = *(const uint4*)(Qb + (size_t)(n0 + r1s) * 128 + c1s);
            pk0 = *(const uint4*)(Kb + (size_t)(n0 + r0s) * 256 + c0s);
            pk1 = *(const uint4*)(Kb + (size_t)(n0 + r1s) * 256 + c1s);
        }

        #pragma unroll
        for (int k0 = 0; k0 < 32; k0 += 16) {
            unsigned af[4][4];
            unsigned bfr[4][2];
            #pragma unroll
            for (int mi = 0; mi < 4; mi++)
                ldm_x4_t(af[mi], sptr(Qs + (k0 + at_row) * SROW + wm + 16 * mi + at_coff));
            #pragma unroll
            for (int ni = 0; ni < 4; ni++)
                ldm_x2_t(bfr[ni], sptr(Ks + (k0 + bt_row) * SROW + wn + 8 * ni));
            #pragma unroll
            for (int mi = 0; mi < 4; mi++)
                #pragma unroll
                for (int ni = 0; ni < 4; ni++)
                    mma16816(acc[mi][ni], af[mi], bfr[ni]);
        }
        __syncthreads();
    }

    float* P = g_att_part + (size_t)bx * 16384;
    #pragma unroll
    for (int mi = 0; mi < 4; mi++) {
        int row = wm + 16 * mi + g;
        #pragma unroll
        for (int ni = 0; ni < 4; ni++) {
            int col = wn + 8 * ni + t2;
            *(float2*)(P + row * 128 + col)       = make_float2(acc[mi][ni][0], acc[mi][ni][1]);
            *(float2*)(P + (row + 8) * 128 + col) = make_float2(acc[mi][ni][2], acc[mi][ni][3]);
        }
    }
}

// ---------------- softmax: one block per (b,c), thread = d ----------------
__global__ __launch_bounds__(128)
void softmax_kernel()
{
    __shared__ float rbuf[8];
    int bc = blockIdx.x;
    int b = bc >> 7, c = bc & 127;
    int d = threadIdx.x;

    // norms (L2-resident partials)
    float sq = 0.f, sk = 0.f;
    #pragma unroll
    for (int t = 0; t < 16; t++) {
        sq += g_norm_part[((size_t)b * 16 + t) * 128 + c];
        sk += g_norm_part[((size_t)(8 + b) * 16 + t) * 128 + d];
    }
    float invq = 1.0f / fmaxf(sqrtf(sq), 1e-12f);
    float invk = 1.0f / fmaxf(sqrtf(sk), 1e-12f);

    // sum partials over chunks (coalesced rows)
    const float* P = g_att_part + ((size_t)b * NCHUNK * 128 + c) * 128 + d;
    float s = 0.f;
    #pragma unroll 8
    for (int ch = 0; ch < NCHUNK; ch++)
        s += P[(size_t)ch * 16384];

    float l = s * invq * invk;

    // block max
    float mx = l;
    #pragma unroll
    for (int o = 16; o; o >>= 1) mx = fmaxf(mx, __shfl_xor_sync(0xFFFFFFFFu, mx, o));
    if ((d & 31) == 0) rbuf[d >> 5] = mx;
    __syncthreads();
    mx = fmaxf(fmaxf(rbuf[0], rbuf[1]), fmaxf(rbuf[2], rbuf[3]));

    float e = expf(l - mx);
    float sum = e;
    #pragma unroll
    for (int o = 16; o; o >>= 1) sum += __shfl_xor_sync(0xFFFFFFFFu, sum, o);
    __syncthreads();
    if ((d & 31) == 0) rbuf[4 + (d >> 5)] = sum;
    __syncthreads();
    sum = (rbuf[4] + rbuf[5]) + (rbuf[6] + rbuf[7]);

    g_att[(size_t)bc * 128 + d] = e / sum;
}

// ---------------- W2[b] = out_w @ att[b]  (fp32 compute, bf16 out) ----------------
__global__ __launch_bounds__(256)
void w2_kernel(const float* __restrict__ out_w)
{
    __shared__ float sa[16 * 128];
    int b = blockIdx.x, tid = threadIdx.x;
    int c = tid >> 1, dh = (tid & 1) * 64;
    float acc[64];
    #pragma unroll
    for (int j = 0; j < 64; j++) acc[j] = 0.f;

    for (int e0 = 0; e0 < 128; e0 += 16) {
        if (e0) __syncthreads();
        for (int it = tid; it < 2048; it += 256)
            sa[it] = g_att[(size_t)b * 16384 + (size_t)(e0 + (it >> 7)) * 128 + (it & 127)];
        __syncthreads();
        for (int e = 0; e < 16; e++) {
            float wvv = out_w[c * 128 + e0 + e];
            #pragma unroll
            for (int j = 0; j < 64; j++)
                acc[j] = fmaf(wvv, sa[e * 128 + dh + j], acc[j]);
        }
    }
    for (int j = 0; j < 64; j++)
        g_W2h[(size_t)b * 16384 + c * 128 + dh + j] = __float2bfloat16_rn(acc[j]);
}

// ---------------- final: out[b,n,c] = sum_d W2[c,d] v[b,n,d] + out_b[c] + cur ----------------
__global__ __launch_bounds__(256)
void vgemm(const float* __restrict__ cur, const float* __restrict__ out_b,
           float* __restrict__ out)
{
    extern __shared__ bf16 sm[];
    bf16* As = sm;
    bf16* Bs = sm + 128 * SROW;
    int b = blockIdx.z;
    int m0 = blockIdx.y * 128;
    const bf16* V  = g_kv2 + (size_t)b * HWsz * 256 + 128;
    const bf16* W2 = g_W2h + (size_t)b * 16384;
    int tid = threadIdx.x, lane = tid & 31, w = tid >> 5;

    for (int it = tid; it < 128 * 16; it += 256) {
        int r = it >> 4, c8 = (it & 15) * 8;
        *(uint4*)(As + r * SROW + c8) = *(const uint4*)(V + (size_t)(m0 + r) * 256 + c8);
        *(uint4*)(Bs + r * SROW + c8) = *(const uint4*)(W2 + (size_t)r * 128 + c8);
    }
    __syncthreads();

    int wm = (w & 1) * 64, wn = (w >> 1) * 32;
    int arow  = (lane & 7) + ((lane >> 3) & 1) * 8;
    int akoff = (lane >> 4) * 8;
    int brow  = (lane & 7);
    int bkoff = ((lane >> 3) & 1) * 8;
    int g = lane >> 2, t2 = (lane & 3) * 2;

    float acc[4][4][4];
    #pragma unroll
    for (int mi = 0; mi < 4; mi++)
        #pragma unroll
        for (int ni = 0; ni < 4; ni++)
            #pragma unroll
            for (int t = 0; t < 4; t++) acc[mi][ni][t] = 0.f;

    for (int k0 = 0; k0 < 128; k0 += 16) {
        unsigned af[4][4];
        unsigned bfr[4][2];
        #pragma unroll
        for (int mi = 0; mi < 4; mi++)
            ldm_x4(af[mi], sptr(As + (wm + 16 * mi + arow) * SROW + k0 + akoff));
        #pragma unroll
        for (int ni = 0; ni < 4; ni++)
            ldm_x2(bfr[ni], sptr(Bs + (wn + 8 * ni + brow) * SROW + k0 + bkoff));
        #pragma unroll
        for (int mi = 0; mi < 4; mi++)
            #pragma unroll
            for (int ni = 0; ni < 4; ni++)
                mma16816(acc[mi][ni], af[mi], bfr[ni]);
    }

    const float* curb = cur + (size_t)b * HWsz * 128;
    float* outb = out + (size_t)b * HWsz * 128;
    #pragma unroll
    for (int mi = 0; mi < 4; mi++) {
        int r0 = m0 + wm + 16 * mi + g;
        #pragma unroll
        for (int ni = 0; ni < 4; ni++) {
            int col = wn + 8 * ni + t2;
            float2 bb = *(const float2*)(out_b + col);
            float2 c0 = *(const float2*)(curb + (size_t)r0 * 128 + col);
            float2 c1 = *(const float2*)(curb + (size_t)(r0 + 8) * 128 + col);
            *(float2*)(outb + (size_t)r0 * 128 + col) =
                make_float2(acc[mi][ni][0] + bb.x + c0.x, acc[mi][ni][1] + bb.y + c0.y);
            *(float2*)(outb + (size_t)(r0 + 8) * 128 + col) =
                make_float2(acc[mi][ni][2] + bb.x + c1.x, acc[mi][ni][3] + bb.y + c1.y);
        }
    }
}

// ---------------- host ----------------
extern "C" void kernel_launch(void* const* d_in, const int* in_sizes, int n_in,
                              void* d_out, int out_size)
{
    const float* pre   = (const float*)d_in[0];
    const float* cur   = (const float*)d_in[1];
    const float* ln1_w = (const float*)d_in[2];
    const float* ln1_b = (const float*)d_in[3];
    const float* ln2_w = (const float*)d_in[4];
    const float* ln2_b = (const float*)d_in[5];
    const float* q_w1  = (const float*)d_in[6];
    const float* q_b1  = (const float*)d_in[7];
    const float* q_w2  = (const float*)d_in[8];
    const float* q_b2  = (const float*)d_in[9];
    const float* kv_w1 = (const float*)d_in[10];
    const float* kv_b1 = (const float*)d_in[11];
    const float* kv_w2 = (const float*)d_in[12];
    const float* kv_b2 = (const float*)d_in[13];
    const float* out_w = (const float*)d_in[14];
    const float* out_b = (const float*)d_in[15];
    float* out = (float*)d_out;

    const int SMEM_GEMM = 2 * 128 * SROW * (int)sizeof(bf16);
    const int SMEM_MF   = (2 * 128 * SROW + 3 * SLOTH) * (int)sizeof(bf16);
    cudaFuncSetAttribute(megafuse, cudaFuncAttributeMaxDynamicSharedMemorySize, SMEM_MF);
    cudaFuncSetAttribute(vgemm,    cudaFuncAttributeMaxDynamicSharedMemorySize, SMEM_GEMM);

    megafuse<<<dim3(16, 3, Bsz), 512, SMEM_MF>>>(cur, pre, ln1_w, ln1_b, ln2_w, ln2_b,
                                                 q_w1, kv_w1, q_b1, kv_b1,
                                                 q_w2, q_b2, kv_w2, kv_b2);

    qk_kernel<<<Bsz * NCHUNK, 256>>>();

    softmax_kernel<<<Bsz * 128, 128>>>();

    w2_kernel<<<Bsz, 256>>>(out_w);

    vgemm<<<dim3(1, HWsz / 128, Bsz), 256, SMEM_GEMM>>>(cur, out_b, out);

    (void)in_sizes; (void)n_in; (void)out_size;
}

// round 9
// speedup vs baseline: 4.9757x; 1.2247x over previous
#include <cuda_runtime.h>
#include <cuda_bf16.h>
#include <cstdint>
#include <cstring>
#include <math.h>

#define Bsz 8
#define HWsz 16384
#define Cch 128
#define Ntot (Bsz*HWsz)
#define NCHUNK 64         // qk split-K chunks per batch
typedef __nv_bfloat16 bf16;

// ---------------- scratch (device globals; no allocation) ----------------
__device__ bf16  g_q2[(size_t)Ntot*Cch];
__device__ bf16  g_kv2[(size_t)Ntot*2*Cch];
__device__ float g_att_part[(size_t)Bsz*NCHUNK*Cch*Cch];
__device__ float g_att[(size_t)Bsz*Cch*Cch];
__device__ float g_norm_part[2*Bsz*16*Cch];
__device__ bf16  g_W2h[Bsz*Cch*Cch];

// ---------------- mma / ldmatrix helpers ----------------
__device__ __forceinline__ unsigned sptr(const void* p) {
    return (unsigned)__cvta_generic_to_shared(p);
}
__device__ __forceinline__ void ldm_x4(unsigned* r, unsigned a) {
    asm volatile("ldmatrix.sync.aligned.m8n8.x4.shared.b16 {%0,%1,%2,%3}, [%4];"
        : "=r"(r[0]), "=r"(r[1]), "=r"(r[2]), "=r"(r[3]) : "r"(a));
}
__device__ __forceinline__ void ldm_x4_t(unsigned* r, unsigned a) {
    asm volatile("ldmatrix.sync.aligned.m8n8.x4.trans.shared.b16 {%0,%1,%2,%3}, [%4];"
        : "=r"(r[0]), "=r"(r[1]), "=r"(r[2]), "=r"(r[3]) : "r"(a));
}
__device__ __forceinline__ void ldm_x2(unsigned* r, unsigned a) {
    asm volatile("ldmatrix.sync.aligned.m8n8.x2.shared.b16 {%0,%1}, [%2];"
        : "=r"(r[0]), "=r"(r[1]) : "r"(a));
}
__device__ __forceinline__ void ldm_x2_t(unsigned* r, unsigned a) {
    asm volatile("ldmatrix.sync.aligned.m8n8.x2.trans.shared.b16 {%0,%1}, [%2];"
        : "=r"(r[0]), "=r"(r[1]) : "r"(a));
}
__device__ __forceinline__ void mma16816(float* c, const unsigned* a, const unsigned* b) {
    asm volatile("mma.sync.aligned.m16n8k16.row.col.f32.bf16.bf16.f32 "
        "{%0,%1,%2,%3},{%4,%5,%6,%7},{%8,%9},{%0,%1,%2,%3};"
        : "+f"(c[0]), "+f"(c[1]), "+f"(c[2]), "+f"(c[3])
        : "r"(a[0]), "r"(a[1]), "r"(a[2]), "r"(a[3]), "r"(b[0]), "r"(b[1]));
}
__device__ __forceinline__ void pf_l2(const void* p) {
    asm volatile("prefetch.global.L2 [%0];" :: "l"(p));
}

#define SROW 136          // ldmatrix-padded stride (halves)
#define RROW 132          // ring row stride (halves)
#define SLOTH (128*RROW)  // ring slot size in halves

// ================= MEGAFUSE: LN + 1x1 GEMM + dwconv3x3 + sumsq =================
// grid (16 strips, 3 paths, Bsz), 512 threads.
__global__ __launch_bounds__(512)
void megafuse(const float* __restrict__ cur, const float* __restrict__ pre,
              const float* __restrict__ ln1w, const float* __restrict__ ln1b,
              const float* __restrict__ ln2w, const float* __restrict__ ln2b,
              const float* __restrict__ qw1, const float* __restrict__ kvw1,
              const float* __restrict__ qb1, const float* __restrict__ kvb1,
              const float* __restrict__ qw2, const float* __restrict__ qb2,
              const float* __restrict__ kvw2, const float* __restrict__ kvb2)
{
    extern __shared__ bf16 sm[];
    bf16* As   = sm;                    // [128][SROW]
    bf16* Ws   = sm + 128 * SROW;       // [128][SROW]
    bf16* ring = sm + 2 * 128 * SROW;   // 3 x [128][RROW]
    __shared__ float2 red2[512];

    int tid = threadIdx.x, lane = tid & 31, w = tid >> 5;
    int strip = blockIdx.x, path = blockIdx.y, b = blockIdx.z;
    int y0 = strip * 8;

    const float* Ain; const float* lnw; const float* lnb; const float* Wf;
    const float* gb; const float* cwt; const float* cb;
    bf16* outp; int ldout, coloff, which, dosq;
    if (path == 0) {
        Ain = cur; lnw = ln2w; lnb = ln2b; Wf = qw1;
        gb = qb1; cwt = qw2; cb = qb2;
        outp = g_q2; ldout = 128; coloff = 0; which = 0; dosq = 1;
    } else if (path == 1) {
        Ain = pre; lnw = ln1w; lnb = ln1b; Wf = kvw1;
        gb = kvb1; cwt = kvw2; cb = kvb2;
        outp = g_kv2; ldout = 256; coloff = 0; which = 1; dosq = 1;
    } else {
        Ain = pre; lnw = ln1w; lnb = ln1b; Wf = kvw1 + 128 * 128;
        gb = kvb1 + 128; cwt = kvw2 + 128 * 9; cb = kvb2 + 128;
        outp = g_kv2; ldout = 256; coloff = 128; which = 0; dosq = 0;
    }

    // stage weights from fp32, converting to bf16 (synced by first pre-GEMM barrier)
    for (int it = tid; it < 128 * 16; it += 512) {
        int o = it >> 4, c8 = (it & 15) * 8;
        const float* wp = Wf + (size_t)o * 128 + c8;
        float4 f0 = *(const float4*)wp;
        float4 f1 = *(const float4*)(wp + 4);
        __nv_bfloat162 h0 = __floats2bfloat162_rn(f0.x, f0.y);
        __nv_bfloat162 h1 = __floats2bfloat162_rn(f0.z, f0.w);
        __nv_bfloat162 h2 = __floats2bfloat162_rn(f1.x, f1.y);
        __nv_bfloat162 h3 = __floats2bfloat162_rn(f1.z, f1.w);
        bf16* dp = Ws + o * SROW + c8;
        *(__nv_bfloat162*)(dp)     = h0;
        *(__nv_bfloat162*)(dp + 2) = h1;
        *(__nv_bfloat162*)(dp + 4) = h2;
        *(__nv_bfloat162*)(dp + 6) = h3;
    }

    // conv weights/bias per thread (channel pair)
    int cp = tid & 63, xg = tid >> 6;
    int cg = cp * 2;
    __nv_bfloat162 cw[9];
    #pragma unroll
    for (int t = 0; t < 9; t++)
        cw[t] = __floats2bfloat162_rn(cwt[cg * 9 + t], cwt[cg * 9 + 9 + t]);
    __nv_bfloat162 cb2 = __floats2bfloat162_rn(cb[cg], cb[cg + 1]);
    const __nv_bfloat162 zz = __floats2bfloat162_rn(0.f, 0.f);

    // LN params per lane
    float4 wv = *(const float4*)(lnw + lane * 4);
    float4 bv = *(const float4*)(lnb + lane * 4);

    // GEMM warp tiling: 16 warps, warp tile 32x32
    int wm = (w & 3) * 32, wn = (w >> 2) * 32;
    int arow  = (lane & 7) + ((lane >> 3) & 1) * 8;
    int akoff = (lane >> 4) * 8;
    int brow  = (lane & 7);
    int bkoff = ((lane >> 3) & 1) * 8;
    int g = lane >> 2, t2 = (lane & 3) * 2;

    float sq0 = 0.f, sq1 = 0.f;

    // prefetch first row into L2
    {
        int r = y0 - 1;
        if ((unsigned)r < 128u) {
            #pragma unroll
            for (int i = 0; i < 8; i++) {
                int p = w * 8 + i;
                pf_l2(Ain + ((size_t)b * HWsz + (size_t)r * 128 + p) * 128 + lane * 4);
            }
        }
    }

    for (int ri = 0; ri < 10; ri++) {
        int r = y0 - 1 + ri;
        bf16* rs = ring + (ri % 3) * SLOTH;

        if ((unsigned)r < 128u) {
            // --- LN + stage row r (each warp: 8 positions) ---
            #pragma unroll
            for (int i = 0; i < 8; i++) {
                int p = w * 8 + i;
                const float* ap = Ain + ((size_t)b * HWsz + (size_t)r * 128 + p) * 128 + lane * 4;
                float4 v = *(const float4*)ap;
                float s  = v.x + v.y + v.z + v.w;
                float ss = fmaf(v.x, v.x, fmaf(v.y, v.y, fmaf(v.z, v.z, v.w * v.w)));
                #pragma unroll
                for (int o = 16; o; o >>= 1) {
                    s  += __shfl_xor_sync(0xFFFFFFFFu, s,  o);
                    ss += __shfl_xor_sync(0xFFFFFFFFu, ss, o);
                }
                float mu  = s * (1.0f / 128.0f);
                float inv = rsqrtf(ss * (1.0f / 128.0f) - mu * mu + 1e-5f);
                float x0 = (v.x - mu) * inv * wv.x + bv.x;
                float x1 = (v.y - mu) * inv * wv.y + bv.y;
                float x2 = (v.z - mu) * inv * wv.z + bv.z;
                float x3 = (v.w - mu) * inv * wv.w + bv.w;
                *(__nv_bfloat162*)(As + p * SROW + lane * 4)     = __floats2bfloat162_rn(x0, x1);
                *(__nv_bfloat162*)(As + p * SROW + lane * 4 + 2) = __floats2bfloat162_rn(x2, x3);
            }
            __syncthreads();   // As ready; also orders prior conv reads before ring overwrite

            // prefetch next row into L2 (hidden behind GEMM)
            {
                int rn = r + 1;
                if (ri + 1 < 10 && (unsigned)rn < 128u) {
                    #pragma unroll
                    for (int i = 0; i < 8; i++) {
                        int p = w * 8 + i;
                        pf_l2(Ain + ((size_t)b * HWsz + (size_t)rn * 128 + p) * 128 + lane * 4);
                    }
                }
            }

            // --- GEMM 128x128x128 ---
            float acc[2][4][4];
            #pragma unroll
            for (int mi = 0; mi < 2; mi++)
                #pragma unroll
                for (int ni = 0; ni < 4; ni++)
                    #pragma unroll
                    for (int t = 0; t < 4; t++) acc[mi][ni][t] = 0.f;

            #pragma unroll
            for (int k0 = 0; k0 < 128; k0 += 16) {
                unsigned af[2][4];
                unsigned bfr[4][2];
                #pragma unroll
                for (int mi = 0; mi < 2; mi++)
                    ldm_x4(af[mi], sptr(As + (wm + 16 * mi + arow) * SROW + k0 + akoff));
                #pragma unroll
                for (int ni = 0; ni < 4; ni++)
                    ldm_x2(bfr[ni], sptr(Ws + (wn + 8 * ni + brow) * SROW + k0 + bkoff));
                #pragma unroll
                for (int mi = 0; mi < 2; mi++)
                    #pragma unroll
                    for (int ni = 0; ni < 4; ni++)
                        mma16816(acc[mi][ni], af[mi], bfr[ni]);
            }

            // --- epilogue: +bias, bf16 -> ring slot [pos][ch] ---
            #pragma unroll
            for (int mi = 0; mi < 2; mi++) {
                int p0 = wm + 16 * mi + g;
                #pragma unroll
                for (int ni = 0; ni < 4; ni++) {
                    int col = wn + 8 * ni + t2;
                    float2 bb = *(const float2*)(gb + col);
                    *(__nv_bfloat162*)(rs + p0 * RROW + col) =
                        __floats2bfloat162_rn(acc[mi][ni][0] + bb.x, acc[mi][ni][1] + bb.y);
                    *(__nv_bfloat162*)(rs + (p0 + 8) * RROW + col) =
                        __floats2bfloat162_rn(acc[mi][ni][2] + bb.x, acc[mi][ni][3] + bb.y);
                }
            }
            __syncthreads();   // ring slot visible; As free for next LN
        } else {
            __syncthreads();   // prior conv readers done before zeroing
            for (int it = tid; it < 128 * (RROW / 2); it += 512)
                ((unsigned*)rs)[it] = 0u;
            __syncthreads();
        }

        // --- dwconv output row yo = y0 + ri - 2 ---
        if (ri >= 2) {
            const __nv_bfloat162* r0 = (const __nv_bfloat162*)(ring + ((ri - 2) % 3) * SLOTH);
            const __nv_bfloat162* r1 = (const __nv_bfloat162*)(ring + ((ri - 1) % 3) * SLOTH);
            const __nv_bfloat162* r2 = (const __nv_bfloat162*)(ring + (ri % 3) * SLOTH);
            int yo = y0 + ri - 2;
            int x0 = xg * 16;
            const int RW = RROW / 2;

            __nv_bfloat162 m0, m1, m2, c0, c1, c2;
            if (x0 > 0) {
                m0 = r0[(x0 - 1) * RW + cp]; m1 = r1[(x0 - 1) * RW + cp]; m2 = r2[(x0 - 1) * RW + cp];
            } else { m0 = zz; m1 = zz; m2 = zz; }
            c0 = r0[x0 * RW + cp]; c1 = r1[x0 * RW + cp]; c2 = r2[x0 * RW + cp];

            bf16* ob = outp + ((size_t)b * HWsz + (size_t)yo * 128) * ldout + coloff + cg;
            #pragma unroll 4
            for (int xi = 0; xi < 16; xi++) {
                int x = x0 + xi;
                __nv_bfloat162 p0, p1, p2;
                if (x < 127) {
                    p0 = r0[(x + 1) * RW + cp]; p1 = r1[(x + 1) * RW + cp]; p2 = r2[(x + 1) * RW + cp];
                } else { p0 = zz; p1 = zz; p2 = zz; }
                __nv_bfloat162 a = cb2;
                a = __hfma2(m0, cw[0], a); a = __hfma2(c0, cw[1], a); a = __hfma2(p0, cw[2], a);
                a = __hfma2(m1, cw[3], a); a = __hfma2(c1, cw[4], a); a = __hfma2(p1, cw[5], a);
                a = __hfma2(m2, cw[6], a); a = __hfma2(c2, cw[7], a); a = __hfma2(p2, cw[8], a);
                *(__nv_bfloat162*)(ob + (size_t)x * ldout) = a;
                if (dosq) {
                    float f0 = __bfloat162float(__low2bfloat16(a));
                    float f1 = __bfloat162float(__high2bfloat16(a));
                    sq0 = fmaf(f0, f0, sq0);
                    sq1 = fmaf(f1, f1, sq1);
                }
                m0 = c0; c0 = p0; m1 = c1; c1 = p1; m2 = c2; c2 = p2;
            }
        }
    }

    // --- sumsq reduce -> g_norm_part ---
    red2[tid] = make_float2(sq0, sq1);
    __syncthreads();
    if (dosq && tid < 64) {
        float t0 = 0.f, t1 = 0.f;
        #pragma unroll
        for (int xx = 0; xx < 8; xx++) {
            float2 v = red2[xx * 64 + tid];
            t0 += v.x; t1 += v.y;
        }
        float* dst = g_norm_part + ((size_t)(which * 8 + b) * 16 + strip) * 128 + tid * 2;
        dst[0] = t0; dst[1] = t1;
    }
}

// ---------------- QK^T (bf16 mma, split-K over n), partials fp32, reg double-buffer ----------------
__global__ __launch_bounds__(256)
void qk_kernel()
{
    __shared__ bf16 Qs[32 * SROW];
    __shared__ bf16 Ks[32 * SROW];
    int bx = blockIdx.x;
    int b = bx >> 6, chunk = bx & 63;
    const bf16* Qb = g_q2  + (size_t)b * HWsz * 128;
    const bf16* Kb = g_kv2 + (size_t)b * HWsz * 256;
    int tid = threadIdx.x, lane = tid & 31, w = tid >> 5;
    int wm = (w & 1) * 64, wn = (w >> 1) * 32;

    int at_row  = (lane & 7) + ((lane >> 4) & 1) * 8;
    int at_coff = ((lane >> 3) & 1) * 8;
    int bt_row  = (lane & 7) + ((lane >> 3) & 1) * 8;
    int g = lane >> 2, t2 = (lane & 3) * 2;

    int r0s = tid >> 4,         c0s = (tid & 15) * 8;
    int r1s = (tid + 256) >> 4, c1s = ((tid + 256) & 15) * 8;

    float acc[4][4][4];
    #pragma unroll
    for (int mi = 0; mi < 4; mi++)
        #pragma unroll
        for (int ni = 0; ni < 4; ni++)
            #pragma unroll
            for (int t = 0; t < 4; t++) acc[mi][ni][t] = 0.f;

    const int NS = 8;
    int nbase = chunk * 256;

    uint4 pq0, pq1, pk0, pk1;
    {
        int n0 = nbase;
        pq0 = *(const uint4*)(Qb + (size_t)(n0 + r0s) * 128 + c0s);
        pq1 = *(const uint4*)(Qb + (size_t)(n0 + r1s) * 128 + c1s);
        pk0 = *(const uint4*)(Kb + (size_t)(n0 + r0s) * 256 + c0s);
        pk1 = *(const uint4*)(Kb + (size_t)(n0 + r1s) * 256 + c1s);
    }

    for (int st = 0; st < NS; st++) {
        *(uint4*)(Qs + r0s * SROW + c0s) = pq0;
        *(uint4*)(Qs + r1s * SROW + c1s) = pq1;
        *(uint4*)(Ks + r0s * SROW + c0s) = pk0;
        *(uint4*)(Ks + r1s * SROW + c1s) = pk1;
        __syncthreads();

        if (st + 1 < NS) {
            int n0 = nbase + (st + 1) * 32;
            pq0 = *(const uint4*)(Qb + (size_t)(n0 + r0s) * 128 + c0s);
            pq1 = *(const uint4*)(Qb + (size_t)(n0 + r1s) * 128 + c1s);
            pk0 = *(const uint4*)(Kb + (size_t)(n0 + r0s) * 256 + c0s);
            pk1 = *(const uint4*)(Kb + (size_t)(n0 + r1s) * 256 + c1s);
        }

        #pragma unroll
        for (int k0 = 0; k0 < 32; k0 += 16) {
            unsigned af[4][4];
            unsigned bfr[4][2];
            #pragma unroll
            for (int mi = 0; mi < 4; mi++)
                ldm_x4_t(af[mi], sptr(Qs + (k0 + at_row) * SROW + wm + 16 * mi + at_coff));
            #pragma unroll
            for (int ni = 0; ni < 4; ni++)
                ldm_x2_t(bfr[ni], sptr(Ks + (k0 + bt_row) * SROW + wn + 8 * ni));
            #pragma unroll
            for (int mi = 0; mi < 4; mi++)
                #pragma unroll
                for (int ni = 0; ni < 4; ni++)
                    mma16816(acc[mi][ni], af[mi], bfr[ni]);
        }
        __syncthreads();
    }

    float* P = g_att_part + (size_t)bx * 16384;
    #pragma unroll
    for (int mi = 0; mi < 4; mi++) {
        int row = wm + 16 * mi + g;
        #pragma unroll
        for (int ni = 0; ni < 4; ni++) {
            int col = wn + 8 * ni + t2;
            *(float2*)(P + row * 128 + col)       = make_float2(acc[mi][ni][0], acc[mi][ni][1]);
            *(float2*)(P + (row + 8) * 128 + col) = make_float2(acc[mi][ni][2], acc[mi][ni][3]);
        }
    }
}

// ---------------- softmax: one block per (b,c), thread = d ----------------
__global__ __launch_bounds__(128)
void softmax_kernel()
{
    __shared__ float rbuf[8];
    int bc = blockIdx.x;
    int b = bc >> 7, c = bc & 127;
    int d = threadIdx.x;

    // norms (L2-resident partials)
    float sq = 0.f, sk = 0.f;
    #pragma unroll
    for (int t = 0; t < 16; t++) {
        sq += g_norm_part[((size_t)b * 16 + t) * 128 + c];
        sk += g_norm_part[((size_t)(8 + b) * 16 + t) * 128 + d];
    }
    float invq = 1.0f / fmaxf(sqrtf(sq), 1e-12f);
    float invk = 1.0f / fmaxf(sqrtf(sk), 1e-12f);

    // sum partials over chunks (coalesced rows)
    const float* P = g_att_part + ((size_t)b * NCHUNK * 128 + c) * 128 + d;
    float s = 0.f;
    #pragma unroll 8
    for (int ch = 0; ch < NCHUNK; ch++)
        s += P[(size_t)ch * 16384];

    float l = s * invq * invk;

    // block max
    float mx = l;
    #pragma unroll
    for (int o = 16; o; o >>= 1) mx = fmaxf(mx, __shfl_xor_sync(0xFFFFFFFFu, mx, o));
    if ((d & 31) == 0) rbuf[d >> 5] = mx;
    __syncthreads();
    mx = fmaxf(fmaxf(rbuf[0], rbuf[1]), fmaxf(rbuf[2], rbuf[3]));

    float e = expf(l - mx);
    float sum = e;
    #pragma unroll
    for (int o = 16; o; o >>= 1) sum += __shfl_xor_sync(0xFFFFFFFFu, sum, o);
    __syncthreads();
    if ((d & 31) == 0) rbuf[4 + (d >> 5)] = sum;
    __syncthreads();
    sum = (rbuf[4] + rbuf[5]) + (rbuf[6] + rbuf[7]);

    g_att[(size_t)bc * 128 + d] = e / sum;
}

// ---------------- W2[b] = out_w @ att[b]: grid (Bsz, 16 ctiles), 128 thr ----------------
__global__ __launch_bounds__(128)
void w2_kernel(const float* __restrict__ out_w)
{
    __shared__ float sw[8 * 128];
    int b = blockIdx.x, ct = blockIdx.y;
    int d = threadIdx.x;

    // stage 8 rows of out_w
    for (int it = d; it < 8 * 128; it += 128)
        sw[it] = out_w[(size_t)(ct * 8 + (it >> 7)) * 128 + (it & 127)];
    __syncthreads();

    float acc[8];
    #pragma unroll
    for (int ci = 0; ci < 8; ci++) acc[ci] = 0.f;

    const float* A = g_att + (size_t)b * 16384 + d;
    #pragma unroll 4
    for (int e = 0; e < 128; e++) {
        float a = A[(size_t)e * 128];
        #pragma unroll
        for (int ci = 0; ci < 8; ci++)
            acc[ci] = fmaf(sw[ci * 128 + e], a, acc[ci]);
    }

    bf16* W2 = g_W2h + (size_t)b * 16384 + (size_t)(ct * 8) * 128 + d;
    #pragma unroll
    for (int ci = 0; ci < 8; ci++)
        W2[(size_t)ci * 128] = __float2bfloat16_rn(acc[ci]);
}

// ---------------- final: out[b,n,c] = sum_d W2[c,d] v[b,n,d] + out_b[c] + cur ----------------
__global__ __launch_bounds__(256)
void vgemm(const float* __restrict__ cur, const float* __restrict__ out_b,
           float* __restrict__ out)
{
    extern __shared__ bf16 sm[];
    bf16* As = sm;
    bf16* Bs = sm + 128 * SROW;
    int b = blockIdx.z;
    int m0 = blockIdx.y * 128;
    const bf16* V  = g_kv2 + (size_t)b * HWsz * 256 + 128;
    const bf16* W2 = g_W2h + (size_t)b * 16384;
    int tid = threadIdx.x, lane = tid & 31, w = tid >> 5;

    for (int it = tid; it < 128 * 16; it += 256) {
        int r = it >> 4, c8 = (it & 15) * 8;
        *(uint4*)(As + r * SROW + c8) = *(const uint4*)(V + (size_t)(m0 + r) * 256 + c8);
        *(uint4*)(Bs + r * SROW + c8) = *(const uint4*)(W2 + (size_t)r * 128 + c8);
    }
    __syncthreads();

    int wm = (w & 1) * 64, wn = (w >> 1) * 32;
    int arow  = (lane & 7) + ((lane >> 3) & 1) * 8;
    int akoff = (lane >> 4) * 8;
    int brow  = (lane & 7);
    int bkoff = ((lane >> 3) & 1) * 8;
    int g = lane >> 2, t2 = (lane & 3) * 2;

    float acc[4][4][4];
    #pragma unroll
    for (int mi = 0; mi < 4; mi++)
        #pragma unroll
        for (int ni = 0; ni < 4; ni++)
            #pragma unroll
            for (int t = 0; t < 4; t++) acc[mi][ni][t] = 0.f;

    for (int k0 = 0; k0 < 128; k0 += 16) {
        unsigned af[4][4];
        unsigned bfr[4][2];
        #pragma unroll
        for (int mi = 0; mi < 4; mi++)
            ldm_x4(af[mi], sptr(As + (wm + 16 * mi + arow) * SROW + k0 + akoff));
        #pragma unroll
        for (int ni = 0; ni < 4; ni++)
            ldm_x2(bfr[ni], sptr(Bs + (wn + 8 * ni + brow) * SROW + k0 + bkoff));
        #pragma unroll
        for (int mi = 0; mi < 4; mi++)
            #pragma unroll
            for (int ni = 0; ni < 4; ni++)
                mma16816(acc[mi][ni], af[mi], bfr[ni]);
    }

    const float* curb = cur + (size_t)b * HWsz * 128;
    float* outb = out + (size_t)b * HWsz * 128;
    #pragma unroll
    for (int mi = 0; mi < 4; mi++) {
        int r0 = m0 + wm + 16 * mi + g;
        #pragma unroll
        for (int ni = 0; ni < 4; ni++) {
            int col = wn + 8 * ni + t2;
            float2 bb = *(const float2*)(out_b + col);
            float2 c0 = *(const float2*)(curb + (size_t)r0 * 128 + col);
            float2 c1 = *(const float2*)(curb + (size_t)(r0 + 8) * 128 + col);
            *(float2*)(outb + (size_t)r0 * 128 + col) =
                make_float2(acc[mi][ni][0] + bb.x + c0.x, acc[mi][ni][1] + bb.y + c0.y);
            *(float2*)(outb + (size_t)(r0 + 8) * 128 + col) =
                make_float2(acc[mi][ni][2] + bb.x + c1.x, acc[mi][ni][3] + bb.y + c1.y);
        }
    }
}

// ---------------- host ----------------
extern "C" void kernel_launch(void* const* d_in, const int* in_sizes, int n_in,
                              void* d_out, int out_size)
{
    const float* pre   = (const float*)d_in[0];
    const float* cur   = (const float*)d_in[1];
    const float* ln1_w = (const float*)d_in[2];
    const float* ln1_b = (const float*)d_in[3];
    const float* ln2_w = (const float*)d_in[4];
    const float* ln2_b = (const float*)d_in[5];
    const float* q_w1  = (const float*)d_in[6];
    const float* q_b1  = (const float*)d_in[7];
    const float* q_w2  = (const float*)d_in[8];
    const float* q_b2  = (const float*)d_in[9];
    const float* kv_w1 = (const float*)d_in[10];
    const float* kv_b1 = (const float*)d_in[11];
    const float* kv_w2 = (const float*)d_in[12];
    const float* kv_b2 = (const float*)d_in[13];
    const float* out_w = (const float*)d_in[14];
    const float* out_b = (const float*)d_in[15];
    float* out = (float*)d_out;

    const int SMEM_GEMM = 2 * 128 * SROW * (int)sizeof(bf16);
    const int SMEM_MF   = (2 * 128 * SROW + 3 * SLOTH) * (int)sizeof(bf16);
    cudaFuncSetAttribute(megafuse, cudaFuncAttributeMaxDynamicSharedMemorySize, SMEM_MF);
    cudaFuncSetAttribute(vgemm,    cudaFuncAttributeMaxDynamicSharedMemorySize, SMEM_GEMM);

    megafuse<<<dim3(16, 3, Bsz), 512, SMEM_MF>>>(cur, pre, ln1_w, ln1_b, ln2_w, ln2_b,
                                                 q_w1, kv_w1, q_b1, kv_b1,
                                                 q_w2, q_b2, kv_w2, kv_b2);

    qk_kernel<<<Bsz * NCHUNK, 256>>>();

    softmax_kernel<<<Bsz * 128, 128>>>();

    w2_kernel<<<dim3(Bsz, 16), 128>>>(out_w);

    vgemm<<<dim3(1, HWsz / 128, Bsz), 256, SMEM_GEMM>>>(cur, out_b, out);

    (void)in_sizes; (void)n_in; (void)out_size;
}

// round 10
// speedup vs baseline: 5.1059x; 1.0262x over previous
#include <cuda_runtime.h>
#include <cuda_bf16.h>
#include <cstdint>
#include <cstring>
#include <math.h>

#define Bsz 8
#define HWsz 16384
#define Cch 128
#define Ntot (Bsz*HWsz)
#define NCHUNK 64         // qk split-K chunks per batch
typedef __nv_bfloat16 bf16;

// ---------------- scratch (device globals; no allocation) ----------------
__device__ bf16  g_q2[(size_t)Ntot*Cch];
__device__ bf16  g_kv2[(size_t)Ntot*2*Cch];
__device__ float g_att_part[(size_t)Bsz*NCHUNK*Cch*Cch];
__device__ float g_att[(size_t)Bsz*Cch*Cch];
__device__ float g_norm_part[2*Bsz*16*Cch];
__device__ bf16  g_W2h[Bsz*Cch*Cch];

// ---------------- mma / ldmatrix helpers ----------------
__device__ __forceinline__ unsigned sptr(const void* p) {
    return (unsigned)__cvta_generic_to_shared(p);
}
__device__ __forceinline__ void ldm_x4(unsigned* r, unsigned a) {
    asm volatile("ldmatrix.sync.aligned.m8n8.x4.shared.b16 {%0,%1,%2,%3}, [%4];"
        : "=r"(r[0]), "=r"(r[1]), "=r"(r[2]), "=r"(r[3]) : "r"(a));
}
__device__ __forceinline__ void ldm_x4_t(unsigned* r, unsigned a) {
    asm volatile("ldmatrix.sync.aligned.m8n8.x4.trans.shared.b16 {%0,%1,%2,%3}, [%4];"
        : "=r"(r[0]), "=r"(r[1]), "=r"(r[2]), "=r"(r[3]) : "r"(a));
}
__device__ __forceinline__ void ldm_x2(unsigned* r, unsigned a) {
    asm volatile("ldmatrix.sync.aligned.m8n8.x2.shared.b16 {%0,%1}, [%2];"
        : "=r"(r[0]), "=r"(r[1]) : "r"(a));
}
__device__ __forceinline__ void ldm_x2_t(unsigned* r, unsigned a) {
    asm volatile("ldmatrix.sync.aligned.m8n8.x2.trans.shared.b16 {%0,%1}, [%2];"
        : "=r"(r[0]), "=r"(r[1]) : "r"(a));
}
__device__ __forceinline__ void mma16816(float* c, const unsigned* a, const unsigned* b) {
    asm volatile("mma.sync.aligned.m16n8k16.row.col.f32.bf16.bf16.f32 "
        "{%0,%1,%2,%3},{%4,%5,%6,%7},{%8,%9},{%0,%1,%2,%3};"
        : "+f"(c[0]), "+f"(c[1]), "+f"(c[2]), "+f"(c[3])
        : "r"(a[0]), "r"(a[1]), "r"(a[2]), "r"(a[3]), "r"(b[0]), "r"(b[1]));
}
__device__ __forceinline__ void pf_l2(const void* p) {
    asm volatile("prefetch.global.L2 [%0];" :: "l"(p));
}

#define SROW 136          // ldmatrix-padded stride (halves)
#define RROW 132          // ring row stride (halves)
#define SLOTH (128*RROW)  // ring slot size in halves

// ================= MEGAFUSE: LN + 1x1 GEMM + dwconv3x3 + sumsq =================
// grid (3 paths, 16 strips, Bsz) -- path fastest so k/v blocks sharing `pre` rows
// are co-resident and the second read hits L2. 512 threads.
__global__ __launch_bounds__(512)
void megafuse(const float* __restrict__ cur, const float* __restrict__ pre,
              const float* __restrict__ ln1w, const float* __restrict__ ln1b,
              const float* __restrict__ ln2w, const float* __restrict__ ln2b,
              const float* __restrict__ qw1, const float* __restrict__ kvw1,
              const float* __restrict__ qb1, const float* __restrict__ kvb1,
              const float* __restrict__ qw2, const float* __restrict__ qb2,
              const float* __restrict__ kvw2, const float* __restrict__ kvb2)
{
    extern __shared__ bf16 sm[];
    bf16* As   = sm;                    // [128][SROW]
    bf16* Ws   = sm + 128 * SROW;       // [128][SROW]
    bf16* ring = sm + 2 * 128 * SROW;   // 3 x [128][RROW]
    __shared__ float2 red2[512];

    int tid = threadIdx.x, lane = tid & 31, w = tid >> 5;
    int path = blockIdx.x, strip = blockIdx.y, b = blockIdx.z;
    int y0 = strip * 8;

    const float* Ain; const float* lnw; const float* lnb; const float* Wf;
    const float* gb; const float* cwt; const float* cb;
    bf16* outp; int ldout, coloff, which, dosq;
    if (path == 0) {
        Ain = cur; lnw = ln2w; lnb = ln2b; Wf = qw1;
        gb = qb1; cwt = qw2; cb = qb2;
        outp = g_q2; ldout = 128; coloff = 0; which = 0; dosq = 1;
    } else if (path == 1) {
        Ain = pre; lnw = ln1w; lnb = ln1b; Wf = kvw1;
        gb = kvb1; cwt = kvw2; cb = kvb2;
        outp = g_kv2; ldout = 256; coloff = 0; which = 1; dosq = 1;
    } else {
        Ain = pre; lnw = ln1w; lnb = ln1b; Wf = kvw1 + 128 * 128;
        gb = kvb1 + 128; cwt = kvw2 + 128 * 9; cb = kvb2 + 128;
        outp = g_kv2; ldout = 256; coloff = 128; which = 0; dosq = 0;
    }

    // stage weights from fp32, converting to bf16 (synced by first pre-GEMM barrier)
    for (int it = tid; it < 128 * 16; it += 512) {
        int o = it >> 4, c8 = (it & 15) * 8;
        const float* wp = Wf + (size_t)o * 128 + c8;
        float4 f0 = *(const float4*)wp;
        float4 f1 = *(const float4*)(wp + 4);
        __nv_bfloat162 h0 = __floats2bfloat162_rn(f0.x, f0.y);
        __nv_bfloat162 h1 = __floats2bfloat162_rn(f0.z, f0.w);
        __nv_bfloat162 h2 = __floats2bfloat162_rn(f1.x, f1.y);
        __nv_bfloat162 h3 = __floats2bfloat162_rn(f1.z, f1.w);
        bf16* dp = Ws + o * SROW + c8;
        *(__nv_bfloat162*)(dp)     = h0;
        *(__nv_bfloat162*)(dp + 2) = h1;
        *(__nv_bfloat162*)(dp + 4) = h2;
        *(__nv_bfloat162*)(dp + 6) = h3;
    }

    // conv weights/bias per thread (channel pair)
    int cp = tid & 63, xg = tid >> 6;
    int cg = cp * 2;
    __nv_bfloat162 cw[9];
    #pragma unroll
    for (int t = 0; t < 9; t++)
        cw[t] = __floats2bfloat162_rn(cwt[cg * 9 + t], cwt[cg * 9 + 9 + t]);
    __nv_bfloat162 cb2 = __floats2bfloat162_rn(cb[cg], cb[cg + 1]);
    const __nv_bfloat162 zz = __floats2bfloat162_rn(0.f, 0.f);

    // LN params per lane
    float4 wv = *(const float4*)(lnw + lane * 4);
    float4 bv = *(const float4*)(lnb + lane * 4);

    // GEMM warp tiling: 16 warps, warp tile 32x32
    int wm = (w & 3) * 32, wn = (w >> 2) * 32;
    int arow  = (lane & 7) + ((lane >> 3) & 1) * 8;
    int akoff = (lane >> 4) * 8;
    int brow  = (lane & 7);
    int bkoff = ((lane >> 3) & 1) * 8;
    int g = lane >> 2, t2 = (lane & 3) * 2;

    float sq0 = 0.f, sq1 = 0.f;

    // prefetch first row into L2
    {
        int r = y0 - 1;
        if ((unsigned)r < 128u) {
            #pragma unroll
            for (int i = 0; i < 8; i++) {
                int p = w * 8 + i;
                pf_l2(Ain + ((size_t)b * HWsz + (size_t)r * 128 + p) * 128 + lane * 4);
            }
        }
    }

    for (int ri = 0; ri < 10; ri++) {
        int r = y0 - 1 + ri;
        bf16* rs = ring + (ri % 3) * SLOTH;

        if ((unsigned)r < 128u) {
            // --- LN + stage row r (each warp: 8 positions) ---
            #pragma unroll
            for (int i = 0; i < 8; i++) {
                int p = w * 8 + i;
                const float* ap = Ain + ((size_t)b * HWsz + (size_t)r * 128 + p) * 128 + lane * 4;
                float4 v = *(const float4*)ap;
                float s  = v.x + v.y + v.z + v.w;
                float ss = fmaf(v.x, v.x, fmaf(v.y, v.y, fmaf(v.z, v.z, v.w * v.w)));
                #pragma unroll
                for (int o = 16; o; o >>= 1) {
                    s  += __shfl_xor_sync(0xFFFFFFFFu, s,  o);
                    ss += __shfl_xor_sync(0xFFFFFFFFu, ss, o);
                }
                float mu  = s * (1.0f / 128.0f);
                float inv = rsqrtf(ss * (1.0f / 128.0f) - mu * mu + 1e-5f);
                float x0 = (v.x - mu) * inv * wv.x + bv.x;
                float x1 = (v.y - mu) * inv * wv.y + bv.y;
                float x2 = (v.z - mu) * inv * wv.z + bv.z;
                float x3 = (v.w - mu) * inv * wv.w + bv.w;
                *(__nv_bfloat162*)(As + p * SROW + lane * 4)     = __floats2bfloat162_rn(x0, x1);
                *(__nv_bfloat162*)(As + p * SROW + lane * 4 + 2) = __floats2bfloat162_rn(x2, x3);
            }
            __syncthreads();   // As ready; also orders prior conv reads before ring overwrite

            // prefetch next row into L2 (hidden behind GEMM)
            {
                int rn = r + 1;
                if (ri + 1 < 10 && (unsigned)rn < 128u) {
                    #pragma unroll
                    for (int i = 0; i < 8; i++) {
                        int p = w * 8 + i;
                        pf_l2(Ain + ((size_t)b * HWsz + (size_t)rn * 128 + p) * 128 + lane * 4);
                    }
                }
            }

            // --- GEMM 128x128x128 ---
            float acc[2][4][4];
            #pragma unroll
            for (int mi = 0; mi < 2; mi++)
                #pragma unroll
                for (int ni = 0; ni < 4; ni++)
                    #pragma unroll
                    for (int t = 0; t < 4; t++) acc[mi][ni][t] = 0.f;

            #pragma unroll
            for (int k0 = 0; k0 < 128; k0 += 16) {
                unsigned af[2][4];
                unsigned bfr[4][2];
                #pragma unroll
                for (int mi = 0; mi < 2; mi++)
                    ldm_x4(af[mi], sptr(As + (wm + 16 * mi + arow) * SROW + k0 + akoff));
                #pragma unroll
                for (int ni = 0; ni < 4; ni++)
                    ldm_x2(bfr[ni], sptr(Ws + (wn + 8 * ni + brow) * SROW + k0 + bkoff));
                #pragma unroll
                for (int mi = 0; mi < 2; mi++)
                    #pragma unroll
                    for (int ni = 0; ni < 4; ni++)
                        mma16816(acc[mi][ni], af[mi], bfr[ni]);
            }

            // --- epilogue: +bias, bf16 -> ring slot [pos][ch] ---
            #pragma unroll
            for (int mi = 0; mi < 2; mi++) {
                int p0 = wm + 16 * mi + g;
                #pragma unroll
                for (int ni = 0; ni < 4; ni++) {
                    int col = wn + 8 * ni + t2;
                    float2 bb = *(const float2*)(gb + col);
                    *(__nv_bfloat162*)(rs + p0 * RROW + col) =
                        __floats2bfloat162_rn(acc[mi][ni][0] + bb.x, acc[mi][ni][1] + bb.y);
                    *(__nv_bfloat162*)(rs + (p0 + 8) * RROW + col) =
                        __floats2bfloat162_rn(acc[mi][ni][2] + bb.x, acc[mi][ni][3] + bb.y);
                }
            }
            __syncthreads();   // ring slot visible; As free for next LN
        } else {
            __syncthreads();   // prior conv readers done before zeroing
            for (int it = tid; it < 128 * (RROW / 2); it += 512)
                ((unsigned*)rs)[it] = 0u;
            __syncthreads();
        }

        // --- dwconv output row yo = y0 + ri - 2 ---
        if (ri >= 2) {
            const __nv_bfloat162* r0 = (const __nv_bfloat162*)(ring + ((ri - 2) % 3) * SLOTH);
            const __nv_bfloat162* r1 = (const __nv_bfloat162*)(ring + ((ri - 1) % 3) * SLOTH);
            const __nv_bfloat162* r2 = (const __nv_bfloat162*)(ring + (ri % 3) * SLOTH);
            int yo = y0 + ri - 2;
            int x0 = xg * 16;
            const int RW = RROW / 2;

            __nv_bfloat162 m0, m1, m2, c0, c1, c2;
            if (x0 > 0) {
                m0 = r0[(x0 - 1) * RW + cp]; m1 = r1[(x0 - 1) * RW + cp]; m2 = r2[(x0 - 1) * RW + cp];
            } else { m0 = zz; m1 = zz; m2 = zz; }
            c0 = r0[x0 * RW + cp]; c1 = r1[x0 * RW + cp]; c2 = r2[x0 * RW + cp];

            bf16* ob = outp + ((size_t)b * HWsz + (size_t)yo * 128) * ldout + coloff + cg;
            #pragma unroll 4
            for (int xi = 0; xi < 16; xi++) {
                int x = x0 + xi;
                __nv_bfloat162 p0, p1, p2;
                if (x < 127) {
                    p0 = r0[(x + 1) * RW + cp]; p1 = r1[(x + 1) * RW + cp]; p2 = r2[(x + 1) * RW + cp];
                } else { p0 = zz; p1 = zz; p2 = zz; }
                __nv_bfloat162 a = cb2;
                a = __hfma2(m0, cw[0], a); a = __hfma2(c0, cw[1], a); a = __hfma2(p0, cw[2], a);
                a = __hfma2(m1, cw[3], a); a = __hfma2(c1, cw[4], a); a = __hfma2(p1, cw[5], a);
                a = __hfma2(m2, cw[6], a); a = __hfma2(c2, cw[7], a); a = __hfma2(p2, cw[8], a);
                *(__nv_bfloat162*)(ob + (size_t)x * ldout) = a;
                if (dosq) {
                    float f0 = __bfloat162float(__low2bfloat16(a));
                    float f1 = __bfloat162float(__high2bfloat16(a));
                    sq0 = fmaf(f0, f0, sq0);
                    sq1 = fmaf(f1, f1, sq1);
                }
                m0 = c0; c0 = p0; m1 = c1; c1 = p1; m2 = c2; c2 = p2;
            }
        }
    }

    // --- sumsq reduce -> g_norm_part ---
    red2[tid] = make_float2(sq0, sq1);
    __syncthreads();
    if (dosq && tid < 64) {
        float t0 = 0.f, t1 = 0.f;
        #pragma unroll
        for (int xx = 0; xx < 8; xx++) {
            float2 v = red2[xx * 64 + tid];
            t0 += v.x; t1 += v.y;
        }
        float* dst = g_norm_part + ((size_t)(which * 8 + b) * 16 + strip) * 128 + tid * 2;
        dst[0] = t0; dst[1] = t1;
    }
}

// ---------------- QK^T (bf16 mma, split-K over n), partials fp32, reg double-buffer ----------------
__global__ __launch_bounds__(256)
void qk_kernel()
{
    __shared__ bf16 Qs[32 * SROW];
    __shared__ bf16 Ks[32 * SROW];
    int bx = blockIdx.x;
    int b = bx >> 6, chunk = bx & 63;
    const bf16* Qb = g_q2  + (size_t)b * HWsz * 128;
    const bf16* Kb = g_kv2 + (size_t)b * HWsz * 256;
    int tid = threadIdx.x, lane = tid & 31, w = tid >> 5;
    int wm = (w & 1) * 64, wn = (w >> 1) * 32;

    int at_row  = (lane & 7) + ((lane >> 4) & 1) * 8;
    int at_coff = ((lane >> 3) & 1) * 8;
    int bt_row  = (lane & 7) + ((lane >> 3) & 1) * 8;
    int g = lane >> 2, t2 = (lane & 3) * 2;

    int r0s = tid >> 4,         c0s = (tid & 15) * 8;
    int r1s = (tid + 256) >> 4, c1s = ((tid + 256) & 15) * 8;

    float acc[4][4][4];
    #pragma unroll
    for (int mi = 0; mi < 4; mi++)
        #pragma unroll
        for (int ni = 0; ni < 4; ni++)
            #pragma unroll
            for (int t = 0; t < 4; t++) acc[mi][ni][t] = 0.f;

    const int NS = 8;
    int nbase = chunk * 256;

    uint4 pq0, pq1, pk0, pk1;
    {
        int n0 = nbase;
        pq0 = *(const uint4*)(Qb + (size_t)(n0 + r0s) * 128 + c0s);
        pq1 = *(const uint4*)(Qb + (size_t)(n0 + r1s) * 128 + c1s);
        pk0 = *(const uint4*)(Kb + (size_t)(n0 + r0s) * 256 + c0s);
        pk1 = *(const uint4*)(Kb + (size_t)(n0 + r1s) * 256 + c1s);
    }

    for (int st = 0; st < NS; st++) {
        *(uint4*)(Qs + r0s * SROW + c0s) = pq0;
        *(uint4*)(Qs + r1s * SROW + c1s) = pq1;
        *(uint4*)(Ks + r0s * SROW + c0s) = pk0;
        *(uint4*)(Ks + r1s * SROW + c1s) = pk1;
        __syncthreads();

        if (st + 1 < NS) {
            int n0 = nbase + (st + 1) * 32;
            pq0 = *(const uint4*)(Qb + (size_t)(n0 + r0s) * 128 + c0s);
            pq1 = *(const uint4*)(Qb + (size_t)(n0 + r1s) * 128 + c1s);
            pk0 = *(const uint4*)(Kb + (size_t)(n0 + r0s) * 256 + c0s);
            pk1 = *(const uint4*)(Kb + (size_t)(n0 + r1s) * 256 + c1s);
        }

        #pragma unroll
        for (int k0 = 0; k0 < 32; k0 += 16) {
            unsigned af[4][4];
            unsigned bfr[4][2];
            #pragma unroll
            for (int mi = 0; mi < 4; mi++)
                ldm_x4_t(af[mi], sptr(Qs + (k0 + at_row) * SROW + wm + 16 * mi + at_coff));
            #pragma unroll
            for (int ni = 0; ni < 4; ni++)
                ldm_x2_t(bfr[ni], sptr(Ks + (k0 + bt_row) * SROW + wn + 8 * ni));
            #pragma unroll
            for (int mi = 0; mi < 4; mi++)
                #pragma unroll
                for (int ni = 0; ni < 4; ni++)
                    mma16816(acc[mi][ni], af[mi], bfr[ni]);
        }
        __syncthreads();
    }

    float* P = g_att_part + (size_t)bx * 16384;
    #pragma unroll
    for (int mi = 0; mi < 4; mi++) {
        int row = wm + 16 * mi + g;
        #pragma unroll
        for (int ni = 0; ni < 4; ni++) {
            int col = wn + 8 * ni + t2;
            *(float2*)(P + row * 128 + col)       = make_float2(acc[mi][ni][0], acc[mi][ni][1]);
            *(float2*)(P + (row + 8) * 128 + col) = make_float2(acc[mi][ni][2], acc[mi][ni][3]);
        }
    }
}

// ---------------- softmax: one block per (b,c), thread = d ----------------
__global__ __launch_bounds__(128)
void softmax_kernel()
{
    __shared__ float rbuf[8];
    int bc = blockIdx.x;
    int b = bc >> 7, c = bc & 127;
    int d = threadIdx.x;

    float sq = 0.f, sk = 0.f;
    #pragma unroll
    for (int t = 0; t < 16; t++) {
        sq += g_norm_part[((size_t)b * 16 + t) * 128 + c];
        sk += g_norm_part[((size_t)(8 + b) * 16 + t) * 128 + d];
    }
    float invq = 1.0f / fmaxf(sqrtf(sq), 1e-12f);
    float invk = 1.0f / fmaxf(sqrtf(sk), 1e-12f);

    const float* P = g_att_part + ((size_t)b * NCHUNK * 128 + c) * 128 + d;
    float s = 0.f;
    #pragma unroll 8
    for (int ch = 0; ch < NCHUNK; ch++)
        s += P[(size_t)ch * 16384];

    float l = s * invq * invk;

    float mx = l;
    #pragma unroll
    for (int o = 16; o; o >>= 1) mx = fmaxf(mx, __shfl_xor_sync(0xFFFFFFFFu, mx, o));
    if ((d & 31) == 0) rbuf[d >> 5] = mx;
    __syncthreads();
    mx = fmaxf(fmaxf(rbuf[0], rbuf[1]), fmaxf(rbuf[2], rbuf[3]));

    float e = expf(l - mx);
    float sum = e;
    #pragma unroll
    for (int o = 16; o; o >>= 1) sum += __shfl_xor_sync(0xFFFFFFFFu, sum, o);
    __syncthreads();
    if ((d & 31) == 0) rbuf[4 + (d >> 5)] = sum;
    __syncthreads();
    sum = (rbuf[4] + rbuf[5]) + (rbuf[6] + rbuf[7]);

    g_att[(size_t)bc * 128 + d] = e / sum;
}

// ---------------- W2[b] = out_w @ att[b]: grid (Bsz, 16), 512 thr, 4-way e-split ----------------
__global__ __launch_bounds__(512)
void w2_kernel(const float* __restrict__ out_w)
{
    __shared__ float sw[8 * 128];        // out_w tile [8 c][128 e]
    __shared__ float red[4 * 8 * 128];   // partials [eh][ci][d]
    int b = blockIdx.x, ct = blockIdx.y;
    int tid = threadIdx.x;
    int d = tid & 127, eh = tid >> 7;    // eh in 0..3

    for (int it = tid; it < 8 * 128; it += 512)
        sw[it] = out_w[(size_t)(ct * 8 + (it >> 7)) * 128 + (it & 127)];
    __syncthreads();

    float acc[8];
    #pragma unroll
    for (int ci = 0; ci < 8; ci++) acc[ci] = 0.f;

    const float* A = g_att + (size_t)b * 16384 + d;
    int e0 = eh * 32;
    #pragma unroll 8
    for (int ei = 0; ei < 32; ei++) {
        int e = e0 + ei;
        float a = A[(size_t)e * 128];
        #pragma unroll
        for (int ci = 0; ci < 8; ci++)
            acc[ci] = fmaf(sw[ci * 128 + e], a, acc[ci]);
    }

    #pragma unroll
    for (int ci = 0; ci < 8; ci++)
        red[(eh * 8 + ci) * 128 + d] = acc[ci];
    __syncthreads();

    // combine: 1024 outputs, 512 threads -> 2 each
    #pragma unroll
    for (int t = 0; t < 2; t++) {
        int idx = tid + t * 512;         // idx = ci*128 + d2
        int ci = idx >> 7, d2 = idx & 127;
        float v = red[(0 * 8 + ci) * 128 + d2] + red[(1 * 8 + ci) * 128 + d2]
                + red[(2 * 8 + ci) * 128 + d2] + red[(3 * 8 + ci) * 128 + d2];
        g_W2h[(size_t)b * 16384 + (size_t)(ct * 8 + ci) * 128 + d2] = __float2bfloat16_rn(v);
    }
}

// ---------------- final: out[b,n,c] = sum_d W2[c,d] v[b,n,d] + out_b[c] + cur ----------------
__global__ __launch_bounds__(256)
void vgemm(const float* __restrict__ cur, const float* __restrict__ out_b,
           float* __restrict__ out)
{
    extern __shared__ bf16 sm[];
    bf16* As = sm;
    bf16* Bs = sm + 128 * SROW;
    int b = blockIdx.z;
    int m0 = blockIdx.y * 128;
    const bf16* V  = g_kv2 + (size_t)b * HWsz * 256 + 128;
    const bf16* W2 = g_W2h + (size_t)b * 16384;
    int tid = threadIdx.x, lane = tid & 31, w = tid >> 5;

    for (int it = tid; it < 128 * 16; it += 256) {
        int r = it >> 4, c8 = (it & 15) * 8;
        *(uint4*)(As + r * SROW + c8) = *(const uint4*)(V + (size_t)(m0 + r) * 256 + c8);
        *(uint4*)(Bs + r * SROW + c8) = *(const uint4*)(W2 + (size_t)r * 128 + c8);
    }
    __syncthreads();

    int wm = (w & 1) * 64, wn = (w >> 1) * 32;
    int arow  = (lane & 7) + ((lane >> 3) & 1) * 8;
    int akoff = (lane >> 4) * 8;
    int brow  = (lane & 7);
    int bkoff = ((lane >> 3) & 1) * 8;
    int g = lane >> 2, t2 = (lane & 3) * 2;

    float acc[4][4][4];
    #pragma unroll
    for (int mi = 0; mi < 4; mi++)
        #pragma unroll
        for (int ni = 0; ni < 4; ni++)
            #pragma unroll
            for (int t = 0; t < 4; t++) acc[mi][ni][t] = 0.f;

    for (int k0 = 0; k0 < 128; k0 += 16) {
        unsigned af[4][4];
        unsigned bfr[4][2];
        #pragma unroll
        for (int mi = 0; mi < 4; mi++)
            ldm_x4(af[mi], sptr(As + (wm + 16 * mi + arow) * SROW + k0 + akoff));
        #pragma unroll
        for (int ni = 0; ni < 4; ni++)
            ldm_x2(bfr[ni], sptr(Bs + (wn + 8 * ni + brow) * SROW + k0 + bkoff));
        #pragma unroll
        for (int mi = 0; mi < 4; mi++)
            #pragma unroll
            for (int ni = 0; ni < 4; ni++)
                mma16816(acc[mi][ni], af[mi], bfr[ni]);
    }

    const float* curb = cur + (size_t)b * HWsz * 128;
    float* outb = out + (size_t)b * HWsz * 128;
    #pragma unroll
    for (int mi = 0; mi < 4; mi++) {
        int r0 = m0 + wm + 16 * mi + g;
        #pragma unroll
        for (int ni = 0; ni < 4; ni++) {
            int col = wn + 8 * ni + t2;
            float2 bb = *(const float2*)(out_b + col);
            float2 c0 = *(const float2*)(curb + (size_t)r0 * 128 + col);
            float2 c1 = *(const float2*)(curb + (size_t)(r0 + 8) * 128 + col);
            *(float2*)(outb + (size_t)r0 * 128 + col) =
                make_float2(acc[mi][ni][0] + bb.x + c0.x, acc[mi][ni][1] + bb.y + c0.y);
            *(float2*)(outb + (size_t)(r0 + 8) * 128 + col) =
                make_float2(acc[mi][ni][2] + bb.x + c1.x, acc[mi][ni][3] + bb.y + c1.y);
        }
    }
}

// ---------------- host ----------------
extern "C" void kernel_launch(void* const* d_in, const int* in_sizes, int n_in,
                              void* d_out, int out_size)
{
    const float* pre   = (const float*)d_in[0];
    const float* cur   = (const float*)d_in[1];
    const float* ln1_w = (const float*)d_in[2];
    const float* ln1_b = (const float*)d_in[3];
    const float* ln2_w = (const float*)d_in[4];
    const float* ln2_b = (const float*)d_in[5];
    const float* q_w1  = (const float*)d_in[6];
    const float* q_b1  = (const float*)d_in[7];
    const float* q_w2  = (const float*)d_in[8];
    const float* q_b2  = (const float*)d_in[9];
    const float* kv_w1 = (const float*)d_in[10];
    const float* kv_b1 = (const float*)d_in[11];
    const float* kv_w2 = (const float*)d_in[12];
    const float* kv_b2 = (const float*)d_in[13];
    const float* out_w = (const float*)d_in[14];
    const float* out_b = (const float*)d_in[15];
    float* out = (float*)d_out;

    const int SMEM_GEMM = 2 * 128 * SROW * (int)sizeof(bf16);
    const int SMEM_MF   = (2 * 128 * SROW + 3 * SLOTH) * (int)sizeof(bf16);
    cudaFuncSetAttribute(megafuse, cudaFuncAttributeMaxDynamicSharedMemorySize, SMEM_MF);
    cudaFuncSetAttribute(vgemm,    cudaFuncAttributeMaxDynamicSharedMemorySize, SMEM_GEMM);

    megafuse<<<dim3(3, 16, Bsz), 512, SMEM_MF>>>(cur, pre, ln1_w, ln1_b, ln2_w, ln2_b,
                                                 q_w1, kv_w1, q_b1, kv_b1,
                                                 q_w2, q_b2, kv_w2, kv_b2);

    qk_kernel<<<Bsz * NCHUNK, 256>>>();

    softmax_kernel<<<Bsz * 128, 128>>>();

    w2_kernel<<<dim3(Bsz, 16), 512>>>(out_w);

    vgemm<<<dim3(1, HWsz / 128, Bsz), 256, SMEM_GEMM>>>(cur, out_b, out);

    (void)in_sizes; (void)n_in; (void)out_size;
}